// round 11
// baseline (speedup 1.0000x reference)
#include <cuda_runtime.h>
#include <cuda_fp16.h>
#include <math.h>

#define OBS 8
#define PRED 4
#define NAG 256
#define FIN 2
#define FOUT 2
#define H 128
#define NH 8
#define DH 16
#define FFD 2048
#define NL 6
#define NNODE (OBS*NAG)        /* 2048 */
#define SEQ NAG                /* 256  */
#define BB H                   /* 128  */
#define NTOK (SEQ*BB)          /* 32768 */

// ---------------- scratch (device globals; no allocation) ----------------
static __device__ float  g_ADJ[NNODE*NNODE];
static __device__ __half g_AGGH[NNODE*NNODE];
static __device__ __half g_ENCH[NNODE*H];
static __device__ __half g_MLSH[2*H*NNODE];
static __device__ float  g_PART[8*NNODE*2*H];
static __device__ __half g_ZH[NNODE*H];
static __device__ float  g_OUTB[NNODE*H];
static __device__ float  g_X[NTOK*H];
static __device__ __half g_XH[NTOK*H];
static __device__ __half g_OH[NTOK*H];
static __device__ __half g_QKVH[NTOK*3*H];
static __device__ __half g_WQKVH[NL*3*H*H];
static __device__ __half g_WOUTH[NL*H*H];
static __device__ __half g_WFF1H[(size_t)NL*FFD*H];
static __device__ __half g_WFF2H[(size_t)NL*H*FFD];
static __device__ __half g_WGDLH[H*H];
static __device__ __half g_WMLSH[2*H*H];
static __device__ float  g_BMLS[2*H];
static __device__ float  g_COL[NNODE];
static __device__ float  g_SELF[NNODE];
static __device__ float  g_DIS[NNODE];
static __device__ float  g_mn_acc, g_mx_acc;
static __device__ double g_kld, g_struct, g_traj;

// ---------------- helpers ----------------
__device__ __forceinline__ void atomicMinF(float* a, float v) {
    int* ai = (int*)a; int old = *ai;
    while (__int_as_float(old) > v) {
        int assumed = old;
        old = atomicCAS(ai, assumed, __float_as_int(v));
        if (old == assumed) break;
    }
}
__device__ __forceinline__ void atomicMaxF(float* a, float v) {
    int* ai = (int*)a; int old = *ai;
    while (__int_as_float(old) < v) {
        int assumed = old;
        old = atomicCAS(ai, assumed, __float_as_int(v));
        if (old == assumed) break;
    }
}

template<int NWARPS>
__device__ __forceinline__ float block_sum(float v) {
    __shared__ float w[NWARPS];
    int tid = threadIdx.x + threadIdx.y * blockDim.x;
    int lane = tid & 31, wid = tid >> 5;
    #pragma unroll
    for (int o = 16; o > 0; o >>= 1) v += __shfl_down_sync(0xffffffffu, v, o);
    if (lane == 0) w[wid] = v;
    __syncthreads();
    float r = 0.f;
    #pragma unroll
    for (int i = 0; i < NWARPS; i++) r += w[i];
    __syncthreads();
    return r;
}

__device__ __forceinline__ void mma_f16(float* c, const unsigned* a, unsigned b0, unsigned b1) {
    asm volatile(
        "mma.sync.aligned.m16n8k16.row.col.f32.f16.f16.f32 "
        "{%0,%1,%2,%3}, {%4,%5,%6,%7}, {%8,%9}, {%0,%1,%2,%3};"
        : "+f"(c[0]), "+f"(c[1]), "+f"(c[2]), "+f"(c[3])
        : "r"(a[0]), "r"(a[1]), "r"(a[2]), "r"(a[3]), "r"(b0), "r"(b1));
}

__device__ __forceinline__ unsigned h2pack(float x, float y) {
    __half2 h = __floats2half2_rn(x, y);
    return *(unsigned*)&h;
}

__device__ __forceinline__ unsigned smem_u32(const void* p) {
    return (unsigned)__cvta_generic_to_shared(p);
}
__device__ __forceinline__ void cpa16(unsigned dst, const void* src) {
    asm volatile("cp.async.cg.shared.global [%0], [%1], 16;" :: "r"(dst), "l"(src));
}
__device__ __forceinline__ void lmx4(unsigned& r0, unsigned& r1, unsigned& r2, unsigned& r3, unsigned addr) {
    asm volatile("ldmatrix.sync.aligned.m8n8.x4.shared.b16 {%0,%1,%2,%3}, [%4];"
                 : "=r"(r0), "=r"(r1), "=r"(r2), "=r"(r3) : "r"(addr));
}

// Load a 128x128 half tile into 4 swizzled 8KB sub-buffers.
__device__ __forceinline__ void load_tile128(unsigned dstBase, const __half* src, int srcStride, int tid) {
    int crow = tid >> 1, cpi = (tid & 1) * 2;
    int cswz = (crow >> 1) & 3;
    #pragma unroll
    for (int kc = 0; kc < 4; kc++) {
        const __half* s = src + (size_t)crow * srcStride + kc * 32 + cpi * 8;
        unsigned d = dstBase + kc * 8192 + crow * 64;
        cpa16(d + ((cpi ^ cswz)) * 16, s);
        cpa16(d + (((cpi + 1) ^ cswz)) * 16, s + 8);
    }
}

// ---------------- init ----------------
__global__ void k_init() {
    int i = blockIdx.x * 256 + threadIdx.x;
    if (i < NNODE) g_COL[i] = 0.f;
    if (i == 0) {
        g_mn_acc = __int_as_float(0x7f800000);
        g_mx_acc = __int_as_float(0xff800000);
        g_kld = 0.0; g_struct = 0.0; g_traj = 0.0;
    }
}

// ---------------- fused weight conversion ----------------
__global__ void k_cvt(const float* __restrict__ qkv, const float* __restrict__ outw,
                      const float* __restrict__ ff1, const float* __restrict__ ff2,
                      const float* __restrict__ gdl, const float* __restrict__ muw,
                      const float* __restrict__ lsw, const float* __restrict__ mub,
                      const float* __restrict__ lsb) {
    int k = blockIdx.x * 256 + threadIdx.x;
    const float* src; __half* dst; int off;
    if (k < 73728)       { src = qkv;  dst = g_WQKVH;        off = k; }
    else if (k < 98304)  { src = outw; dst = g_WOUTH;        off = k - 73728; }
    else if (k < 491520) { src = ff1;  dst = g_WFF1H;        off = k - 98304; }
    else if (k < 884736) { src = ff2;  dst = g_WFF2H;        off = k - 491520; }
    else if (k < 888832) { src = gdl;  dst = g_WGDLH;        off = k - 884736; }
    else if (k < 892928) { src = muw;  dst = g_WMLSH;        off = k - 888832; }
    else if (k < 897024) { src = lsw;  dst = g_WMLSH + H*H;  off = k - 892928; }
    else if (k < 897088) {
        int o = k - 897024;
        float4 v = (o < 32) ? ((const float4*)mub)[o] : ((const float4*)lsb)[o - 32];
        ((float4*)g_BMLS)[o] = v;
        return;
    } else return;
    float4 v = ((const float4*)src)[off];
    __half2* d = (__half2*)dst + off * 2;
    d[0] = __floats2half2_rn(v.x, v.y);
    d[1] = __floats2half2_rn(v.z, v.w);
}

// ---------------- adjacency prep ----------------
__global__ void k_minmax(const float* __restrict__ adj) {
    const int n = OBS * NAG * NAG;
    float mn = __int_as_float(0x7f800000), mx = -mn;
    for (int i = blockIdx.x * blockDim.x + threadIdx.x; i < n; i += gridDim.x * blockDim.x) {
        float v = adj[i];
        mn = fminf(mn, v); mx = fmaxf(mx, v);
    }
    #pragma unroll
    for (int o = 16; o > 0; o >>= 1) {
        mn = fminf(mn, __shfl_down_sync(0xffffffffu, mn, o));
        mx = fmaxf(mx, __shfl_down_sync(0xffffffffu, mx, o));
    }
    __shared__ float smn[8], smx[8];
    int lane = threadIdx.x & 31, wid = threadIdx.x >> 5;
    if (lane == 0) { smn[wid] = mn; smx[wid] = mx; }
    __syncthreads();
    if (threadIdx.x == 0) {
        for (int w = 1; w < 8; w++) { mn = fminf(mn, smn[w]); mx = fmaxf(mx, smx[w]); }
        atomicMinF(&g_mn_acc, mn);
        atomicMaxF(&g_mx_acc, mx);
    }
}

__global__ void k_build(const float* __restrict__ adj) {
    float mn = fminf(g_mn_acc, 0.f);
    float mx = fmaxf(g_mx_acc, 0.f);
    float inv = 1.f / (mx - mn);
    int i = blockIdx.y;
    int j = (blockIdx.x * 256 + threadIdx.x) * 4;
    int ti = i >> 8, tj = j >> 8;
    float4 a = make_float4(0.f, 0.f, 0.f, 0.f);
    if (ti == tj)
        a = *(const float4*)(adj + (ti << 16) + ((i & 255) << 8) + (j & 255));
    float4 v = make_float4((a.x - mn) * inv, (a.y - mn) * inv, (a.z - mn) * inv, (a.w - mn) * inv);
    *(float4*)(g_ADJ + (size_t)i * NNODE + j) = v;
    if (i >= j && i < j + 4) {
        float d = (i == j) ? v.x : (i == j + 1) ? v.y : (i == j + 2) ? v.z : v.w;
        g_SELF[i] = (d == 0.f) ? 1.f : 0.f;
    }
}

__global__ void k_colsum() {
    int j = blockIdx.x * 128 + threadIdx.x;
    int i0 = blockIdx.y * 32;
    float s = 0.f;
    for (int r = 0; r < 32; r++) s += g_ADJ[(size_t)(i0 + r) * NNODE + j];
    atomicAdd(&g_COL[j], s);
}

__global__ void k_dis() {
    int j = blockIdx.x * 256 + threadIdx.x;
    if (j < NNODE) {
        float deg = g_COL[j] + g_SELF[j];
        g_DIS[j] = (deg > 0.f) ? (1.f / sqrtf(deg)) : 0.f;
    }
}

__global__ void k_agg() {
    __shared__ float s[32][33];
    int i0 = blockIdx.y * 32, j0 = blockIdx.x * 32;
    int tx = threadIdx.x, ty = threadIdx.y;
    s[ty][tx] = g_ADJ[(size_t)(j0 + ty) * NNODE + (i0 + tx)];
    __syncthreads();
    int i = i0 + ty, j = j0 + tx;
    float v = s[tx][ty];
    if (i == j) v += g_SELF[i];
    g_AGGH[(size_t)i * NNODE + j] = __float2half(g_DIS[j] * v * g_DIS[i]);
}

// ---------------- encoder ----------------
__global__ void k_enc(const float* __restrict__ traj,
                      const float* __restrict__ w1, const float* __restrict__ b1,
                      const float* __restrict__ w2, const float* __restrict__ b2) {
    int n = blockIdx.x, j = threadIdx.x;
    __shared__ float h1[128];
    float x0 = traj[n * 2], x1 = traj[n * 2 + 1];
    h1[j] = fmaxf(w1[j * 2] * x0 + w1[j * 2 + 1] * x1 + b1[j], 0.f);
    __syncthreads();
    float a = b2[j];
    #pragma unroll 8
    for (int k = 0; k < 128; k++) a += w2[j * 128 + k] * h1[k];
    g_ENCH[n * 128 + j] = __float2half(a);
}

// ---------------- fp16 TC GEMM (unchanged) ------------------
template<int EPI>
__global__ __launch_bounds__(256, 2) void k_hgemm(
    const __half* __restrict__ A, const __half* __restrict__ B,
    const float* __restrict__ bias, float* __restrict__ C, __half* __restrict__ Ch,
    int M, int N, int K,
    const float* __restrict__ gamma, const float* __restrict__ beta)
{
    __shared__ __align__(16) __half SA[3][4096];
    __shared__ __align__(16) __half SB[3][4096];
    int bm = blockIdx.y * 128, bn = blockIdx.x * 128;
    int tid = threadIdx.x;
    int warp = tid >> 5, lane = tid & 31;
    int wm = warp & 3, wn = warp >> 2;
    int g = lane >> 2, tig = lane & 3;

    int ksz = K / gridDim.z;
    int k_begin = blockIdx.z * ksz;
    const int nch = ksz >> 5;

    unsigned baseSA = smem_u32(&SA[0][0]);
    unsigned baseSB = smem_u32(&SB[0][0]);

    int crow = tid >> 1, cp = (tid & 1) * 2;
    int cswz = (crow >> 1) & 3;
    unsigned dA0 = baseSA + crow * 64 + ((cp ^ cswz)) * 16;
    unsigned dA1 = baseSA + crow * 64 + (((cp + 1) ^ cswz)) * 16;
    unsigned dB0 = baseSB + crow * 64 + ((cp ^ cswz)) * 16;
    unsigned dB1 = baseSB + crow * 64 + (((cp + 1) ^ cswz)) * 16;
    const __half* srcA = A + (size_t)(bm + crow) * K + k_begin + cp * 8;
    const __half* srcB = B + (size_t)(bn + crow) * K + k_begin + cp * 8;

    int m = lane >> 3, mi = lane & 7;
    int rA0 = wm * 32 + ((m & 1) << 3) + mi;
    int rB0 = wn * 64 + ((m >> 1) << 3) + mi;
    int swA = (rA0 >> 1) & 3;
    int swB = (rB0 >> 1) & 3;
    int kselA = m >> 1, kselB = m & 1;

    float acc[2][8][4] = {};

    #pragma unroll
    for (int s = 0; s < 2; s++) {
        if (s < nch) {
            unsigned so = s * 8192u;
            cpa16(dA0 + so, srcA + s * 32);
            cpa16(dA1 + so, srcA + s * 32 + 8);
            cpa16(dB0 + so, srcB + s * 32);
            cpa16(dB1 + so, srcB + s * 32 + 8);
        }
        asm volatile("cp.async.commit_group;");
    }

    for (int c = 0; c < nch; c++) {
        asm volatile("cp.async.wait_group 1;");
        __syncthreads();
        int pf = c + 2;
        if (pf < nch) {
            unsigned so = (pf % 3) * 8192u;
            cpa16(dA0 + so, srcA + pf * 32);
            cpa16(dA1 + so, srcA + pf * 32 + 8);
            cpa16(dB0 + so, srcB + pf * 32);
            cpa16(dB1 + so, srcB + pf * 32 + 8);
        }
        asm volatile("cp.async.commit_group;");
        unsigned so = (c % 3) * 8192u;
        #pragma unroll
        for (int ks = 0; ks < 2; ks++) {
            unsigned af[2][4];
            #pragma unroll
            for (int mt = 0; mt < 2; mt++) {
                unsigned addr = baseSA + so + (rA0 + mt * 16) * 64 + (((2 * ks + kselA) ^ swA)) * 16;
                lmx4(af[mt][0], af[mt][1], af[mt][2], af[mt][3], addr);
            }
            unsigned bf[8][2];
            #pragma unroll
            for (int jj = 0; jj < 4; jj++) {
                unsigned addr = baseSB + so + (rB0 + jj * 16) * 64 + (((2 * ks + kselB) ^ swB)) * 16;
                lmx4(bf[2 * jj][0], bf[2 * jj][1], bf[2 * jj + 1][0], bf[2 * jj + 1][1], addr);
            }
            #pragma unroll
            for (int nt = 0; nt < 8; nt++) {
                mma_f16(acc[0][nt], af[0], bf[nt][0], bf[nt][1]);
                mma_f16(acc[1][nt], af[1], bf[nt][0], bf[nt][1]);
            }
        }
    }

    if (EPI == 0) {
        #pragma unroll
        for (int mt = 0; mt < 2; mt++) {
            int r0 = bm + wm * 32 + mt * 16 + g;
            #pragma unroll
            for (int nt = 0; nt < 8; nt++) {
                int c0 = bn + wn * 64 + nt * 8 + 2 * tig;
                float bv0 = bias[c0], bv1 = bias[c0 + 1];
                *(float2*)(C + (size_t)r0 * N + c0) =
                    make_float2(acc[mt][nt][0] + bv0, acc[mt][nt][1] + bv1);
                *(float2*)(C + (size_t)(r0 + 8) * N + c0) =
                    make_float2(acc[mt][nt][2] + bv0, acc[mt][nt][3] + bv1);
            }
        }
    } else if (EPI == 1) {
        int p = blockIdx.x;
        #pragma unroll
        for (int mt = 0; mt < 2; mt++) {
            int r0 = bm + wm * 32 + mt * 16 + g;
            int r1 = r0 + 8;
            #pragma unroll
            for (int nt = 0; nt < 8; nt++) {
                int rem = wn * 64 + nt * 8 + 2 * tig;
                int h = rem >> 4, d = rem & 15;
                int c0 = bn + rem;
                float bv0 = bias[c0], bv1 = bias[c0 + 1];
                size_t b0 = ((size_t)((p * 8 + h) * 128 + (r0 & 127)) * 256 + (r0 >> 7)) * 16 + d;
                size_t b1 = ((size_t)((p * 8 + h) * 128 + (r1 & 127)) * 256 + (r1 >> 7)) * 16 + d;
                *(__half2*)(Ch + b0) = __floats2half2_rn(acc[mt][nt][0] + bv0, acc[mt][nt][1] + bv1);
                *(__half2*)(Ch + b1) = __floats2half2_rn(acc[mt][nt][2] + bv0, acc[mt][nt][3] + bv1);
            }
        }
    } else if (EPI == 2) {
        float sums[2][2], sqs[2][2];
        #pragma unroll
        for (int mt = 0; mt < 2; mt++) { sums[mt][0] = sums[mt][1] = sqs[mt][0] = sqs[mt][1] = 0.f; }
        #pragma unroll
        for (int mt = 0; mt < 2; mt++) {
            int r0 = bm + wm * 32 + mt * 16 + g;
            #pragma unroll
            for (int nt = 0; nt < 8; nt++) {
                int c0 = wn * 64 + nt * 8 + 2 * tig;
                float bv0 = bias[c0], bv1 = bias[c0 + 1];
                float v00 = acc[mt][nt][0] + bv0 + C[(size_t)r0 * 128 + c0];
                float v01 = acc[mt][nt][1] + bv1 + C[(size_t)r0 * 128 + c0 + 1];
                float v10 = acc[mt][nt][2] + bv0 + C[(size_t)(r0 + 8) * 128 + c0];
                float v11 = acc[mt][nt][3] + bv1 + C[(size_t)(r0 + 8) * 128 + c0 + 1];
                acc[mt][nt][0] = v00; acc[mt][nt][1] = v01;
                acc[mt][nt][2] = v10; acc[mt][nt][3] = v11;
                sums[mt][0] += v00 + v01; sqs[mt][0] += v00 * v00 + v01 * v01;
                sums[mt][1] += v10 + v11; sqs[mt][1] += v10 * v10 + v11 * v11;
            }
        }
        #pragma unroll
        for (int mt = 0; mt < 2; mt++)
            #pragma unroll
            for (int rp = 0; rp < 2; rp++) {
                float s = sums[mt][rp], q = sqs[mt][rp];
                s += __shfl_xor_sync(0xffffffffu, s, 1); q += __shfl_xor_sync(0xffffffffu, q, 1);
                s += __shfl_xor_sync(0xffffffffu, s, 2); q += __shfl_xor_sync(0xffffffffu, q, 2);
                sums[mt][rp] = s; sqs[mt][rp] = q;
            }
        __syncthreads();
        float* red = (float*)SA;
        if (tig == 0) {
            #pragma unroll
            for (int mt = 0; mt < 2; mt++)
                #pragma unroll
                for (int rp = 0; rp < 2; rp++) {
                    int ix = ((warp * 16 + g) * 4 + mt * 2 + rp) * 2;
                    red[ix] = sums[mt][rp]; red[ix + 1] = sqs[mt][rp];
                }
        }
        __syncthreads();
        float mean[2][2], inv[2][2];
        #pragma unroll
        for (int mt = 0; mt < 2; mt++)
            #pragma unroll
            for (int rp = 0; rp < 2; rp++) {
                int i0 = (((wm) * 16 + g) * 4 + mt * 2 + rp) * 2;
                int i1 = (((wm + 4) * 16 + g) * 4 + mt * 2 + rp) * 2;
                float s = red[i0] + red[i1];
                float q = red[i0 + 1] + red[i1 + 1];
                float mm = s * (1.f / 128.f);
                float var = q * (1.f / 128.f) - mm * mm;
                mean[mt][rp] = mm;
                inv[mt][rp] = rsqrtf(var + 1e-5f);
            }
        #pragma unroll
        for (int mt = 0; mt < 2; mt++) {
            int r0 = bm + wm * 32 + mt * 16 + g;
            #pragma unroll
            for (int nt = 0; nt < 8; nt++) {
                int c0 = wn * 64 + nt * 8 + 2 * tig;
                float g0 = gamma[c0], g1 = gamma[c0 + 1];
                float be0 = beta[c0], be1 = beta[c0 + 1];
                float v00 = (acc[mt][nt][0] - mean[mt][0]) * inv[mt][0] * g0 + be0;
                float v01 = (acc[mt][nt][1] - mean[mt][0]) * inv[mt][0] * g1 + be1;
                float v10 = (acc[mt][nt][2] - mean[mt][1]) * inv[mt][1] * g0 + be0;
                float v11 = (acc[mt][nt][3] - mean[mt][1]) * inv[mt][1] * g1 + be1;
                *(float2*)(C + (size_t)r0 * 128 + c0)       = make_float2(v00, v01);
                *(float2*)(C + (size_t)(r0 + 8) * 128 + c0) = make_float2(v10, v11);
                *(__half2*)(Ch + (size_t)r0 * 128 + c0)       = __floats2half2_rn(v00, v01);
                *(__half2*)(Ch + (size_t)(r0 + 8) * 128 + c0) = __floats2half2_rn(v10, v11);
            }
        }
    } else if (EPI == 5) {
        #pragma unroll
        for (int mt = 0; mt < 2; mt++) {
            int r0 = bm + wm * 32 + mt * 16 + g;
            #pragma unroll
            for (int nt = 0; nt < 8; nt++) {
                int c0 = bn + wn * 64 + nt * 8 + 2 * tig;
                float bv0 = bias[c0], bv1 = bias[c0 + 1];
                Ch[(size_t)c0 * M + r0]           = __float2half(acc[mt][nt][0] + bv0);
                Ch[(size_t)(c0 + 1) * M + r0]     = __float2half(acc[mt][nt][1] + bv1);
                Ch[(size_t)c0 * M + r0 + 8]       = __float2half(acc[mt][nt][2] + bv0);
                Ch[(size_t)(c0 + 1) * M + r0 + 8] = __float2half(acc[mt][nt][3] + bv1);
            }
        }
    } else if (EPI == 6) {
        float contrib = 0.f;
        #pragma unroll
        for (int mt = 0; mt < 2; mt++) {
            int r0 = bm + wm * 32 + mt * 16 + g;
            #pragma unroll
            for (int nt = 0; nt < 8; nt++) {
                int c0 = bn + wn * 64 + nt * 8 + 2 * tig;
                float2 ad0 = *(const float2*)(g_ADJ + (size_t)r0 * NNODE + c0);
                float2 ad1 = *(const float2*)(g_ADJ + (size_t)(r0 + 8) * NNODE + c0);
                float a00 = acc[mt][nt][0], a01 = acc[mt][nt][1];
                float a10 = acc[mt][nt][2], a11 = acc[mt][nt][3];
                contrib += fmaxf(a00, 0.f) - a00 * ad0.x + log1pf(expf(-fabsf(a00)));
                contrib += fmaxf(a01, 0.f) - a01 * ad0.y + log1pf(expf(-fabsf(a01)));
                contrib += fmaxf(a10, 0.f) - a10 * ad1.x + log1pf(expf(-fabsf(a10)));
                contrib += fmaxf(a11, 0.f) - a11 * ad1.y + log1pf(expf(-fabsf(a11)));
            }
        }
        #pragma unroll
        for (int o = 16; o > 0; o >>= 1) contrib += __shfl_down_sync(0xffffffffu, contrib, o);
        __syncthreads();
        float* red = (float*)SA;
        if (lane == 0) red[warp] = contrib;
        __syncthreads();
        if (tid == 0) {
            float s = 0.f;
            for (int w = 0; w < 8; w++) s += red[w];
            atomicAdd(&g_struct, (double)s);
        }
    } else { // EPI == 7
        float* P = C + (size_t)blockIdx.z * M * N;
        #pragma unroll
        for (int mt = 0; mt < 2; mt++) {
            int r0 = bm + wm * 32 + mt * 16 + g;
            #pragma unroll
            for (int nt = 0; nt < 8; nt++) {
                int c0 = bn + wn * 64 + nt * 8 + 2 * tig;
                *(float2*)(P + (size_t)r0 * N + c0)       = make_float2(acc[mt][nt][0], acc[mt][nt][1]);
                *(float2*)(P + (size_t)(r0 + 8) * N + c0) = make_float2(acc[mt][nt][2], acc[mt][nt][3]);
            }
        }
    }
}

// ---------------- fused FF, 112KB smem (2 blocks/SM), 64-neuron chunks -------
__global__ __launch_bounds__(256, 2) void k_ffn(
    const float* __restrict__ bias1, const float* __restrict__ bias2,
    const __half* __restrict__ W1, const __half* __restrict__ W2,
    float* __restrict__ X, __half* __restrict__ XH,
    const float* __restrict__ gamma, const float* __restrict__ beta)
{
    extern __shared__ __align__(16) __half sm[];
    unsigned baseSX = smem_u32(sm);          // 32KB X tile
    unsigned baseSH = baseSX + 32768;        // 16KB H tile (128x64)
    unsigned baseW1 = baseSH + 16384;        // 2 x 16KB W1 chunk (64x128)
    unsigned baseW2 = baseW1 + 32768;        // 2 x 16KB W2 chunk (128x64)
    int bm = blockIdx.x * 128;
    int tid = threadIdx.x;
    int warp = tid >> 5, lane = tid & 31;
    int wm = warp & 3, wn = warp >> 2;       // wn in {0,1}
    int g = lane >> 2, tig = lane & 3;
    int m = lane >> 3, mi = lane & 7;
    int rA0 = wm * 32 + ((m & 1) << 3) + mi;
    int rB0 = wn * 64 + ((m >> 1) << 3) + mi;   // GEMM2 B rows
    int rB1 = wn * 32 + ((m >> 1) << 3) + mi;   // GEMM1 B rows
    int swA = (rA0 >> 1) & 3;
    int swB0 = (rB0 >> 1) & 3;
    int swB1 = (rB1 >> 1) & 3;
    int kselA = m >> 1, kselB = m & 1;

    int w1row = tid >> 2, w1kc = tid & 3;
    int w1swz = (w1row >> 1) & 3;
    int w2row = tid >> 1, w2kc = tid & 1;
    int w2swz = (w2row >> 1) & 3;

    load_tile128(baseSX, XH + (size_t)bm * 128, 128, tid);
    {
        const __half* s1 = W1 + (size_t)w1row * 128 + w1kc * 32;
        unsigned d1 = baseW1 + w1kc * 4096 + w1row * 64;
        #pragma unroll
        for (int q = 0; q < 4; q++) cpa16(d1 + ((q ^ w1swz)) * 16, s1 + q * 8);
        const __half* s2 = W2 + (size_t)w2row * FFD + w2kc * 32;
        unsigned d2 = baseW2 + w2kc * 8192 + w2row * 64;
        #pragma unroll
        for (int q = 0; q < 4; q++) cpa16(d2 + ((q ^ w2swz)) * 16, s2 + q * 8);
    }
    asm volatile("cp.async.commit_group;");

    float acc2[2][8][4] = {};

    for (int ch = 0; ch < 32; ch++) {
        int buf = ch & 1;
        asm volatile("cp.async.wait_group 0;");
        __syncthreads();
        if (ch + 1 < 32) {
            unsigned off = (buf ^ 1) * 16384u;
            const __half* s1 = W1 + ((size_t)(ch + 1) * 64 + w1row) * 128 + w1kc * 32;
            unsigned d1 = baseW1 + off + w1kc * 4096 + w1row * 64;
            #pragma unroll
            for (int q = 0; q < 4; q++) cpa16(d1 + ((q ^ w1swz)) * 16, s1 + q * 8);
            const __half* s2 = W2 + (size_t)w2row * FFD + (ch + 1) * 64 + w2kc * 32;
            unsigned d2 = baseW2 + off + w2kc * 8192 + w2row * 64;
            #pragma unroll
            for (int q = 0; q < 4; q++) cpa16(d2 + ((q ^ w2swz)) * 16, s2 + q * 8);
        }
        asm volatile("cp.async.commit_group;");

        unsigned w1b = baseW1 + buf * 16384u;
        // GEMM1: H(128x64) = X(128x128) @ W1c(64x128)^T, two register halves
        #pragma unroll
        for (int half = 0; half < 2; half++) {
            float acc1[2][2][4] = {};
            #pragma unroll
            for (int kc = 0; kc < 4; kc++) {
                #pragma unroll
                for (int ks = 0; ks < 2; ks++) {
                    unsigned af[2][4];
                    #pragma unroll
                    for (int mt = 0; mt < 2; mt++) {
                        unsigned addr = baseSX + kc * 8192 + (rA0 + mt * 16) * 64 + (((2 * ks + kselA) ^ swA)) * 16;
                        lmx4(af[mt][0], af[mt][1], af[mt][2], af[mt][3], addr);
                    }
                    unsigned bf[2][2];
                    unsigned addr = w1b + kc * 4096 + (rB1 + half * 16) * 64 + (((2 * ks + kselB) ^ swB1)) * 16;
                    lmx4(bf[0][0], bf[0][1], bf[1][0], bf[1][1], addr);
                    #pragma unroll
                    for (int ntl = 0; ntl < 2; ntl++) {
                        mma_f16(acc1[0][ntl], af[0], bf[ntl][0], bf[ntl][1]);
                        mma_f16(acc1[1][ntl], af[1], bf[ntl][0], bf[ntl][1]);
                    }
                }
            }
            // bias + relu -> SH (swizzled). acc1[0] -> rows r0,r0+8; acc1[1] -> rows r0+16,r0+24.
            {
                int r0 = wm * 32 + g;
                int r1 = r0 + 8;
                int r2 = r0 + 16, r3 = r0 + 24;
                int sw0 = (r0 >> 1) & 3, sw1 = (r1 >> 1) & 3;
                int sw2 = (r2 >> 1) & 3, sw3 = (r3 >> 1) & 3;
                #pragma unroll
                for (int ntl = 0; ntl < 2; ntl++) {
                    int nt = half * 2 + ntl;
                    int c0 = wn * 32 + nt * 8 + 2 * tig;
                    float bv0 = bias1[ch * 64 + c0], bv1 = bias1[ch * 64 + c0 + 1];
                    unsigned h0 = h2pack(fmaxf(acc1[0][ntl][0] + bv0, 0.f), fmaxf(acc1[0][ntl][1] + bv1, 0.f));
                    unsigned h1 = h2pack(fmaxf(acc1[0][ntl][2] + bv0, 0.f), fmaxf(acc1[0][ntl][3] + bv1, 0.f));
                    unsigned h2 = h2pack(fmaxf(acc1[1][ntl][0] + bv0, 0.f), fmaxf(acc1[1][ntl][1] + bv1, 0.f));
                    unsigned h3 = h2pack(fmaxf(acc1[1][ntl][2] + bv0, 0.f), fmaxf(acc1[1][ntl][3] + bv1, 0.f));
                    int gsel = (c0 >> 3) & 3;    // granule within kc chunk (= nt)
                    int kc2 = c0 >> 5;           // = wn
                    unsigned a0 = baseSH + kc2 * 8192u + r0 * 64 + ((gsel ^ sw0)) * 16 + 4 * tig;
                    unsigned a1 = baseSH + kc2 * 8192u + r1 * 64 + ((gsel ^ sw1)) * 16 + 4 * tig;
                    unsigned a2 = baseSH + kc2 * 8192u + r2 * 64 + ((gsel ^ sw2)) * 16 + 4 * tig;
                    unsigned a3 = baseSH + kc2 * 8192u + r3 * 64 + ((gsel ^ sw3)) * 16 + 4 * tig;
                    asm volatile("st.shared.b32 [%0], %1;" :: "r"(a0), "r"(h0));
                    asm volatile("st.shared.b32 [%0], %1;" :: "r"(a1), "r"(h1));
                    asm volatile("st.shared.b32 [%0], %1;" :: "r"(a2), "r"(h2));
                    asm volatile("st.shared.b32 [%0], %1;" :: "r"(a3), "r"(h3));
                }
            }
        }
        __syncthreads();
        // GEMM2: acc2 += H(128x64) @ W2c(128x64)^T
        unsigned w2b = baseW2 + buf * 16384u;
        #pragma unroll
        for (int kc = 0; kc < 2; kc++) {
            #pragma unroll
            for (int ks = 0; ks < 2; ks++) {
                unsigned af[2][4];
                #pragma unroll
                for (int mt = 0; mt < 2; mt++) {
                    unsigned addr = baseSH + kc * 8192 + (rA0 + mt * 16) * 64 + (((2 * ks + kselA) ^ swA)) * 16;
                    lmx4(af[mt][0], af[mt][1], af[mt][2], af[mt][3], addr);
                }
                unsigned bf[8][2];
                #pragma unroll
                for (int jj = 0; jj < 4; jj++) {
                    unsigned addr = w2b + kc * 8192 + (rB0 + jj * 16) * 64 + (((2 * ks + kselB) ^ swB0)) * 16;
                    lmx4(bf[2 * jj][0], bf[2 * jj][1], bf[2 * jj + 1][0], bf[2 * jj + 1][1], addr);
                }
                #pragma unroll
                for (int nt = 0; nt < 8; nt++) {
                    mma_f16(acc2[0][nt], af[0], bf[nt][0], bf[nt][1]);
                    mma_f16(acc2[1][nt], af[1], bf[nt][0], bf[nt][1]);
                }
            }
        }
    }

    // epilogue: bias2 + residual + LayerNorm
    float sums[2][2], sqs[2][2];
    #pragma unroll
    for (int mt = 0; mt < 2; mt++) { sums[mt][0] = sums[mt][1] = sqs[mt][0] = sqs[mt][1] = 0.f; }
    #pragma unroll
    for (int mt = 0; mt < 2; mt++) {
        int r0 = bm + wm * 32 + mt * 16 + g;
        #pragma unroll
        for (int nt = 0; nt < 8; nt++) {
            int c0 = wn * 64 + nt * 8 + 2 * tig;
            float bv0 = bias2[c0], bv1 = bias2[c0 + 1];
            float v00 = acc2[mt][nt][0] + bv0 + X[(size_t)r0 * 128 + c0];
            float v01 = acc2[mt][nt][1] + bv1 + X[(size_t)r0 * 128 + c0 + 1];
            float v10 = acc2[mt][nt][2] + bv0 + X[(size_t)(r0 + 8) * 128 + c0];
            float v11 = acc2[mt][nt][3] + bv1 + X[(size_t)(r0 + 8) * 128 + c0 + 1];
            acc2[mt][nt][0] = v00; acc2[mt][nt][1] = v01;
            acc2[mt][nt][2] = v10; acc2[mt][nt][3] = v11;
            sums[mt][0] += v00 + v01; sqs[mt][0] += v00 * v00 + v01 * v01;
            sums[mt][1] += v10 + v11; sqs[mt][1] += v10 * v10 + v11 * v11;
        }
    }
    #pragma unroll
    for (int mt = 0; mt < 2; mt++)
        #pragma unroll
        for (int rp = 0; rp < 2; rp++) {
            float s = sums[mt][rp], q = sqs[mt][rp];
            s += __shfl_xor_sync(0xffffffffu, s, 1); q += __shfl_xor_sync(0xffffffffu, q, 1);
            s += __shfl_xor_sync(0xffffffffu, s, 2); q += __shfl_xor_sync(0xffffffffu, q, 2);
            sums[mt][rp] = s; sqs[mt][rp] = q;
        }
    __syncthreads();
    float* red = (float*)sm;
    if (tig == 0) {
        #pragma unroll
        for (int mt = 0; mt < 2; mt++)
            #pragma unroll
            for (int rp = 0; rp < 2; rp++) {
                int ix = ((warp * 16 + g) * 4 + mt * 2 + rp) * 2;
                red[ix] = sums[mt][rp]; red[ix + 1] = sqs[mt][rp];
            }
    }
    __syncthreads();
    float mean[2][2], inv[2][2];
    #pragma unroll
    for (int mt = 0; mt < 2; mt++)
        #pragma unroll
        for (int rp = 0; rp < 2; rp++) {
            int i0 = (((wm) * 16 + g) * 4 + mt * 2 + rp) * 2;
            int i1 = (((wm + 4) * 16 + g) * 4 + mt * 2 + rp) * 2;
            float s = red[i0] + red[i1];
            float q = red[i0 + 1] + red[i1 + 1];
            float mm = s * (1.f / 128.f);
            float var = q * (1.f / 128.f) - mm * mm;
            mean[mt][rp] = mm;
            inv[mt][rp] = rsqrtf(var + 1e-5f);
        }
    #pragma unroll
    for (int mt = 0; mt < 2; mt++) {
        int r0 = bm + wm * 32 + mt * 16 + g;
        #pragma unroll
        for (int nt = 0; nt < 8; nt++) {
            int c0 = wn * 64 + nt * 8 + 2 * tig;
            float g0 = gamma[c0], g1 = gamma[c0 + 1];
            float be0 = beta[c0], be1 = beta[c0 + 1];
            float v00 = (acc2[mt][nt][0] - mean[mt][0]) * inv[mt][0] * g0 + be0;
            float v01 = (acc2[mt][nt][1] - mean[mt][0]) * inv[mt][0] * g1 + be1;
            float v10 = (acc2[mt][nt][2] - mean[mt][1]) * inv[mt][1] * g0 + be0;
            float v11 = (acc2[mt][nt][3] - mean[mt][1]) * inv[mt][1] * g1 + be1;
            *(float2*)(X + (size_t)r0 * 128 + c0)       = make_float2(v00, v01);
            *(float2*)(X + (size_t)(r0 + 8) * 128 + c0) = make_float2(v10, v11);
            *(__half2*)(XH + (size_t)r0 * 128 + c0)       = __floats2half2_rn(v00, v01);
            *(__half2*)(XH + (size_t)(r0 + 8) * 128 + c0) = __floats2half2_rn(v10, v11);
        }
    }
}

// ---------------- split-K reduce + reparameterization + KLD -----------------
__global__ void k_zred(const float* __restrict__ eps, const int* __restrict__ iftrain) {
    int idx = blockIdx.x * 256 + threadIdx.x;
    int i = idx >> 7, j = idx & 127;
    float mu = 0.f, ls = 0.f;
    #pragma unroll
    for (int z = 0; z < 8; z++) {
        mu += g_PART[((size_t)z * NNODE + i) * 256 + j];
        ls += g_PART[((size_t)z * NNODE + i) * 256 + 128 + j];
    }
    ls = fminf(ls, 10.f);
    float zz = (*iftrain > 0) ? (mu + eps[idx] * expf(ls)) : mu;
    g_ZH[idx] = __float2half(zz);
    float term = 1.f + 2.f * ls - mu * mu - expf(2.f * ls);
    float bs = block_sum<8>(term);
    if (threadIdx.x == 0) atomicAdd(&g_kld, (double)bs);
}

// ---------------- build transformer input x ----------------
__global__ void k_xbuild(const float* __restrict__ w3, const float* __restrict__ b3) {
    int idx = blockIdx.x * 256 + threadIdx.x;
    int j = idx & 127;
    int tok = idx >> 7;
    int a = tok >> 7, h = tok & 127;
    float acc = b3[j];
    #pragma unroll
    for (int t = 0; t < OBS; t++)
        acc += g_OUTB[(size_t)((t << 8) + a) * H + h] * w3[j * OBS + t];
    g_X[idx] = acc;
    g_XH[idx] = __float2half(acc);
}

// ---------------- tensor-core flash attention (unchanged) -------------------
__global__ __launch_bounds__(256) void k_attn_tc() {
    __shared__ __half Qs[256][16];
    __shared__ __half Ks[256][16];
    __shared__ __half Vt[16][264];
    int bh = blockIdx.x;
    int b = bh >> 3, h = bh & 7;
    int tid = threadIdx.x, warp = tid >> 5, lane = tid & 31;
    int g = lane >> 2, tig = lane & 3;
    const __half* Qb = g_QKVH + ((size_t)((0 * 8 + h) * 128 + b)) * 4096;
    const __half* Kb = g_QKVH + ((size_t)((1 * 8 + h) * 128 + b)) * 4096;
    const __half* Vb = g_QKVH + ((size_t)((2 * 8 + h) * 128 + b)) * 4096;
    for (int i = tid; i < 512; i += 256) {
        ((uint4*)Qs)[i] = ((const uint4*)Qb)[i];
        ((uint4*)Ks)[i] = ((const uint4*)Kb)[i];
    }
    {
        const __half2* vp = (const __half2*)(Vb + (size_t)tid * 16);
        #pragma unroll
        for (int j = 0; j < 8; j++) {
            __half2 v = vp[j];
            Vt[2 * j][tid] = __low2half(v);
            Vt[2 * j + 1][tid] = __high2half(v);
        }
    }
    __syncthreads();

    unsigned qf[2][4];
    #pragma unroll
    for (int mt = 0; mt < 2; mt++) {
        int r = warp * 32 + mt * 16 + g;
        qf[mt][0] = *(const unsigned*)&Qs[r][2 * tig];
        qf[mt][1] = *(const unsigned*)&Qs[r + 8][2 * tig];
        qf[mt][2] = *(const unsigned*)&Qs[r][2 * tig + 8];
        qf[mt][3] = *(const unsigned*)&Qs[r + 8][2 * tig + 8];
    }
    float mr[2][2], lr[2][2], oa[2][2][4];
    #pragma unroll
    for (int mt = 0; mt < 2; mt++)
        #pragma unroll
        for (int rp = 0; rp < 2; rp++) { mr[mt][rp] = -1e30f; lr[mt][rp] = 0.f; }
    #pragma unroll
    for (int mt = 0; mt < 2; mt++)
        #pragma unroll
        for (int nv = 0; nv < 2; nv++)
            #pragma unroll
            for (int c = 0; c < 4; c++) oa[mt][nv][c] = 0.f;

    #pragma unroll
    for (int kt = 0; kt < 4; kt++) {
        float s[2][8][4] = {};
        #pragma unroll
        for (int nt = 0; nt < 8; nt++) {
            int sr = kt * 64 + nt * 8 + g;
            unsigned b0 = *(const unsigned*)&Ks[sr][2 * tig];
            unsigned b1 = *(const unsigned*)&Ks[sr][2 * tig + 8];
            mma_f16(s[0][nt], qf[0], b0, b1);
            mma_f16(s[1][nt], qf[1], b0, b1);
        }
        #pragma unroll
        for (int mt = 0; mt < 2; mt++) {
            float mx[2] = {-1e30f, -1e30f};
            #pragma unroll
            for (int nt = 0; nt < 8; nt++) {
                mx[0] = fmaxf(mx[0], fmaxf(s[mt][nt][0], s[mt][nt][1]));
                mx[1] = fmaxf(mx[1], fmaxf(s[mt][nt][2], s[mt][nt][3]));
            }
            float mnew[2], corr[2], sum[2] = {0.f, 0.f};
            #pragma unroll
            for (int rp = 0; rp < 2; rp++) {
                mx[rp] = fmaxf(mx[rp], __shfl_xor_sync(0xffffffffu, mx[rp], 1));
                mx[rp] = fmaxf(mx[rp], __shfl_xor_sync(0xffffffffu, mx[rp], 2));
                mnew[rp] = fmaxf(mr[mt][rp], mx[rp]);
                corr[rp] = __expf((mr[mt][rp] - mnew[rp]) * 0.25f);
                mr[mt][rp] = mnew[rp];
            }
            #pragma unroll
            for (int nt = 0; nt < 8; nt++) {
                s[mt][nt][0] = __expf((s[mt][nt][0] - mnew[0]) * 0.25f);
                s[mt][nt][1] = __expf((s[mt][nt][1] - mnew[0]) * 0.25f);
                s[mt][nt][2] = __expf((s[mt][nt][2] - mnew[1]) * 0.25f);
                s[mt][nt][3] = __expf((s[mt][nt][3] - mnew[1]) * 0.25f);
                sum[0] += s[mt][nt][0] + s[mt][nt][1];
                sum[1] += s[mt][nt][2] + s[mt][nt][3];
            }
            #pragma unroll
            for (int rp = 0; rp < 2; rp++) {
                sum[rp] += __shfl_xor_sync(0xffffffffu, sum[rp], 1);
                sum[rp] += __shfl_xor_sync(0xffffffffu, sum[rp], 2);
                lr[mt][rp] = lr[mt][rp] * corr[rp] + sum[rp];
            }
            #pragma unroll
            for (int nv = 0; nv < 2; nv++) {
                oa[mt][nv][0] *= corr[0]; oa[mt][nv][1] *= corr[0];
                oa[mt][nv][2] *= corr[1]; oa[mt][nv][3] *= corr[1];
            }
        }
        #pragma unroll
        for (int ks = 0; ks < 4; ks++) {
            unsigned pa[2][4];
            #pragma unroll
            for (int mt = 0; mt < 2; mt++) {
                pa[mt][0] = h2pack(s[mt][2 * ks][0], s[mt][2 * ks][1]);
                pa[mt][1] = h2pack(s[mt][2 * ks][2], s[mt][2 * ks][3]);
                pa[mt][2] = h2pack(s[mt][2 * ks + 1][0], s[mt][2 * ks + 1][1]);
                pa[mt][3] = h2pack(s[mt][2 * ks + 1][2], s[mt][2 * ks + 1][3]);
            }
            int kr = kt * 64 + ks * 16;
            #pragma unroll
            for (int nv = 0; nv < 2; nv++) {
                unsigned b0 = *(const unsigned*)&Vt[nv * 8 + g][kr + 2 * tig];
                unsigned b1 = *(const unsigned*)&Vt[nv * 8 + g][kr + 2 * tig + 8];
                mma_f16(oa[0][nv], pa[0], b0, b1);
                mma_f16(oa[1][nv], pa[1], b0, b1);
            }
        }
    }
    #pragma unroll
    for (int mt = 0; mt < 2; mt++) {
        int r0 = warp * 32 + mt * 16 + g;
        float il0 = 1.f / lr[mt][0], il1 = 1.f / lr[mt][1];
        #pragma unroll
        for (int nv = 0; nv < 2; nv++) {
            int d = nv * 8 + 2 * tig;
            *(__half2*)(g_OH + ((size_t)r0 * BB + b) * H + h * 16 + d) =
                __floats2half2_rn(oa[mt][nv][0] * il0, oa[mt][nv][1] * il0);
            *(__half2*)(g_OH + ((size_t)(r0 + 8) * BB + b) * H + h * 16 + d) =
                __floats2half2_rn(oa[mt][nv][2] * il1, oa[mt][nv][3] * il1);
        }
    }
}

// ---------------- final projection + traj output + traj loss ----------------
__global__ void k_traj(const float* __restrict__ w4, const float* __restrict__ b4,
                       const float* __restrict__ w5, const float* __restrict__ b5,
                       const float* __restrict__ traj_in, float* __restrict__ out) {
    int tt = blockIdx.x >> 8;
    int a  = blockIdx.x & 255;
    int b  = threadIdx.x;
    int o = tt + (OBS - PRED);
    const float* xr = g_X + ((size_t)a * 128 + b) * 128;
    float acc = b4[o];
    #pragma unroll 8
    for (int j = 0; j < 128; j++) acc += xr[j] * w4[o * 128 + j];
    float s0 = block_sum<4>(acc * w5[b]);
    float s1 = block_sum<4>(acc * w5[128 + b]);
    if (b == 0) {
        float t0 = s0 + b5[0], t1 = s1 + b5[1];
        float y0 = traj_in[(OBS + tt) * (NAG * 2) + a * 2 + 0];
        float y1 = traj_in[(OBS + tt) * (NAG * 2) + a * 2 + 1];
        out[(tt * 256 + a) * 2 + 0] = t0;
        out[(tt * 256 + a) * 2 + 1] = t1;
        float d0 = t0 - y0, d1 = t1 - y1;
        atomicAdd(&g_traj, (double)sqrtf(d0 * d0 + d1 * d1));
    }
}

__global__ void k_final(float* __restrict__ out) {
    double kld = -0.5 * (g_kld / 2048.0);
    double st = g_struct / (2048.0 * 2048.0);
    double tl = g_traj / 256.0;
    out[PRED * NAG * FOUT] = (float)(tl + kld + st);
}

// ---------------- launch ----------------
extern "C" void kernel_launch(void* const* d_in, const int* in_sizes, int n_in,
                              void* d_out, int out_size) {
    const float* traj_in = (const float*)d_in[0];
    const float* adj_in  = (const float*)d_in[1];
    const float* eps     = (const float*)d_in[2];
    const float* pro1_w  = (const float*)d_in[3];
    const float* pro1_b  = (const float*)d_in[4];
    const float* pro2_w  = (const float*)d_in[5];
    const float* pro2_b  = (const float*)d_in[6];
    const float* mu_w    = (const float*)d_in[7];
    const float* mu_b    = (const float*)d_in[8];
    const float* ls_w    = (const float*)d_in[9];
    const float* ls_b    = (const float*)d_in[10];
    const float* gdl_w   = (const float*)d_in[11];
    const float* gdl_b   = (const float*)d_in[12];
    const float* pro3_w  = (const float*)d_in[13];
    const float* pro3_b  = (const float*)d_in[14];
    const float* pro4_w  = (const float*)d_in[15];
    const float* pro4_b  = (const float*)d_in[16];
    const float* pro5_w  = (const float*)d_in[17];
    const float* pro5_b  = (const float*)d_in[18];
    const float* qkv_w   = (const float*)d_in[19];
    const float* qkv_b   = (const float*)d_in[20];
    const float* out_w   = (const float*)d_in[21];
    const float* out_b   = (const float*)d_in[22];
    const float* ff1_w   = (const float*)d_in[23];
    const float* ff1_b   = (const float*)d_in[24];
    const float* ff2_w   = (const float*)d_in[25];
    const float* ff2_b   = (const float*)d_in[26];
    const float* ln1_g   = (const float*)d_in[27];
    const float* ln1_b   = (const float*)d_in[28];
    const float* ln2_g   = (const float*)d_in[29];
    const float* ln2_b   = (const float*)d_in[30];
    const int*   iftrain = (const int*)d_in[31];
    float* out = (float*)d_out;

    float *pOUTB, *pBMLS, *pX, *pPART;
    __half *pMLSH, *pAGGH, *pENCH, *pZH, *pXH, *pOH, *pQKVH;
    __half *pWQKVH, *pWOUTH, *pWFF1H, *pWFF2H, *pWGDLH, *pWMLSH;
    cudaGetSymbolAddress((void**)&pOUTB,  g_OUTB);
    cudaGetSymbolAddress((void**)&pBMLS,  g_BMLS);
    cudaGetSymbolAddress((void**)&pX,     g_X);
    cudaGetSymbolAddress((void**)&pPART,  g_PART);
    cudaGetSymbolAddress((void**)&pMLSH,  g_MLSH);
    cudaGetSymbolAddress((void**)&pAGGH,  g_AGGH);
    cudaGetSymbolAddress((void**)&pENCH,  g_ENCH);
    cudaGetSymbolAddress((void**)&pZH,    g_ZH);
    cudaGetSymbolAddress((void**)&pXH,    g_XH);
    cudaGetSymbolAddress((void**)&pOH,    g_OH);
    cudaGetSymbolAddress((void**)&pQKVH,  g_QKVH);
    cudaGetSymbolAddress((void**)&pWQKVH, g_WQKVH);
    cudaGetSymbolAddress((void**)&pWOUTH, g_WOUTH);
    cudaGetSymbolAddress((void**)&pWFF1H, g_WFF1H);
    cudaGetSymbolAddress((void**)&pWFF2H, g_WFF2H);
    cudaGetSymbolAddress((void**)&pWGDLH, g_WGDLH);
    cudaGetSymbolAddress((void**)&pWMLSH, g_WMLSH);

    static int smem_set = 0;
    if (!smem_set) {
        cudaFuncSetAttribute(k_ffn, cudaFuncAttributeMaxDynamicSharedMemorySize, 114688);
        smem_set = 1;
    }

    // ---- fused weight conversion + packing ----
    k_cvt<<<3505, 256>>>(qkv_w, out_w, ff1_w, ff2_w, gdl_w, mu_w, ls_w, mu_b, ls_b);

    // ---- graph-VAE front end ----
    k_init<<<8, 256>>>();
    k_minmax<<<512, 256>>>(adj_in);
    k_build<<<dim3(2, NNODE), 256>>>(adj_in);
    k_colsum<<<dim3(16, 64), 128>>>();
    k_dis<<<8, 256>>>();
    k_agg<<<dim3(64, 64), dim3(32, 32)>>>();
    k_enc<<<NNODE, 128>>>(traj_in, pro1_w, pro1_b, pro2_w, pro2_b);

    k_hgemm<5><<<dim3(2, 16), 256>>>(pENCH, pWMLSH, pBMLS, nullptr, pMLSH,
                                     NNODE, 256, H, nullptr, nullptr);
    k_hgemm<7><<<dim3(2, 16, 8), 256>>>(pAGGH, pMLSH, nullptr, pPART, nullptr,
                                        NNODE, 256, NNODE, nullptr, nullptr);
    k_zred<<<1024, 256>>>(eps, iftrain);
    k_hgemm<6><<<dim3(16, 16), 256>>>(pZH, pZH, nullptr, nullptr, nullptr,
                                      NNODE, NNODE, H, nullptr, nullptr);
    k_hgemm<0><<<dim3(1, 16), 256>>>(pZH, pWGDLH, gdl_b, pOUTB, nullptr,
                                     NNODE, H, H, nullptr, nullptr);
    k_xbuild<<<16384, 256>>>(pro3_w, pro3_b);

    // ---- transformer ----
    for (int l = 0; l < NL; l++) {
        k_hgemm<1><<<dim3(3, 256), 256>>>(pXH, pWQKVH + (size_t)l * 3 * H * H, qkv_b + (size_t)l * 3 * H,
                                          nullptr, pQKVH, NTOK, 3 * H, H, nullptr, nullptr);
        k_attn_tc<<<BB * NH, 256>>>();
        k_hgemm<2><<<dim3(1, 256), 256>>>(pOH, pWOUTH + (size_t)l * H * H, out_b + (size_t)l * H,
                                          pX, pXH, NTOK, H, H, ln1_g + l * H, ln1_b + l * H);
        k_ffn<<<256, 256, 114688>>>(ff1_b + (size_t)l * FFD, ff2_b + (size_t)l * H,
                                    pWFF1H + (size_t)l * FFD * H, pWFF2H + (size_t)l * H * FFD,
                                    pX, pXH, ln2_g + l * H, ln2_b + l * H);
    }

    // ---- output + loss ----
    k_traj<<<PRED * NAG, 128>>>(pro4_w, pro4_b, pro5_w, pro5_b, traj_in, out);
    k_final<<<1, 1>>>(out);
}

// round 12
// speedup vs baseline: 1.1394x; 1.1394x over previous
#include <cuda_runtime.h>
#include <cuda_fp16.h>
#include <math.h>

#define OBS 8
#define PRED 4
#define NAG 256
#define FIN 2
#define FOUT 2
#define H 128
#define NH 8
#define DH 16
#define FFD 2048
#define NL 6
#define NNODE (OBS*NAG)        /* 2048 */
#define SEQ NAG                /* 256  */
#define BB H                   /* 128  */
#define NTOK (SEQ*BB)          /* 32768 */

// ---------------- scratch (device globals; no allocation) ----------------
static __device__ float  g_ADJ[NNODE*NNODE];
static __device__ __half g_AGGH[NNODE*NNODE];
static __device__ __half g_ENCH[NNODE*H];
static __device__ __half g_MLSH[2*H*NNODE];
static __device__ float  g_PART[8*NNODE*2*H];
static __device__ __half g_ZH[NNODE*H];
static __device__ float  g_OUTB[NNODE*H];
static __device__ float  g_X[NTOK*H];
static __device__ __half g_XH[NTOK*H];
static __device__ __half g_OH[NTOK*H];
static __device__ __half g_QKVH[NTOK*3*H];
static __device__ __half g_WQKVH[NL*3*H*H];
static __device__ __half g_WOUTH[NL*H*H];
static __device__ __half g_WFF1H[(size_t)NL*FFD*H];
static __device__ __half g_WFF2H[(size_t)NL*H*FFD];
static __device__ __half g_WGDLH[H*H];
static __device__ __half g_WMLSH[2*H*H];
static __device__ float  g_BMLS[2*H];
static __device__ float  g_COL[NNODE];
static __device__ float  g_SELF[NNODE];
static __device__ float  g_DIS[NNODE];
static __device__ float  g_mn_acc, g_mx_acc;
static __device__ double g_kld, g_struct, g_traj;

// ---------------- helpers ----------------
__device__ __forceinline__ void atomicMinF(float* a, float v) {
    int* ai = (int*)a; int old = *ai;
    while (__int_as_float(old) > v) {
        int assumed = old;
        old = atomicCAS(ai, assumed, __float_as_int(v));
        if (old == assumed) break;
    }
}
__device__ __forceinline__ void atomicMaxF(float* a, float v) {
    int* ai = (int*)a; int old = *ai;
    while (__int_as_float(old) < v) {
        int assumed = old;
        old = atomicCAS(ai, assumed, __float_as_int(v));
        if (old == assumed) break;
    }
}

template<int NWARPS>
__device__ __forceinline__ float block_sum(float v) {
    __shared__ float w[NWARPS];
    int tid = threadIdx.x + threadIdx.y * blockDim.x;
    int lane = tid & 31, wid = tid >> 5;
    #pragma unroll
    for (int o = 16; o > 0; o >>= 1) v += __shfl_down_sync(0xffffffffu, v, o);
    if (lane == 0) w[wid] = v;
    __syncthreads();
    float r = 0.f;
    #pragma unroll
    for (int i = 0; i < NWARPS; i++) r += w[i];
    __syncthreads();
    return r;
}

__device__ __forceinline__ void mma_f16(float* c, const unsigned* a, unsigned b0, unsigned b1) {
    asm volatile(
        "mma.sync.aligned.m16n8k16.row.col.f32.f16.f16.f32 "
        "{%0,%1,%2,%3}, {%4,%5,%6,%7}, {%8,%9}, {%0,%1,%2,%3};"
        : "+f"(c[0]), "+f"(c[1]), "+f"(c[2]), "+f"(c[3])
        : "r"(a[0]), "r"(a[1]), "r"(a[2]), "r"(a[3]), "r"(b0), "r"(b1));
}

__device__ __forceinline__ unsigned h2pack(float x, float y) {
    __half2 h = __floats2half2_rn(x, y);
    return *(unsigned*)&h;
}

__device__ __forceinline__ unsigned smem_u32(const void* p) {
    return (unsigned)__cvta_generic_to_shared(p);
}
__device__ __forceinline__ void cpa16(unsigned dst, const void* src) {
    asm volatile("cp.async.cg.shared.global [%0], [%1], 16;" :: "r"(dst), "l"(src));
}
__device__ __forceinline__ void lmx4(unsigned& r0, unsigned& r1, unsigned& r2, unsigned& r3, unsigned addr) {
    asm volatile("ldmatrix.sync.aligned.m8n8.x4.shared.b16 {%0,%1,%2,%3}, [%4];"
                 : "=r"(r0), "=r"(r1), "=r"(r2), "=r"(r3) : "r"(addr));
}

// Load a 128x128 half tile into 4 swizzled 8KB sub-buffers.
__device__ __forceinline__ void load_tile128(unsigned dstBase, const __half* src, int srcStride, int tid) {
    int crow = tid >> 1, cpi = (tid & 1) * 2;
    int cswz = (crow >> 1) & 3;
    #pragma unroll
    for (int kc = 0; kc < 4; kc++) {
        const __half* s = src + (size_t)crow * srcStride + kc * 32 + cpi * 8;
        unsigned d = dstBase + kc * 8192 + crow * 64;
        cpa16(d + ((cpi ^ cswz)) * 16, s);
        cpa16(d + (((cpi + 1) ^ cswz)) * 16, s + 8);
    }
}

__device__ __forceinline__ void gemm128(float (&acc)[2][8][4], unsigned abase, unsigned bbase,
                                        int rA0, int rB0, int swA, int swB, int kselA, int kselB) {
    #pragma unroll
    for (int kc = 0; kc < 4; kc++) {
        #pragma unroll
        for (int ks = 0; ks < 2; ks++) {
            unsigned af[2][4];
            #pragma unroll
            for (int mt = 0; mt < 2; mt++) {
                unsigned addr = abase + kc * 8192 + (rA0 + mt * 16) * 64 + (((2 * ks + kselA) ^ swA)) * 16;
                lmx4(af[mt][0], af[mt][1], af[mt][2], af[mt][3], addr);
            }
            unsigned bf[8][2];
            #pragma unroll
            for (int jj = 0; jj < 4; jj++) {
                unsigned addr = bbase + kc * 8192 + (rB0 + jj * 16) * 64 + (((2 * ks + kselB) ^ swB)) * 16;
                lmx4(bf[2 * jj][0], bf[2 * jj][1], bf[2 * jj + 1][0], bf[2 * jj + 1][1], addr);
            }
            #pragma unroll
            for (int nt = 0; nt < 8; nt++) {
                mma_f16(acc[0][nt], af[0], bf[nt][0], bf[nt][1]);
                mma_f16(acc[1][nt], af[1], bf[nt][0], bf[nt][1]);
            }
        }
    }
}

// ---------------- init ----------------
__global__ void k_init() {
    int i = blockIdx.x * 256 + threadIdx.x;
    if (i < NNODE) g_COL[i] = 0.f;
    if (i == 0) {
        g_mn_acc = __int_as_float(0x7f800000);
        g_mx_acc = __int_as_float(0xff800000);
        g_kld = 0.0; g_struct = 0.0; g_traj = 0.0;
    }
}

// ---------------- fused weight conversion ----------------
__global__ void k_cvt(const float* __restrict__ qkv, const float* __restrict__ outw,
                      const float* __restrict__ ff1, const float* __restrict__ ff2,
                      const float* __restrict__ gdl, const float* __restrict__ muw,
                      const float* __restrict__ lsw, const float* __restrict__ mub,
                      const float* __restrict__ lsb) {
    int k = blockIdx.x * 256 + threadIdx.x;
    const float* src; __half* dst; int off;
    if (k < 73728)       { src = qkv;  dst = g_WQKVH;        off = k; }
    else if (k < 98304)  { src = outw; dst = g_WOUTH;        off = k - 73728; }
    else if (k < 491520) { src = ff1;  dst = g_WFF1H;        off = k - 98304; }
    else if (k < 884736) { src = ff2;  dst = g_WFF2H;        off = k - 491520; }
    else if (k < 888832) { src = gdl;  dst = g_WGDLH;        off = k - 884736; }
    else if (k < 892928) { src = muw;  dst = g_WMLSH;        off = k - 888832; }
    else if (k < 897024) { src = lsw;  dst = g_WMLSH + H*H;  off = k - 892928; }
    else if (k < 897088) {
        int o = k - 897024;
        float4 v = (o < 32) ? ((const float4*)mub)[o] : ((const float4*)lsb)[o - 32];
        ((float4*)g_BMLS)[o] = v;
        return;
    } else return;
    float4 v = ((const float4*)src)[off];
    __half2* d = (__half2*)dst + off * 2;
    d[0] = __floats2half2_rn(v.x, v.y);
    d[1] = __floats2half2_rn(v.z, v.w);
}

// ---------------- adjacency prep ----------------
__global__ void k_minmax(const float* __restrict__ adj) {
    const int n = OBS * NAG * NAG;
    float mn = __int_as_float(0x7f800000), mx = -mn;
    for (int i = blockIdx.x * blockDim.x + threadIdx.x; i < n; i += gridDim.x * blockDim.x) {
        float v = adj[i];
        mn = fminf(mn, v); mx = fmaxf(mx, v);
    }
    #pragma unroll
    for (int o = 16; o > 0; o >>= 1) {
        mn = fminf(mn, __shfl_down_sync(0xffffffffu, mn, o));
        mx = fmaxf(mx, __shfl_down_sync(0xffffffffu, mx, o));
    }
    __shared__ float smn[8], smx[8];
    int lane = threadIdx.x & 31, wid = threadIdx.x >> 5;
    if (lane == 0) { smn[wid] = mn; smx[wid] = mx; }
    __syncthreads();
    if (threadIdx.x == 0) {
        for (int w = 1; w < 8; w++) { mn = fminf(mn, smn[w]); mx = fmaxf(mx, smx[w]); }
        atomicMinF(&g_mn_acc, mn);
        atomicMaxF(&g_mx_acc, mx);
    }
}

__global__ void k_build(const float* __restrict__ adj) {
    float mn = fminf(g_mn_acc, 0.f);
    float mx = fmaxf(g_mx_acc, 0.f);
    float inv = 1.f / (mx - mn);
    int i = blockIdx.y;
    int j = (blockIdx.x * 256 + threadIdx.x) * 4;
    int ti = i >> 8, tj = j >> 8;
    float4 a = make_float4(0.f, 0.f, 0.f, 0.f);
    if (ti == tj)
        a = *(const float4*)(adj + (ti << 16) + ((i & 255) << 8) + (j & 255));
    float4 v = make_float4((a.x - mn) * inv, (a.y - mn) * inv, (a.z - mn) * inv, (a.w - mn) * inv);
    *(float4*)(g_ADJ + (size_t)i * NNODE + j) = v;
    if (i >= j && i < j + 4) {
        float d = (i == j) ? v.x : (i == j + 1) ? v.y : (i == j + 2) ? v.z : v.w;
        g_SELF[i] = (d == 0.f) ? 1.f : 0.f;
    }
}

__global__ void k_colsum() {
    int j = blockIdx.x * 128 + threadIdx.x;
    int i0 = blockIdx.y * 32;
    float s = 0.f;
    for (int r = 0; r < 32; r++) s += g_ADJ[(size_t)(i0 + r) * NNODE + j];
    atomicAdd(&g_COL[j], s);
}

__global__ void k_dis() {
    int j = blockIdx.x * 256 + threadIdx.x;
    if (j < NNODE) {
        float deg = g_COL[j] + g_SELF[j];
        g_DIS[j] = (deg > 0.f) ? (1.f / sqrtf(deg)) : 0.f;
    }
}

__global__ void k_agg() {
    __shared__ float s[32][33];
    int i0 = blockIdx.y * 32, j0 = blockIdx.x * 32;
    int tx = threadIdx.x, ty = threadIdx.y;
    s[ty][tx] = g_ADJ[(size_t)(j0 + ty) * NNODE + (i0 + tx)];
    __syncthreads();
    int i = i0 + ty, j = j0 + tx;
    float v = s[tx][ty];
    if (i == j) v += g_SELF[i];
    g_AGGH[(size_t)i * NNODE + j] = __float2half(g_DIS[j] * v * g_DIS[i]);
}

// ---------------- encoder ----------------
__global__ void k_enc(const float* __restrict__ traj,
                      const float* __restrict__ w1, const float* __restrict__ b1,
                      const float* __restrict__ w2, const float* __restrict__ b2) {
    int n = blockIdx.x, j = threadIdx.x;
    __shared__ float h1[128];
    float x0 = traj[n * 2], x1 = traj[n * 2 + 1];
    h1[j] = fmaxf(w1[j * 2] * x0 + w1[j * 2 + 1] * x1 + b1[j], 0.f);
    __syncthreads();
    float a = b2[j];
    #pragma unroll 8
    for (int k = 0; k < 128; k++) a += w2[j * 128 + k] * h1[k];
    g_ENCH[n * 128 + j] = __float2half(a);
}

// ---------------- fp16 TC GEMM, cp.async 3-stage + ldmatrix ------------------
template<int EPI>
__global__ __launch_bounds__(256, 2) void k_hgemm(
    const __half* __restrict__ A, const __half* __restrict__ B,
    const float* __restrict__ bias, float* __restrict__ C, __half* __restrict__ Ch,
    int M, int N, int K,
    const float* __restrict__ gamma, const float* __restrict__ beta)
{
    __shared__ __align__(16) __half SA[3][4096];
    __shared__ __align__(16) __half SB[3][4096];
    int bm = blockIdx.y * 128, bn = blockIdx.x * 128;
    int tid = threadIdx.x;
    int warp = tid >> 5, lane = tid & 31;
    int wm = warp & 3, wn = warp >> 2;
    int g = lane >> 2, tig = lane & 3;

    int ksz = K / gridDim.z;
    int k_begin = blockIdx.z * ksz;
    const int nch = ksz >> 5;

    unsigned baseSA = smem_u32(&SA[0][0]);
    unsigned baseSB = smem_u32(&SB[0][0]);

    int crow = tid >> 1, cp = (tid & 1) * 2;
    int cswz = (crow >> 1) & 3;
    unsigned dA0 = baseSA + crow * 64 + ((cp ^ cswz)) * 16;
    unsigned dA1 = baseSA + crow * 64 + (((cp + 1) ^ cswz)) * 16;
    unsigned dB0 = baseSB + crow * 64 + ((cp ^ cswz)) * 16;
    unsigned dB1 = baseSB + crow * 64 + (((cp + 1) ^ cswz)) * 16;
    const __half* srcA = A + (size_t)(bm + crow) * K + k_begin + cp * 8;
    const __half* srcB = B + (size_t)(bn + crow) * K + k_begin + cp * 8;

    int m = lane >> 3, mi = lane & 7;
    int rA0 = wm * 32 + ((m & 1) << 3) + mi;
    int rB0 = wn * 64 + ((m >> 1) << 3) + mi;
    int swA = (rA0 >> 1) & 3;
    int swB = (rB0 >> 1) & 3;
    int kselA = m >> 1, kselB = m & 1;

    float acc[2][8][4] = {};

    #pragma unroll
    for (int s = 0; s < 2; s++) {
        if (s < nch) {
            unsigned so = s * 8192u;
            cpa16(dA0 + so, srcA + s * 32);
            cpa16(dA1 + so, srcA + s * 32 + 8);
            cpa16(dB0 + so, srcB + s * 32);
            cpa16(dB1 + so, srcB + s * 32 + 8);
        }
        asm volatile("cp.async.commit_group;");
    }

    for (int c = 0; c < nch; c++) {
        asm volatile("cp.async.wait_group 1;");
        __syncthreads();
        int pf = c + 2;
        if (pf < nch) {
            unsigned so = (pf % 3) * 8192u;
            cpa16(dA0 + so, srcA + pf * 32);
            cpa16(dA1 + so, srcA + pf * 32 + 8);
            cpa16(dB0 + so, srcB + pf * 32);
            cpa16(dB1 + so, srcB + pf * 32 + 8);
        }
        asm volatile("cp.async.commit_group;");
        unsigned so = (c % 3) * 8192u;
        #pragma unroll
        for (int ks = 0; ks < 2; ks++) {
            unsigned af[2][4];
            #pragma unroll
            for (int mt = 0; mt < 2; mt++) {
                unsigned addr = baseSA + so + (rA0 + mt * 16) * 64 + (((2 * ks + kselA) ^ swA)) * 16;
                lmx4(af[mt][0], af[mt][1], af[mt][2], af[mt][3], addr);
            }
            unsigned bf[8][2];
            #pragma unroll
            for (int jj = 0; jj < 4; jj++) {
                unsigned addr = baseSB + so + (rB0 + jj * 16) * 64 + (((2 * ks + kselB) ^ swB)) * 16;
                lmx4(bf[2 * jj][0], bf[2 * jj][1], bf[2 * jj + 1][0], bf[2 * jj + 1][1], addr);
            }
            #pragma unroll
            for (int nt = 0; nt < 8; nt++) {
                mma_f16(acc[0][nt], af[0], bf[nt][0], bf[nt][1]);
                mma_f16(acc[1][nt], af[1], bf[nt][0], bf[nt][1]);
            }
        }
    }

    if (EPI == 0) {
        #pragma unroll
        for (int mt = 0; mt < 2; mt++) {
            int r0 = bm + wm * 32 + mt * 16 + g;
            #pragma unroll
            for (int nt = 0; nt < 8; nt++) {
                int c0 = bn + wn * 64 + nt * 8 + 2 * tig;
                float bv0 = bias[c0], bv1 = bias[c0 + 1];
                *(float2*)(C + (size_t)r0 * N + c0) =
                    make_float2(acc[mt][nt][0] + bv0, acc[mt][nt][1] + bv1);
                *(float2*)(C + (size_t)(r0 + 8) * N + c0) =
                    make_float2(acc[mt][nt][2] + bv0, acc[mt][nt][3] + bv1);
            }
        }
    } else if (EPI == 1) {
        int p = blockIdx.x;
        #pragma unroll
        for (int mt = 0; mt < 2; mt++) {
            int r0 = bm + wm * 32 + mt * 16 + g;
            int r1 = r0 + 8;
            #pragma unroll
            for (int nt = 0; nt < 8; nt++) {
                int rem = wn * 64 + nt * 8 + 2 * tig;
                int h = rem >> 4, d = rem & 15;
                int c0 = bn + rem;
                float bv0 = bias[c0], bv1 = bias[c0 + 1];
                size_t b0 = ((size_t)((p * 8 + h) * 128 + (r0 & 127)) * 256 + (r0 >> 7)) * 16 + d;
                size_t b1 = ((size_t)((p * 8 + h) * 128 + (r1 & 127)) * 256 + (r1 >> 7)) * 16 + d;
                *(__half2*)(Ch + b0) = __floats2half2_rn(acc[mt][nt][0] + bv0, acc[mt][nt][1] + bv1);
                *(__half2*)(Ch + b1) = __floats2half2_rn(acc[mt][nt][2] + bv0, acc[mt][nt][3] + bv1);
            }
        }
    } else if (EPI == 2) {
        float sums[2][2], sqs[2][2];
        #pragma unroll
        for (int mt = 0; mt < 2; mt++) { sums[mt][0] = sums[mt][1] = sqs[mt][0] = sqs[mt][1] = 0.f; }
        #pragma unroll
        for (int mt = 0; mt < 2; mt++) {
            int r0 = bm + wm * 32 + mt * 16 + g;
            #pragma unroll
            for (int nt = 0; nt < 8; nt++) {
                int c0 = wn * 64 + nt * 8 + 2 * tig;
                float bv0 = bias[c0], bv1 = bias[c0 + 1];
                float v00 = acc[mt][nt][0] + bv0 + C[(size_t)r0 * 128 + c0];
                float v01 = acc[mt][nt][1] + bv1 + C[(size_t)r0 * 128 + c0 + 1];
                float v10 = acc[mt][nt][2] + bv0 + C[(size_t)(r0 + 8) * 128 + c0];
                float v11 = acc[mt][nt][3] + bv1 + C[(size_t)(r0 + 8) * 128 + c0 + 1];
                acc[mt][nt][0] = v00; acc[mt][nt][1] = v01;
                acc[mt][nt][2] = v10; acc[mt][nt][3] = v11;
                sums[mt][0] += v00 + v01; sqs[mt][0] += v00 * v00 + v01 * v01;
                sums[mt][1] += v10 + v11; sqs[mt][1] += v10 * v10 + v11 * v11;
            }
        }
        #pragma unroll
        for (int mt = 0; mt < 2; mt++)
            #pragma unroll
            for (int rp = 0; rp < 2; rp++) {
                float s = sums[mt][rp], q = sqs[mt][rp];
                s += __shfl_xor_sync(0xffffffffu, s, 1); q += __shfl_xor_sync(0xffffffffu, q, 1);
                s += __shfl_xor_sync(0xffffffffu, s, 2); q += __shfl_xor_sync(0xffffffffu, q, 2);
                sums[mt][rp] = s; sqs[mt][rp] = q;
            }
        __syncthreads();
        float* red = (float*)SA;
        if (tig == 0) {
            #pragma unroll
            for (int mt = 0; mt < 2; mt++)
                #pragma unroll
                for (int rp = 0; rp < 2; rp++) {
                    int ix = ((warp * 16 + g) * 4 + mt * 2 + rp) * 2;
                    red[ix] = sums[mt][rp]; red[ix + 1] = sqs[mt][rp];
                }
        }
        __syncthreads();
        float mean[2][2], inv[2][2];
        #pragma unroll
        for (int mt = 0; mt < 2; mt++)
            #pragma unroll
            for (int rp = 0; rp < 2; rp++) {
                int i0 = (((wm) * 16 + g) * 4 + mt * 2 + rp) * 2;
                int i1 = (((wm + 4) * 16 + g) * 4 + mt * 2 + rp) * 2;
                float s = red[i0] + red[i1];
                float q = red[i0 + 1] + red[i1 + 1];
                float mm = s * (1.f / 128.f);
                float var = q * (1.f / 128.f) - mm * mm;
                mean[mt][rp] = mm;
                inv[mt][rp] = rsqrtf(var + 1e-5f);
            }
        #pragma unroll
        for (int mt = 0; mt < 2; mt++) {
            int r0 = bm + wm * 32 + mt * 16 + g;
            #pragma unroll
            for (int nt = 0; nt < 8; nt++) {
                int c0 = wn * 64 + nt * 8 + 2 * tig;
                float g0 = gamma[c0], g1 = gamma[c0 + 1];
                float be0 = beta[c0], be1 = beta[c0 + 1];
                float v00 = (acc[mt][nt][0] - mean[mt][0]) * inv[mt][0] * g0 + be0;
                float v01 = (acc[mt][nt][1] - mean[mt][0]) * inv[mt][0] * g1 + be1;
                float v10 = (acc[mt][nt][2] - mean[mt][1]) * inv[mt][1] * g0 + be0;
                float v11 = (acc[mt][nt][3] - mean[mt][1]) * inv[mt][1] * g1 + be1;
                *(float2*)(C + (size_t)r0 * 128 + c0)       = make_float2(v00, v01);
                *(float2*)(C + (size_t)(r0 + 8) * 128 + c0) = make_float2(v10, v11);
                *(__half2*)(Ch + (size_t)r0 * 128 + c0)       = __floats2half2_rn(v00, v01);
                *(__half2*)(Ch + (size_t)(r0 + 8) * 128 + c0) = __floats2half2_rn(v10, v11);
            }
        }
    } else if (EPI == 5) {
        #pragma unroll
        for (int mt = 0; mt < 2; mt++) {
            int r0 = bm + wm * 32 + mt * 16 + g;
            #pragma unroll
            for (int nt = 0; nt < 8; nt++) {
                int c0 = bn + wn * 64 + nt * 8 + 2 * tig;
                float bv0 = bias[c0], bv1 = bias[c0 + 1];
                Ch[(size_t)c0 * M + r0]           = __float2half(acc[mt][nt][0] + bv0);
                Ch[(size_t)(c0 + 1) * M + r0]     = __float2half(acc[mt][nt][1] + bv1);
                Ch[(size_t)c0 * M + r0 + 8]       = __float2half(acc[mt][nt][2] + bv0);
                Ch[(size_t)(c0 + 1) * M + r0 + 8] = __float2half(acc[mt][nt][3] + bv1);
            }
        }
    } else if (EPI == 6) {
        float contrib = 0.f;
        #pragma unroll
        for (int mt = 0; mt < 2; mt++) {
            int r0 = bm + wm * 32 + mt * 16 + g;
            #pragma unroll
            for (int nt = 0; nt < 8; nt++) {
                int c0 = bn + wn * 64 + nt * 8 + 2 * tig;
                float2 ad0 = *(const float2*)(g_ADJ + (size_t)r0 * NNODE + c0);
                float2 ad1 = *(const float2*)(g_ADJ + (size_t)(r0 + 8) * NNODE + c0);
                float a00 = acc[mt][nt][0], a01 = acc[mt][nt][1];
                float a10 = acc[mt][nt][2], a11 = acc[mt][nt][3];
                contrib += fmaxf(a00, 0.f) - a00 * ad0.x + log1pf(expf(-fabsf(a00)));
                contrib += fmaxf(a01, 0.f) - a01 * ad0.y + log1pf(expf(-fabsf(a01)));
                contrib += fmaxf(a10, 0.f) - a10 * ad1.x + log1pf(expf(-fabsf(a10)));
                contrib += fmaxf(a11, 0.f) - a11 * ad1.y + log1pf(expf(-fabsf(a11)));
            }
        }
        #pragma unroll
        for (int o = 16; o > 0; o >>= 1) contrib += __shfl_down_sync(0xffffffffu, contrib, o);
        __syncthreads();
        float* red = (float*)SA;
        if (lane == 0) red[warp] = contrib;
        __syncthreads();
        if (tid == 0) {
            float s = 0.f;
            for (int w = 0; w < 8; w++) s += red[w];
            atomicAdd(&g_struct, (double)s);
        }
    } else { // EPI == 7
        float* P = C + (size_t)blockIdx.z * M * N;
        #pragma unroll
        for (int mt = 0; mt < 2; mt++) {
            int r0 = bm + wm * 32 + mt * 16 + g;
            #pragma unroll
            for (int nt = 0; nt < 8; nt++) {
                int c0 = bn + wn * 64 + nt * 8 + 2 * tig;
                *(float2*)(P + (size_t)r0 * N + c0)       = make_float2(acc[mt][nt][0], acc[mt][nt][1]);
                *(float2*)(P + (size_t)(r0 + 8) * N + c0) = make_float2(acc[mt][nt][2], acc[mt][nt][3]);
            }
        }
    }
}

// ---------------- fused FF (R9 192KB variant: 16 chunks of 128) --------------
__global__ __launch_bounds__(256, 1) void k_ffn(
    const float* __restrict__ bias1, const float* __restrict__ bias2,
    const __half* __restrict__ W1, const __half* __restrict__ W2,
    float* __restrict__ X, __half* __restrict__ XH,
    const float* __restrict__ gamma, const float* __restrict__ beta)
{
    extern __shared__ __align__(16) __half sm[];
    unsigned baseSX = smem_u32(sm);
    unsigned baseSH = baseSX + 32768;
    unsigned baseW1 = baseSH + 32768;
    unsigned baseW2 = baseW1 + 65536;
    int bm = blockIdx.x * 128;
    int tid = threadIdx.x;
    int warp = tid >> 5, lane = tid & 31;
    int wm = warp & 3, wn = warp >> 2;
    int g = lane >> 2, tig = lane & 3;
    int m = lane >> 3, mi = lane & 7;
    int rA0 = wm * 32 + ((m & 1) << 3) + mi;
    int rB0 = wn * 64 + ((m >> 1) << 3) + mi;
    int swA = (rA0 >> 1) & 3;
    int swB = (rB0 >> 1) & 3;
    int kselA = m >> 1, kselB = m & 1;

    load_tile128(baseSX, XH + (size_t)bm * 128, 128, tid);
    load_tile128(baseW1, W1, 128, tid);
    load_tile128(baseW2, W2, FFD, tid);
    asm volatile("cp.async.commit_group;");

    float acc2[2][8][4] = {};

    for (int ch = 0; ch < 16; ch++) {
        int buf = ch & 1;
        asm volatile("cp.async.wait_group 0;");
        __syncthreads();
        if (ch + 1 < 16) {
            load_tile128(baseW1 + (buf ^ 1) * 32768u, W1 + (size_t)(ch + 1) * 128 * 128, 128, tid);
            load_tile128(baseW2 + (buf ^ 1) * 32768u, W2 + (ch + 1) * 128, FFD, tid);
        }
        asm volatile("cp.async.commit_group;");

        float acc1[2][8][4] = {};
        gemm128(acc1, baseSX, baseW1 + buf * 32768u, rA0, rB0, swA, swB, kselA, kselB);

        #pragma unroll
        for (int mt = 0; mt < 2; mt++) {
            int r0 = wm * 32 + mt * 16 + g;
            int r1 = r0 + 8;
            int sw0 = (r0 >> 1) & 3, sw1 = (r1 >> 1) & 3;
            #pragma unroll
            for (int nt = 0; nt < 8; nt++) {
                int c0 = wn * 64 + nt * 8 + 2 * tig;
                float bv0 = bias1[ch * 128 + c0], bv1 = bias1[ch * 128 + c0 + 1];
                unsigned h0 = h2pack(fmaxf(acc1[mt][nt][0] + bv0, 0.f), fmaxf(acc1[mt][nt][1] + bv1, 0.f));
                unsigned h1 = h2pack(fmaxf(acc1[mt][nt][2] + bv0, 0.f), fmaxf(acc1[mt][nt][3] + bv1, 0.f));
                int kc = c0 >> 5;
                int chunkLog = (c0 >> 3) & 3;
                unsigned off = (unsigned)(kc * 8192 + ((chunkLog ^ sw0)) * 16 + 2 * (2 * tig));
                asm volatile("st.shared.b32 [%0], %1;" :: "r"(baseSH + r0 * 64 + off), "r"(h0));
                unsigned off1 = (unsigned)(kc * 8192 + ((chunkLog ^ sw1)) * 16 + 2 * (2 * tig));
                asm volatile("st.shared.b32 [%0], %1;" :: "r"(baseSH + r1 * 64 + off1), "r"(h1));
            }
        }
        __syncthreads();
        gemm128(acc2, baseSH, baseW2 + buf * 32768u, rA0, rB0, swA, swB, kselA, kselB);
    }

    float sums[2][2], sqs[2][2];
    #pragma unroll
    for (int mt = 0; mt < 2; mt++) { sums[mt][0] = sums[mt][1] = sqs[mt][0] = sqs[mt][1] = 0.f; }
    #pragma unroll
    for (int mt = 0; mt < 2; mt++) {
        int r0 = bm + wm * 32 + mt * 16 + g;
        #pragma unroll
        for (int nt = 0; nt < 8; nt++) {
            int c0 = wn * 64 + nt * 8 + 2 * tig;
            float bv0 = bias2[c0], bv1 = bias2[c0 + 1];
            float v00 = acc2[mt][nt][0] + bv0 + X[(size_t)r0 * 128 + c0];
            float v01 = acc2[mt][nt][1] + bv1 + X[(size_t)r0 * 128 + c0 + 1];
            float v10 = acc2[mt][nt][2] + bv0 + X[(size_t)(r0 + 8) * 128 + c0];
            float v11 = acc2[mt][nt][3] + bv1 + X[(size_t)(r0 + 8) * 128 + c0 + 1];
            acc2[mt][nt][0] = v00; acc2[mt][nt][1] = v01;
            acc2[mt][nt][2] = v10; acc2[mt][nt][3] = v11;
            sums[mt][0] += v00 + v01; sqs[mt][0] += v00 * v00 + v01 * v01;
            sums[mt][1] += v10 + v11; sqs[mt][1] += v10 * v10 + v11 * v11;
        }
    }
    #pragma unroll
    for (int mt = 0; mt < 2; mt++)
        #pragma unroll
        for (int rp = 0; rp < 2; rp++) {
            float s = sums[mt][rp], q = sqs[mt][rp];
            s += __shfl_xor_sync(0xffffffffu, s, 1); q += __shfl_xor_sync(0xffffffffu, q, 1);
            s += __shfl_xor_sync(0xffffffffu, s, 2); q += __shfl_xor_sync(0xffffffffu, q, 2);
            sums[mt][rp] = s; sqs[mt][rp] = q;
        }
    __syncthreads();
    float* red = (float*)sm;
    if (tig == 0) {
        #pragma unroll
        for (int mt = 0; mt < 2; mt++)
            #pragma unroll
            for (int rp = 0; rp < 2; rp++) {
                int ix = ((warp * 16 + g) * 4 + mt * 2 + rp) * 2;
                red[ix] = sums[mt][rp]; red[ix + 1] = sqs[mt][rp];
            }
    }
    __syncthreads();
    float mean[2][2], inv[2][2];
    #pragma unroll
    for (int mt = 0; mt < 2; mt++)
        #pragma unroll
        for (int rp = 0; rp < 2; rp++) {
            int i0 = (((wm) * 16 + g) * 4 + mt * 2 + rp) * 2;
            int i1 = (((wm + 4) * 16 + g) * 4 + mt * 2 + rp) * 2;
            float s = red[i0] + red[i1];
            float q = red[i0 + 1] + red[i1 + 1];
            float mm = s * (1.f / 128.f);
            float var = q * (1.f / 128.f) - mm * mm;
            mean[mt][rp] = mm;
            inv[mt][rp] = rsqrtf(var + 1e-5f);
        }
    #pragma unroll
    for (int mt = 0; mt < 2; mt++) {
        int r0 = bm + wm * 32 + mt * 16 + g;
        #pragma unroll
        for (int nt = 0; nt < 8; nt++) {
            int c0 = wn * 64 + nt * 8 + 2 * tig;
            float g0 = gamma[c0], g1 = gamma[c0 + 1];
            float be0 = beta[c0], be1 = beta[c0 + 1];
            float v00 = (acc2[mt][nt][0] - mean[mt][0]) * inv[mt][0] * g0 + be0;
            float v01 = (acc2[mt][nt][1] - mean[mt][0]) * inv[mt][0] * g1 + be1;
            float v10 = (acc2[mt][nt][2] - mean[mt][1]) * inv[mt][1] * g0 + be0;
            float v11 = (acc2[mt][nt][3] - mean[mt][1]) * inv[mt][1] * g1 + be1;
            *(float2*)(X + (size_t)r0 * 128 + c0)       = make_float2(v00, v01);
            *(float2*)(X + (size_t)(r0 + 8) * 128 + c0) = make_float2(v10, v11);
            *(__half2*)(XH + (size_t)r0 * 128 + c0)       = __floats2half2_rn(v00, v01);
            *(__half2*)(XH + (size_t)(r0 + 8) * 128 + c0) = __floats2half2_rn(v10, v11);
        }
    }
}

// ---------------- split-K reduce + reparameterization + KLD -----------------
__global__ void k_zred(const float* __restrict__ eps, const int* __restrict__ iftrain) {
    int idx = blockIdx.x * 256 + threadIdx.x;
    int i = idx >> 7, j = idx & 127;
    float mu = 0.f, ls = 0.f;
    #pragma unroll
    for (int z = 0; z < 8; z++) {
        mu += g_PART[((size_t)z * NNODE + i) * 256 + j];
        ls += g_PART[((size_t)z * NNODE + i) * 256 + 128 + j];
    }
    ls = fminf(ls, 10.f);
    float zz = (*iftrain > 0) ? (mu + eps[idx] * expf(ls)) : mu;
    g_ZH[idx] = __float2half(zz);
    float term = 1.f + 2.f * ls - mu * mu - expf(2.f * ls);
    float bs = block_sum<8>(term);
    if (threadIdx.x == 0) atomicAdd(&g_kld, (double)bs);
}

// ---------------- build transformer input x ----------------
__global__ void k_xbuild(const float* __restrict__ w3, const float* __restrict__ b3) {
    int idx = blockIdx.x * 256 + threadIdx.x;
    int j = idx & 127;
    int tok = idx >> 7;
    int a = tok >> 7, h = tok & 127;
    float acc = b3[j];
    #pragma unroll
    for (int t = 0; t < OBS; t++)
        acc += g_OUTB[(size_t)((t << 8) + a) * H + h] * w3[j * OBS + t];
    g_X[idx] = acc;
    g_XH[idx] = __float2half(acc);
}

// ---------------- tensor-core flash attention -------------------------------
__global__ __launch_bounds__(256) void k_attn_tc() {
    __shared__ __half Qs[256][16];
    __shared__ __half Ks[256][16];
    __shared__ __half Vt[16][264];
    int bh = blockIdx.x;
    int b = bh >> 3, h = bh & 7;
    int tid = threadIdx.x, warp = tid >> 5, lane = tid & 31;
    int g = lane >> 2, tig = lane & 3;
    const __half* Qb = g_QKVH + ((size_t)((0 * 8 + h) * 128 + b)) * 4096;
    const __half* Kb = g_QKVH + ((size_t)((1 * 8 + h) * 128 + b)) * 4096;
    const __half* Vb = g_QKVH + ((size_t)((2 * 8 + h) * 128 + b)) * 4096;
    for (int i = tid; i < 512; i += 256) {
        ((uint4*)Qs)[i] = ((const uint4*)Qb)[i];
        ((uint4*)Ks)[i] = ((const uint4*)Kb)[i];
    }
    {
        const __half2* vp = (const __half2*)(Vb + (size_t)tid * 16);
        #pragma unroll
        for (int j = 0; j < 8; j++) {
            __half2 v = vp[j];
            Vt[2 * j][tid] = __low2half(v);
            Vt[2 * j + 1][tid] = __high2half(v);
        }
    }
    __syncthreads();

    unsigned qf[2][4];
    #pragma unroll
    for (int mt = 0; mt < 2; mt++) {
        int r = warp * 32 + mt * 16 + g;
        qf[mt][0] = *(const unsigned*)&Qs[r][2 * tig];
        qf[mt][1] = *(const unsigned*)&Qs[r + 8][2 * tig];
        qf[mt][2] = *(const unsigned*)&Qs[r][2 * tig + 8];
        qf[mt][3] = *(const unsigned*)&Qs[r + 8][2 * tig + 8];
    }
    float mr[2][2], lr[2][2], oa[2][2][4];
    #pragma unroll
    for (int mt = 0; mt < 2; mt++)
        #pragma unroll
        for (int rp = 0; rp < 2; rp++) { mr[mt][rp] = -1e30f; lr[mt][rp] = 0.f; }
    #pragma unroll
    for (int mt = 0; mt < 2; mt++)
        #pragma unroll
        for (int nv = 0; nv < 2; nv++)
            #pragma unroll
            for (int c = 0; c < 4; c++) oa[mt][nv][c] = 0.f;

    #pragma unroll
    for (int kt = 0; kt < 4; kt++) {
        float s[2][8][4] = {};
        #pragma unroll
        for (int nt = 0; nt < 8; nt++) {
            int sr = kt * 64 + nt * 8 + g;
            unsigned b0 = *(const unsigned*)&Ks[sr][2 * tig];
            unsigned b1 = *(const unsigned*)&Ks[sr][2 * tig + 8];
            mma_f16(s[0][nt], qf[0], b0, b1);
            mma_f16(s[1][nt], qf[1], b0, b1);
        }
        #pragma unroll
        for (int mt = 0; mt < 2; mt++) {
            float mx[2] = {-1e30f, -1e30f};
            #pragma unroll
            for (int nt = 0; nt < 8; nt++) {
                mx[0] = fmaxf(mx[0], fmaxf(s[mt][nt][0], s[mt][nt][1]));
                mx[1] = fmaxf(mx[1], fmaxf(s[mt][nt][2], s[mt][nt][3]));
            }
            float mnew[2], corr[2], sum[2] = {0.f, 0.f};
            #pragma unroll
            for (int rp = 0; rp < 2; rp++) {
                mx[rp] = fmaxf(mx[rp], __shfl_xor_sync(0xffffffffu, mx[rp], 1));
                mx[rp] = fmaxf(mx[rp], __shfl_xor_sync(0xffffffffu, mx[rp], 2));
                mnew[rp] = fmaxf(mr[mt][rp], mx[rp]);
                corr[rp] = __expf((mr[mt][rp] - mnew[rp]) * 0.25f);
                mr[mt][rp] = mnew[rp];
            }
            #pragma unroll
            for (int nt = 0; nt < 8; nt++) {
                s[mt][nt][0] = __expf((s[mt][nt][0] - mnew[0]) * 0.25f);
                s[mt][nt][1] = __expf((s[mt][nt][1] - mnew[0]) * 0.25f);
                s[mt][nt][2] = __expf((s[mt][nt][2] - mnew[1]) * 0.25f);
                s[mt][nt][3] = __expf((s[mt][nt][3] - mnew[1]) * 0.25f);
                sum[0] += s[mt][nt][0] + s[mt][nt][1];
                sum[1] += s[mt][nt][2] + s[mt][nt][3];
            }
            #pragma unroll
            for (int rp = 0; rp < 2; rp++) {
                sum[rp] += __shfl_xor_sync(0xffffffffu, sum[rp], 1);
                sum[rp] += __shfl_xor_sync(0xffffffffu, sum[rp], 2);
                lr[mt][rp] = lr[mt][rp] * corr[rp] + sum[rp];
            }
            #pragma unroll
            for (int nv = 0; nv < 2; nv++) {
                oa[mt][nv][0] *= corr[0]; oa[mt][nv][1] *= corr[0];
                oa[mt][nv][2] *= corr[1]; oa[mt][nv][3] *= corr[1];
            }
        }
        #pragma unroll
        for (int ks = 0; ks < 4; ks++) {
            unsigned pa[2][4];
            #pragma unroll
            for (int mt = 0; mt < 2; mt++) {
                pa[mt][0] = h2pack(s[mt][2 * ks][0], s[mt][2 * ks][1]);
                pa[mt][1] = h2pack(s[mt][2 * ks][2], s[mt][2 * ks][3]);
                pa[mt][2] = h2pack(s[mt][2 * ks + 1][0], s[mt][2 * ks + 1][1]);
                pa[mt][3] = h2pack(s[mt][2 * ks + 1][2], s[mt][2 * ks + 1][3]);
            }
            int kr = kt * 64 + ks * 16;
            #pragma unroll
            for (int nv = 0; nv < 2; nv++) {
                unsigned b0 = *(const unsigned*)&Vt[nv * 8 + g][kr + 2 * tig];
                unsigned b1 = *(const unsigned*)&Vt[nv * 8 + g][kr + 2 * tig + 8];
                mma_f16(oa[0][nv], pa[0], b0, b1);
                mma_f16(oa[1][nv], pa[1], b0, b1);
            }
        }
    }
    #pragma unroll
    for (int mt = 0; mt < 2; mt++) {
        int r0 = warp * 32 + mt * 16 + g;
        float il0 = 1.f / lr[mt][0], il1 = 1.f / lr[mt][1];
        #pragma unroll
        for (int nv = 0; nv < 2; nv++) {
            int d = nv * 8 + 2 * tig;
            *(__half2*)(g_OH + ((size_t)r0 * BB + b) * H + h * 16 + d) =
                __floats2half2_rn(oa[mt][nv][0] * il0, oa[mt][nv][1] * il0);
            *(__half2*)(g_OH + ((size_t)(r0 + 8) * BB + b) * H + h * 16 + d) =
                __floats2half2_rn(oa[mt][nv][2] * il1, oa[mt][nv][3] * il1);
        }
    }
}

// ---------------- final projection + traj output + traj loss ----------------
__global__ void k_traj(const float* __restrict__ w4, const float* __restrict__ b4,
                       const float* __restrict__ w5, const float* __restrict__ b5,
                       const float* __restrict__ traj_in, float* __restrict__ out) {
    int tt = blockIdx.x >> 8;
    int a  = blockIdx.x & 255;
    int b  = threadIdx.x;
    int o = tt + (OBS - PRED);
    const float* xr = g_X + ((size_t)a * 128 + b) * 128;
    float acc = b4[o];
    #pragma unroll 8
    for (int j = 0; j < 128; j++) acc += xr[j] * w4[o * 128 + j];
    float s0 = block_sum<4>(acc * w5[b]);
    float s1 = block_sum<4>(acc * w5[128 + b]);
    if (b == 0) {
        float t0 = s0 + b5[0], t1 = s1 + b5[1];
        float y0 = traj_in[(OBS + tt) * (NAG * 2) + a * 2 + 0];
        float y1 = traj_in[(OBS + tt) * (NAG * 2) + a * 2 + 1];
        out[(tt * 256 + a) * 2 + 0] = t0;
        out[(tt * 256 + a) * 2 + 1] = t1;
        float d0 = t0 - y0, d1 = t1 - y1;
        atomicAdd(&g_traj, (double)sqrtf(d0 * d0 + d1 * d1));
    }
}

__global__ void k_final(float* __restrict__ out) {
    double kld = -0.5 * (g_kld / 2048.0);
    double st = g_struct / (2048.0 * 2048.0);
    double tl = g_traj / 256.0;
    out[PRED * NAG * FOUT] = (float)(tl + kld + st);
}

// ---------------- launch ----------------
extern "C" void kernel_launch(void* const* d_in, const int* in_sizes, int n_in,
                              void* d_out, int out_size) {
    const float* traj_in = (const float*)d_in[0];
    const float* adj_in  = (const float*)d_in[1];
    const float* eps     = (const float*)d_in[2];
    const float* pro1_w  = (const float*)d_in[3];
    const float* pro1_b  = (const float*)d_in[4];
    const float* pro2_w  = (const float*)d_in[5];
    const float* pro2_b  = (const float*)d_in[6];
    const float* mu_w    = (const float*)d_in[7];
    const float* mu_b    = (const float*)d_in[8];
    const float* ls_w    = (const float*)d_in[9];
    const float* ls_b    = (const float*)d_in[10];
    const float* gdl_w   = (const float*)d_in[11];
    const float* gdl_b   = (const float*)d_in[12];
    const float* pro3_w  = (const float*)d_in[13];
    const float* pro3_b  = (const float*)d_in[14];
    const float* pro4_w  = (const float*)d_in[15];
    const float* pro4_b  = (const float*)d_in[16];
    const float* pro5_w  = (const float*)d_in[17];
    const float* pro5_b  = (const float*)d_in[18];
    const float* qkv_w   = (const float*)d_in[19];
    const float* qkv_b   = (const float*)d_in[20];
    const float* out_w   = (const float*)d_in[21];
    const float* out_b   = (const float*)d_in[22];
    const float* ff1_w   = (const float*)d_in[23];
    const float* ff1_b   = (const float*)d_in[24];
    const float* ff2_w   = (const float*)d_in[25];
    const float* ff2_b   = (const float*)d_in[26];
    const float* ln1_g   = (const float*)d_in[27];
    const float* ln1_b   = (const float*)d_in[28];
    const float* ln2_g   = (const float*)d_in[29];
    const float* ln2_b   = (const float*)d_in[30];
    const int*   iftrain = (const int*)d_in[31];
    float* out = (float*)d_out;

    float *pOUTB, *pBMLS, *pX, *pPART;
    __half *pMLSH, *pAGGH, *pENCH, *pZH, *pXH, *pOH, *pQKVH;
    __half *pWQKVH, *pWOUTH, *pWFF1H, *pWFF2H, *pWGDLH, *pWMLSH;
    cudaGetSymbolAddress((void**)&pOUTB,  g_OUTB);
    cudaGetSymbolAddress((void**)&pBMLS,  g_BMLS);
    cudaGetSymbolAddress((void**)&pX,     g_X);
    cudaGetSymbolAddress((void**)&pPART,  g_PART);
    cudaGetSymbolAddress((void**)&pMLSH,  g_MLSH);
    cudaGetSymbolAddress((void**)&pAGGH,  g_AGGH);
    cudaGetSymbolAddress((void**)&pENCH,  g_ENCH);
    cudaGetSymbolAddress((void**)&pZH,    g_ZH);
    cudaGetSymbolAddress((void**)&pXH,    g_XH);
    cudaGetSymbolAddress((void**)&pOH,    g_OH);
    cudaGetSymbolAddress((void**)&pQKVH,  g_QKVH);
    cudaGetSymbolAddress((void**)&pWQKVH, g_WQKVH);
    cudaGetSymbolAddress((void**)&pWOUTH, g_WOUTH);
    cudaGetSymbolAddress((void**)&pWFF1H, g_WFF1H);
    cudaGetSymbolAddress((void**)&pWFF2H, g_WFF2H);
    cudaGetSymbolAddress((void**)&pWGDLH, g_WGDLH);
    cudaGetSymbolAddress((void**)&pWMLSH, g_WMLSH);

    static int smem_set = 0;
    if (!smem_set) {
        cudaFuncSetAttribute(k_ffn, cudaFuncAttributeMaxDynamicSharedMemorySize, 196608);
        smem_set = 1;
    }

    // ---- fused weight conversion + packing ----
    k_cvt<<<3505, 256>>>(qkv_w, out_w, ff1_w, ff2_w, gdl_w, mu_w, ls_w, mu_b, ls_b);

    // ---- graph-VAE front end ----
    k_init<<<8, 256>>>();
    k_minmax<<<512, 256>>>(adj_in);
    k_build<<<dim3(2, NNODE), 256>>>(adj_in);
    k_colsum<<<dim3(16, 64), 128>>>();
    k_dis<<<8, 256>>>();
    k_agg<<<dim3(64, 64), dim3(32, 32)>>>();
    k_enc<<<NNODE, 128>>>(traj_in, pro1_w, pro1_b, pro2_w, pro2_b);

    k_hgemm<5><<<dim3(2, 16), 256>>>(pENCH, pWMLSH, pBMLS, nullptr, pMLSH,
                                     NNODE, 256, H, nullptr, nullptr);
    k_hgemm<7><<<dim3(2, 16, 8), 256>>>(pAGGH, pMLSH, nullptr, pPART, nullptr,
                                        NNODE, 256, NNODE, nullptr, nullptr);
    k_zred<<<1024, 256>>>(eps, iftrain);
    k_hgemm<6><<<dim3(16, 16), 256>>>(pZH, pZH, nullptr, nullptr, nullptr,
                                      NNODE, NNODE, H, nullptr, nullptr);
    k_hgemm<0><<<dim3(1, 16), 256>>>(pZH, pWGDLH, gdl_b, pOUTB, nullptr,
                                     NNODE, H, H, nullptr, nullptr);
    k_xbuild<<<16384, 256>>>(pro3_w, pro3_b);

    // ---- transformer ----
    for (int l = 0; l < NL; l++) {
        k_hgemm<1><<<dim3(3, 256), 256>>>(pXH, pWQKVH + (size_t)l * 3 * H * H, qkv_b + (size_t)l * 3 * H,
                                          nullptr, pQKVH, NTOK, 3 * H, H, nullptr, nullptr);
        k_attn_tc<<<BB * NH, 256>>>();
        k_hgemm<2><<<dim3(1, 256), 256>>>(pOH, pWOUTH + (size_t)l * H * H, out_b + (size_t)l * H,
                                          pX, pXH, NTOK, H, H, ln1_g + l * H, ln1_b + l * H);
        k_ffn<<<256, 256, 196608>>>(ff1_b + (size_t)l * FFD, ff2_b + (size_t)l * H,
                                    pWFF1H + (size_t)l * FFD * H, pWFF2H + (size_t)l * H * FFD,
                                    pX, pXH, ln2_g + l * H, ln2_b + l * H);
    }

    // ---- output + loss ----
    k_traj<<<PRED * NAG, 128>>>(pro4_w, pro4_b, pro5_w, pro5_b, traj_in, out);
    k_final<<<1, 1>>>(out);
}

// round 13
// speedup vs baseline: 1.1536x; 1.0125x over previous
#include <cuda_runtime.h>
#include <cuda_fp16.h>
#include <math.h>

#define OBS 8
#define PRED 4
#define NAG 256
#define FIN 2
#define FOUT 2
#define H 128
#define NH 8
#define DH 16
#define FFD 2048
#define NL 6
#define NNODE (OBS*NAG)        /* 2048 */
#define SEQ NAG                /* 256  */
#define BB H                   /* 128  */
#define NTOK (SEQ*BB)          /* 32768 */

// ---------------- scratch (device globals; no allocation) ----------------
static __device__ float  g_ADJ[NNODE*NNODE];
static __device__ __half g_AGGH[NNODE*NNODE];
static __device__ __half g_ENCH[NNODE*H];
static __device__ __half g_MLSH[2*H*NNODE];
static __device__ float  g_PART[8*NNODE*2*H];
static __device__ __half g_ZH[NNODE*H];
static __device__ float  g_OUTB[NNODE*H];
static __device__ float  g_X[NTOK*H];
static __device__ __half g_XH[NTOK*H];
static __device__ __half g_OH[NTOK*H];
static __device__ __half g_QKVH[NTOK*3*H];
static __device__ __half g_WQKVH[NL*3*H*H];
static __device__ __half g_WOUTH[NL*H*H];
static __device__ __half g_WFF1H[(size_t)NL*FFD*H];
static __device__ __half g_WFF2H[(size_t)NL*H*FFD];
static __device__ __half g_WGDLH[H*H];
static __device__ __half g_WMLSH[2*H*H];
static __device__ float  g_BMLS[2*H];
static __device__ float  g_COL[NNODE];
static __device__ float  g_SELF[NNODE];
static __device__ float  g_DIS[NNODE];
static __device__ float  g_mn_acc, g_mx_acc;
static __device__ double g_kld, g_struct, g_traj;

// ---------------- helpers ----------------
__device__ __forceinline__ void atomicMinF(float* a, float v) {
    int* ai = (int*)a; int old = *ai;
    while (__int_as_float(old) > v) {
        int assumed = old;
        old = atomicCAS(ai, assumed, __float_as_int(v));
        if (old == assumed) break;
    }
}
__device__ __forceinline__ void atomicMaxF(float* a, float v) {
    int* ai = (int*)a; int old = *ai;
    while (__int_as_float(old) < v) {
        int assumed = old;
        old = atomicCAS(ai, assumed, __float_as_int(v));
        if (old == assumed) break;
    }
}

template<int NWARPS>
__device__ __forceinline__ float block_sum(float v) {
    __shared__ float w[NWARPS];
    int tid = threadIdx.x + threadIdx.y * blockDim.x;
    int lane = tid & 31, wid = tid >> 5;
    #pragma unroll
    for (int o = 16; o > 0; o >>= 1) v += __shfl_down_sync(0xffffffffu, v, o);
    if (lane == 0) w[wid] = v;
    __syncthreads();
    float r = 0.f;
    #pragma unroll
    for (int i = 0; i < NWARPS; i++) r += w[i];
    __syncthreads();
    return r;
}

__device__ __forceinline__ void mma_f16(float* c, const unsigned* a, unsigned b0, unsigned b1) {
    asm volatile(
        "mma.sync.aligned.m16n8k16.row.col.f32.f16.f16.f32 "
        "{%0,%1,%2,%3}, {%4,%5,%6,%7}, {%8,%9}, {%0,%1,%2,%3};"
        : "+f"(c[0]), "+f"(c[1]), "+f"(c[2]), "+f"(c[3])
        : "r"(a[0]), "r"(a[1]), "r"(a[2]), "r"(a[3]), "r"(b0), "r"(b1));
}

__device__ __forceinline__ unsigned h2pack(float x, float y) {
    __half2 h = __floats2half2_rn(x, y);
    return *(unsigned*)&h;
}

__device__ __forceinline__ unsigned smem_u32(const void* p) {
    return (unsigned)__cvta_generic_to_shared(p);
}
__device__ __forceinline__ void cpa16(unsigned dst, const void* src) {
    asm volatile("cp.async.cg.shared.global [%0], [%1], 16;" :: "r"(dst), "l"(src));
}
__device__ __forceinline__ void lmx4(unsigned& r0, unsigned& r1, unsigned& r2, unsigned& r3, unsigned addr) {
    asm volatile("ldmatrix.sync.aligned.m8n8.x4.shared.b16 {%0,%1,%2,%3}, [%4];"
                 : "=r"(r0), "=r"(r1), "=r"(r2), "=r"(r3) : "r"(addr));
}

// Load a 128x128 half tile into 4 swizzled 8KB sub-buffers.
__device__ __forceinline__ void load_tile128(unsigned dstBase, const __half* src, int srcStride, int tid) {
    int crow = tid >> 1, cpi = (tid & 1) * 2;
    int cswz = (crow >> 1) & 3;
    #pragma unroll
    for (int kc = 0; kc < 4; kc++) {
        const __half* s = src + (size_t)crow * srcStride + kc * 32 + cpi * 8;
        unsigned d = dstBase + kc * 8192 + crow * 64;
        cpa16(d + ((cpi ^ cswz)) * 16, s);
        cpa16(d + (((cpi + 1) ^ cswz)) * 16, s + 8);
    }
}

__device__ __forceinline__ void gemm128(float (&acc)[2][8][4], unsigned abase, unsigned bbase,
                                        int rA0, int rB0, int swA, int swB, int kselA, int kselB) {
    #pragma unroll
    for (int kc = 0; kc < 4; kc++) {
        #pragma unroll
        for (int ks = 0; ks < 2; ks++) {
            unsigned af[2][4];
            #pragma unroll
            for (int mt = 0; mt < 2; mt++) {
                unsigned addr = abase + kc * 8192 + (rA0 + mt * 16) * 64 + (((2 * ks + kselA) ^ swA)) * 16;
                lmx4(af[mt][0], af[mt][1], af[mt][2], af[mt][3], addr);
            }
            unsigned bf[8][2];
            #pragma unroll
            for (int jj = 0; jj < 4; jj++) {
                unsigned addr = bbase + kc * 8192 + (rB0 + jj * 16) * 64 + (((2 * ks + kselB) ^ swB)) * 16;
                lmx4(bf[2 * jj][0], bf[2 * jj][1], bf[2 * jj + 1][0], bf[2 * jj + 1][1], addr);
            }
            #pragma unroll
            for (int nt = 0; nt < 8; nt++) {
                mma_f16(acc[0][nt], af[0], bf[nt][0], bf[nt][1]);
                mma_f16(acc[1][nt], af[1], bf[nt][0], bf[nt][1]);
            }
        }
    }
}

// ---------------- init ----------------
__global__ void k_init() {
    int i = blockIdx.x * 256 + threadIdx.x;
    if (i < NNODE) g_COL[i] = 0.f;
    if (i == 0) {
        g_mn_acc = __int_as_float(0x7f800000);
        g_mx_acc = __int_as_float(0xff800000);
        g_kld = 0.0; g_struct = 0.0; g_traj = 0.0;
    }
}

// ---------------- fused weight conversion ----------------
__global__ void k_cvt(const float* __restrict__ qkv, const float* __restrict__ outw,
                      const float* __restrict__ ff1, const float* __restrict__ ff2,
                      const float* __restrict__ gdl, const float* __restrict__ muw,
                      const float* __restrict__ lsw, const float* __restrict__ mub,
                      const float* __restrict__ lsb) {
    int k = blockIdx.x * 256 + threadIdx.x;
    const float* src; __half* dst; int off;
    if (k < 73728)       { src = qkv;  dst = g_WQKVH;        off = k; }
    else if (k < 98304)  { src = outw; dst = g_WOUTH;        off = k - 73728; }
    else if (k < 491520) { src = ff1;  dst = g_WFF1H;        off = k - 98304; }
    else if (k < 884736) { src = ff2;  dst = g_WFF2H;        off = k - 491520; }
    else if (k < 888832) { src = gdl;  dst = g_WGDLH;        off = k - 884736; }
    else if (k < 892928) { src = muw;  dst = g_WMLSH;        off = k - 888832; }
    else if (k < 897024) { src = lsw;  dst = g_WMLSH + H*H;  off = k - 892928; }
    else if (k < 897088) {
        int o = k - 897024;
        float4 v = (o < 32) ? ((const float4*)mub)[o] : ((const float4*)lsb)[o - 32];
        ((float4*)g_BMLS)[o] = v;
        return;
    } else return;
    float4 v = ((const float4*)src)[off];
    __half2* d = (__half2*)dst + off * 2;
    d[0] = __floats2half2_rn(v.x, v.y);
    d[1] = __floats2half2_rn(v.z, v.w);
}

// ---------------- adjacency prep ----------------
__global__ void k_minmax(const float* __restrict__ adj) {
    const int n = OBS * NAG * NAG;
    float mn = __int_as_float(0x7f800000), mx = -mn;
    for (int i = blockIdx.x * blockDim.x + threadIdx.x; i < n; i += gridDim.x * blockDim.x) {
        float v = adj[i];
        mn = fminf(mn, v); mx = fmaxf(mx, v);
    }
    #pragma unroll
    for (int o = 16; o > 0; o >>= 1) {
        mn = fminf(mn, __shfl_down_sync(0xffffffffu, mn, o));
        mx = fmaxf(mx, __shfl_down_sync(0xffffffffu, mx, o));
    }
    __shared__ float smn[8], smx[8];
    int lane = threadIdx.x & 31, wid = threadIdx.x >> 5;
    if (lane == 0) { smn[wid] = mn; smx[wid] = mx; }
    __syncthreads();
    if (threadIdx.x == 0) {
        for (int w = 1; w < 8; w++) { mn = fminf(mn, smn[w]); mx = fmaxf(mx, smx[w]); }
        atomicMinF(&g_mn_acc, mn);
        atomicMaxF(&g_mx_acc, mx);
    }
}

__global__ void k_build(const float* __restrict__ adj) {
    float mn = fminf(g_mn_acc, 0.f);
    float mx = fmaxf(g_mx_acc, 0.f);
    float inv = 1.f / (mx - mn);
    int i = blockIdx.y;
    int j = (blockIdx.x * 256 + threadIdx.x) * 4;
    int ti = i >> 8, tj = j >> 8;
    float4 a = make_float4(0.f, 0.f, 0.f, 0.f);
    if (ti == tj)
        a = *(const float4*)(adj + (ti << 16) + ((i & 255) << 8) + (j & 255));
    float4 v = make_float4((a.x - mn) * inv, (a.y - mn) * inv, (a.z - mn) * inv, (a.w - mn) * inv);
    *(float4*)(g_ADJ + (size_t)i * NNODE + j) = v;
    if (i >= j && i < j + 4) {
        float d = (i == j) ? v.x : (i == j + 1) ? v.y : (i == j + 2) ? v.z : v.w;
        g_SELF[i] = (d == 0.f) ? 1.f : 0.f;
    }
}

__global__ void k_colsum() {
    int j = blockIdx.x * 128 + threadIdx.x;
    int i0 = blockIdx.y * 32;
    float s = 0.f;
    for (int r = 0; r < 32; r++) s += g_ADJ[(size_t)(i0 + r) * NNODE + j];
    atomicAdd(&g_COL[j], s);
}

__global__ void k_dis() {
    int j = blockIdx.x * 256 + threadIdx.x;
    if (j < NNODE) {
        float deg = g_COL[j] + g_SELF[j];
        g_DIS[j] = (deg > 0.f) ? (1.f / sqrtf(deg)) : 0.f;
    }
}

__global__ void k_agg() {
    __shared__ float s[32][33];
    int i0 = blockIdx.y * 32, j0 = blockIdx.x * 32;
    int tx = threadIdx.x, ty = threadIdx.y;
    s[ty][tx] = g_ADJ[(size_t)(j0 + ty) * NNODE + (i0 + tx)];
    __syncthreads();
    int i = i0 + ty, j = j0 + tx;
    float v = s[tx][ty];
    if (i == j) v += g_SELF[i];
    g_AGGH[(size_t)i * NNODE + j] = __float2half(g_DIS[j] * v * g_DIS[i]);
}

// ---------------- encoder ----------------
__global__ void k_enc(const float* __restrict__ traj,
                      const float* __restrict__ w1, const float* __restrict__ b1,
                      const float* __restrict__ w2, const float* __restrict__ b2) {
    int n = blockIdx.x, j = threadIdx.x;
    __shared__ float h1[128];
    float x0 = traj[n * 2], x1 = traj[n * 2 + 1];
    h1[j] = fmaxf(w1[j * 2] * x0 + w1[j * 2 + 1] * x1 + b1[j], 0.f);
    __syncthreads();
    float a = b2[j];
    #pragma unroll 8
    for (int k = 0; k < 128; k++) a += w2[j * 128 + k] * h1[k];
    g_ENCH[n * 128 + j] = __float2half(a);
}

// ---------------- fp16 TC GEMM, cp.async 3-stage + ldmatrix ------------------
template<int EPI>
__global__ __launch_bounds__(256, 2) void k_hgemm(
    const __half* __restrict__ A, const __half* __restrict__ B,
    const float* __restrict__ bias, float* __restrict__ C, __half* __restrict__ Ch,
    int M, int N, int K,
    const float* __restrict__ gamma, const float* __restrict__ beta)
{
    __shared__ __align__(16) __half SA[3][4096];
    __shared__ __align__(16) __half SB[3][4096];
    int bm = blockIdx.y * 128, bn = blockIdx.x * 128;
    int tid = threadIdx.x;
    int warp = tid >> 5, lane = tid & 31;
    int wm = warp & 3, wn = warp >> 2;
    int g = lane >> 2, tig = lane & 3;

    int ksz = K / gridDim.z;
    int k_begin = blockIdx.z * ksz;
    const int nch = ksz >> 5;

    unsigned baseSA = smem_u32(&SA[0][0]);
    unsigned baseSB = smem_u32(&SB[0][0]);

    int crow = tid >> 1, cp = (tid & 1) * 2;
    int cswz = (crow >> 1) & 3;
    unsigned dA0 = baseSA + crow * 64 + ((cp ^ cswz)) * 16;
    unsigned dA1 = baseSA + crow * 64 + (((cp + 1) ^ cswz)) * 16;
    unsigned dB0 = baseSB + crow * 64 + ((cp ^ cswz)) * 16;
    unsigned dB1 = baseSB + crow * 64 + (((cp + 1) ^ cswz)) * 16;
    const __half* srcA = A + (size_t)(bm + crow) * K + k_begin + cp * 8;
    const __half* srcB = B + (size_t)(bn + crow) * K + k_begin + cp * 8;

    int m = lane >> 3, mi = lane & 7;
    int rA0 = wm * 32 + ((m & 1) << 3) + mi;
    int rB0 = wn * 64 + ((m >> 1) << 3) + mi;
    int swA = (rA0 >> 1) & 3;
    int swB = (rB0 >> 1) & 3;
    int kselA = m >> 1, kselB = m & 1;

    float acc[2][8][4] = {};

    #pragma unroll
    for (int s = 0; s < 2; s++) {
        if (s < nch) {
            unsigned so = s * 8192u;
            cpa16(dA0 + so, srcA + s * 32);
            cpa16(dA1 + so, srcA + s * 32 + 8);
            cpa16(dB0 + so, srcB + s * 32);
            cpa16(dB1 + so, srcB + s * 32 + 8);
        }
        asm volatile("cp.async.commit_group;");
    }

    for (int c = 0; c < nch; c++) {
        asm volatile("cp.async.wait_group 1;");
        __syncthreads();
        int pf = c + 2;
        if (pf < nch) {
            unsigned so = (pf % 3) * 8192u;
            cpa16(dA0 + so, srcA + pf * 32);
            cpa16(dA1 + so, srcA + pf * 32 + 8);
            cpa16(dB0 + so, srcB + pf * 32);
            cpa16(dB1 + so, srcB + pf * 32 + 8);
        }
        asm volatile("cp.async.commit_group;");
        unsigned so = (c % 3) * 8192u;
        #pragma unroll
        for (int ks = 0; ks < 2; ks++) {
            unsigned af[2][4];
            #pragma unroll
            for (int mt = 0; mt < 2; mt++) {
                unsigned addr = baseSA + so + (rA0 + mt * 16) * 64 + (((2 * ks + kselA) ^ swA)) * 16;
                lmx4(af[mt][0], af[mt][1], af[mt][2], af[mt][3], addr);
            }
            unsigned bf[8][2];
            #pragma unroll
            for (int jj = 0; jj < 4; jj++) {
                unsigned addr = baseSB + so + (rB0 + jj * 16) * 64 + (((2 * ks + kselB) ^ swB)) * 16;
                lmx4(bf[2 * jj][0], bf[2 * jj][1], bf[2 * jj + 1][0], bf[2 * jj + 1][1], addr);
            }
            #pragma unroll
            for (int nt = 0; nt < 8; nt++) {
                mma_f16(acc[0][nt], af[0], bf[nt][0], bf[nt][1]);
                mma_f16(acc[1][nt], af[1], bf[nt][0], bf[nt][1]);
            }
        }
    }

    if (EPI == 0) {
        #pragma unroll
        for (int mt = 0; mt < 2; mt++) {
            int r0 = bm + wm * 32 + mt * 16 + g;
            #pragma unroll
            for (int nt = 0; nt < 8; nt++) {
                int c0 = bn + wn * 64 + nt * 8 + 2 * tig;
                float bv0 = bias[c0], bv1 = bias[c0 + 1];
                *(float2*)(C + (size_t)r0 * N + c0) =
                    make_float2(acc[mt][nt][0] + bv0, acc[mt][nt][1] + bv1);
                *(float2*)(C + (size_t)(r0 + 8) * N + c0) =
                    make_float2(acc[mt][nt][2] + bv0, acc[mt][nt][3] + bv1);
            }
        }
    } else if (EPI == 1) {
        int p = blockIdx.x;
        #pragma unroll
        for (int mt = 0; mt < 2; mt++) {
            int r0 = bm + wm * 32 + mt * 16 + g;
            int r1 = r0 + 8;
            #pragma unroll
            for (int nt = 0; nt < 8; nt++) {
                int rem = wn * 64 + nt * 8 + 2 * tig;
                int h = rem >> 4, d = rem & 15;
                int c0 = bn + rem;
                float bv0 = bias[c0], bv1 = bias[c0 + 1];
                size_t b0 = ((size_t)((p * 8 + h) * 128 + (r0 & 127)) * 256 + (r0 >> 7)) * 16 + d;
                size_t b1 = ((size_t)((p * 8 + h) * 128 + (r1 & 127)) * 256 + (r1 >> 7)) * 16 + d;
                *(__half2*)(Ch + b0) = __floats2half2_rn(acc[mt][nt][0] + bv0, acc[mt][nt][1] + bv1);
                *(__half2*)(Ch + b1) = __floats2half2_rn(acc[mt][nt][2] + bv0, acc[mt][nt][3] + bv1);
            }
        }
    } else if (EPI == 2) {
        float sums[2][2], sqs[2][2];
        #pragma unroll
        for (int mt = 0; mt < 2; mt++) { sums[mt][0] = sums[mt][1] = sqs[mt][0] = sqs[mt][1] = 0.f; }
        #pragma unroll
        for (int mt = 0; mt < 2; mt++) {
            int r0 = bm + wm * 32 + mt * 16 + g;
            #pragma unroll
            for (int nt = 0; nt < 8; nt++) {
                int c0 = wn * 64 + nt * 8 + 2 * tig;
                float bv0 = bias[c0], bv1 = bias[c0 + 1];
                float v00 = acc[mt][nt][0] + bv0 + C[(size_t)r0 * 128 + c0];
                float v01 = acc[mt][nt][1] + bv1 + C[(size_t)r0 * 128 + c0 + 1];
                float v10 = acc[mt][nt][2] + bv0 + C[(size_t)(r0 + 8) * 128 + c0];
                float v11 = acc[mt][nt][3] + bv1 + C[(size_t)(r0 + 8) * 128 + c0 + 1];
                acc[mt][nt][0] = v00; acc[mt][nt][1] = v01;
                acc[mt][nt][2] = v10; acc[mt][nt][3] = v11;
                sums[mt][0] += v00 + v01; sqs[mt][0] += v00 * v00 + v01 * v01;
                sums[mt][1] += v10 + v11; sqs[mt][1] += v10 * v10 + v11 * v11;
            }
        }
        #pragma unroll
        for (int mt = 0; mt < 2; mt++)
            #pragma unroll
            for (int rp = 0; rp < 2; rp++) {
                float s = sums[mt][rp], q = sqs[mt][rp];
                s += __shfl_xor_sync(0xffffffffu, s, 1); q += __shfl_xor_sync(0xffffffffu, q, 1);
                s += __shfl_xor_sync(0xffffffffu, s, 2); q += __shfl_xor_sync(0xffffffffu, q, 2);
                sums[mt][rp] = s; sqs[mt][rp] = q;
            }
        __syncthreads();
        float* red = (float*)SA;
        if (tig == 0) {
            #pragma unroll
            for (int mt = 0; mt < 2; mt++)
                #pragma unroll
                for (int rp = 0; rp < 2; rp++) {
                    int ix = ((warp * 16 + g) * 4 + mt * 2 + rp) * 2;
                    red[ix] = sums[mt][rp]; red[ix + 1] = sqs[mt][rp];
                }
        }
        __syncthreads();
        float mean[2][2], inv[2][2];
        #pragma unroll
        for (int mt = 0; mt < 2; mt++)
            #pragma unroll
            for (int rp = 0; rp < 2; rp++) {
                int i0 = (((wm) * 16 + g) * 4 + mt * 2 + rp) * 2;
                int i1 = (((wm + 4) * 16 + g) * 4 + mt * 2 + rp) * 2;
                float s = red[i0] + red[i1];
                float q = red[i0 + 1] + red[i1 + 1];
                float mm = s * (1.f / 128.f);
                float var = q * (1.f / 128.f) - mm * mm;
                mean[mt][rp] = mm;
                inv[mt][rp] = rsqrtf(var + 1e-5f);
            }
        #pragma unroll
        for (int mt = 0; mt < 2; mt++) {
            int r0 = bm + wm * 32 + mt * 16 + g;
            #pragma unroll
            for (int nt = 0; nt < 8; nt++) {
                int c0 = wn * 64 + nt * 8 + 2 * tig;
                float g0 = gamma[c0], g1 = gamma[c0 + 1];
                float be0 = beta[c0], be1 = beta[c0 + 1];
                float v00 = (acc[mt][nt][0] - mean[mt][0]) * inv[mt][0] * g0 + be0;
                float v01 = (acc[mt][nt][1] - mean[mt][0]) * inv[mt][0] * g1 + be1;
                float v10 = (acc[mt][nt][2] - mean[mt][1]) * inv[mt][1] * g0 + be0;
                float v11 = (acc[mt][nt][3] - mean[mt][1]) * inv[mt][1] * g1 + be1;
                *(float2*)(C + (size_t)r0 * 128 + c0)       = make_float2(v00, v01);
                *(float2*)(C + (size_t)(r0 + 8) * 128 + c0) = make_float2(v10, v11);
                *(__half2*)(Ch + (size_t)r0 * 128 + c0)       = __floats2half2_rn(v00, v01);
                *(__half2*)(Ch + (size_t)(r0 + 8) * 128 + c0) = __floats2half2_rn(v10, v11);
            }
        }
    } else if (EPI == 5) {
        #pragma unroll
        for (int mt = 0; mt < 2; mt++) {
            int r0 = bm + wm * 32 + mt * 16 + g;
            #pragma unroll
            for (int nt = 0; nt < 8; nt++) {
                int c0 = bn + wn * 64 + nt * 8 + 2 * tig;
                float bv0 = bias[c0], bv1 = bias[c0 + 1];
                Ch[(size_t)c0 * M + r0]           = __float2half(acc[mt][nt][0] + bv0);
                Ch[(size_t)(c0 + 1) * M + r0]     = __float2half(acc[mt][nt][1] + bv1);
                Ch[(size_t)c0 * M + r0 + 8]       = __float2half(acc[mt][nt][2] + bv0);
                Ch[(size_t)(c0 + 1) * M + r0 + 8] = __float2half(acc[mt][nt][3] + bv1);
            }
        }
    } else if (EPI == 6) {
        float contrib = 0.f;
        #pragma unroll
        for (int mt = 0; mt < 2; mt++) {
            int r0 = bm + wm * 32 + mt * 16 + g;
            #pragma unroll
            for (int nt = 0; nt < 8; nt++) {
                int c0 = bn + wn * 64 + nt * 8 + 2 * tig;
                float2 ad0 = *(const float2*)(g_ADJ + (size_t)r0 * NNODE + c0);
                float2 ad1 = *(const float2*)(g_ADJ + (size_t)(r0 + 8) * NNODE + c0);
                float a00 = acc[mt][nt][0], a01 = acc[mt][nt][1];
                float a10 = acc[mt][nt][2], a11 = acc[mt][nt][3];
                contrib += fmaxf(a00, 0.f) - a00 * ad0.x + log1pf(expf(-fabsf(a00)));
                contrib += fmaxf(a01, 0.f) - a01 * ad0.y + log1pf(expf(-fabsf(a01)));
                contrib += fmaxf(a10, 0.f) - a10 * ad1.x + log1pf(expf(-fabsf(a10)));
                contrib += fmaxf(a11, 0.f) - a11 * ad1.y + log1pf(expf(-fabsf(a11)));
            }
        }
        #pragma unroll
        for (int o = 16; o > 0; o >>= 1) contrib += __shfl_down_sync(0xffffffffu, contrib, o);
        __syncthreads();
        float* red = (float*)SA;
        if (lane == 0) red[warp] = contrib;
        __syncthreads();
        if (tid == 0) {
            float s = 0.f;
            for (int w = 0; w < 8; w++) s += red[w];
            atomicAdd(&g_struct, (double)s);
        }
    } else { // EPI == 7
        float* P = C + (size_t)blockIdx.z * M * N;
        #pragma unroll
        for (int mt = 0; mt < 2; mt++) {
            int r0 = bm + wm * 32 + mt * 16 + g;
            #pragma unroll
            for (int nt = 0; nt < 8; nt++) {
                int c0 = bn + wn * 64 + nt * 8 + 2 * tig;
                *(float2*)(P + (size_t)r0 * N + c0)       = make_float2(acc[mt][nt][0], acc[mt][nt][1]);
                *(float2*)(P + (size_t)(r0 + 8) * N + c0) = make_float2(acc[mt][nt][2], acc[mt][nt][3]);
            }
        }
    }
}

// ---------------- fused FF + next-layer QKV ---------------------------------
// 192KB smem; 16 chunks of 128 FF neurons; after LN epilogue, if Wqkv!=null,
// computes QKV = XH_tile @ Wqkv^T (3 x 128-col chunks, double-buffered) and
// scatters to g_QKVH (same indexing as k_hgemm EPI=1).
__global__ __launch_bounds__(256, 1) void k_ffn(
    const float* __restrict__ bias1, const float* __restrict__ bias2,
    const __half* __restrict__ W1, const __half* __restrict__ W2,
    float* __restrict__ X, __half* __restrict__ XH,
    const float* __restrict__ gamma, const float* __restrict__ beta,
    const __half* __restrict__ Wqkv, const float* __restrict__ bqkv,
    __half* __restrict__ QKV)
{
    extern __shared__ __align__(16) __half sm[];
    unsigned baseSX = smem_u32(sm);
    unsigned baseSH = baseSX + 32768;
    unsigned baseW1 = baseSH + 32768;
    unsigned baseW2 = baseW1 + 65536;
    int bm = blockIdx.x * 128;
    int tid = threadIdx.x;
    int warp = tid >> 5, lane = tid & 31;
    int wm = warp & 3, wn = warp >> 2;
    int g = lane >> 2, tig = lane & 3;
    int m = lane >> 3, mi = lane & 7;
    int rA0 = wm * 32 + ((m & 1) << 3) + mi;
    int rB0 = wn * 64 + ((m >> 1) << 3) + mi;
    int swA = (rA0 >> 1) & 3;
    int swB = (rB0 >> 1) & 3;
    int kselA = m >> 1, kselB = m & 1;

    load_tile128(baseSX, XH + (size_t)bm * 128, 128, tid);
    load_tile128(baseW1, W1, 128, tid);
    load_tile128(baseW2, W2, FFD, tid);
    asm volatile("cp.async.commit_group;");

    float acc2[2][8][4] = {};

    for (int ch = 0; ch < 16; ch++) {
        int buf = ch & 1;
        asm volatile("cp.async.wait_group 0;");
        __syncthreads();
        if (ch + 1 < 16) {
            load_tile128(baseW1 + (buf ^ 1) * 32768u, W1 + (size_t)(ch + 1) * 128 * 128, 128, tid);
            load_tile128(baseW2 + (buf ^ 1) * 32768u, W2 + (ch + 1) * 128, FFD, tid);
        }
        asm volatile("cp.async.commit_group;");

        float acc1[2][8][4] = {};
        gemm128(acc1, baseSX, baseW1 + buf * 32768u, rA0, rB0, swA, swB, kselA, kselB);

        #pragma unroll
        for (int mt = 0; mt < 2; mt++) {
            int r0 = wm * 32 + mt * 16 + g;
            int r1 = r0 + 8;
            int sw0 = (r0 >> 1) & 3, sw1 = (r1 >> 1) & 3;
            #pragma unroll
            for (int nt = 0; nt < 8; nt++) {
                int c0 = wn * 64 + nt * 8 + 2 * tig;
                float bv0 = bias1[ch * 128 + c0], bv1 = bias1[ch * 128 + c0 + 1];
                unsigned h0 = h2pack(fmaxf(acc1[mt][nt][0] + bv0, 0.f), fmaxf(acc1[mt][nt][1] + bv1, 0.f));
                unsigned h1 = h2pack(fmaxf(acc1[mt][nt][2] + bv0, 0.f), fmaxf(acc1[mt][nt][3] + bv1, 0.f));
                int kc = c0 >> 5;
                int chunkLog = (c0 >> 3) & 3;
                unsigned off = (unsigned)(kc * 8192 + ((chunkLog ^ sw0)) * 16 + 2 * (2 * tig));
                asm volatile("st.shared.b32 [%0], %1;" :: "r"(baseSH + r0 * 64 + off), "r"(h0));
                unsigned off1 = (unsigned)(kc * 8192 + ((chunkLog ^ sw1)) * 16 + 2 * (2 * tig));
                asm volatile("st.shared.b32 [%0], %1;" :: "r"(baseSH + r1 * 64 + off1), "r"(h1));
            }
        }
        __syncthreads();
        gemm128(acc2, baseSH, baseW2 + buf * 32768u, rA0, rB0, swA, swB, kselA, kselB);
    }

    // prefetch Wqkv chunk 0 (W buffers are free after the last gemm above)
    if (Wqkv) load_tile128(baseW1, Wqkv, 128, tid);
    asm volatile("cp.async.commit_group;");

    // epilogue: bias2 + residual + LayerNorm
    float sums[2][2], sqs[2][2];
    #pragma unroll
    for (int mt = 0; mt < 2; mt++) { sums[mt][0] = sums[mt][1] = sqs[mt][0] = sqs[mt][1] = 0.f; }
    #pragma unroll
    for (int mt = 0; mt < 2; mt++) {
        int r0 = bm + wm * 32 + mt * 16 + g;
        #pragma unroll
        for (int nt = 0; nt < 8; nt++) {
            int c0 = wn * 64 + nt * 8 + 2 * tig;
            float bv0 = bias2[c0], bv1 = bias2[c0 + 1];
            float v00 = acc2[mt][nt][0] + bv0 + X[(size_t)r0 * 128 + c0];
            float v01 = acc2[mt][nt][1] + bv1 + X[(size_t)r0 * 128 + c0 + 1];
            float v10 = acc2[mt][nt][2] + bv0 + X[(size_t)(r0 + 8) * 128 + c0];
            float v11 = acc2[mt][nt][3] + bv1 + X[(size_t)(r0 + 8) * 128 + c0 + 1];
            acc2[mt][nt][0] = v00; acc2[mt][nt][1] = v01;
            acc2[mt][nt][2] = v10; acc2[mt][nt][3] = v11;
            sums[mt][0] += v00 + v01; sqs[mt][0] += v00 * v00 + v01 * v01;
            sums[mt][1] += v10 + v11; sqs[mt][1] += v10 * v10 + v11 * v11;
        }
    }
    #pragma unroll
    for (int mt = 0; mt < 2; mt++)
        #pragma unroll
        for (int rp = 0; rp < 2; rp++) {
            float s = sums[mt][rp], q = sqs[mt][rp];
            s += __shfl_xor_sync(0xffffffffu, s, 1); q += __shfl_xor_sync(0xffffffffu, q, 1);
            s += __shfl_xor_sync(0xffffffffu, s, 2); q += __shfl_xor_sync(0xffffffffu, q, 2);
            sums[mt][rp] = s; sqs[mt][rp] = q;
        }
    __syncthreads();
    float* red = (float*)sm;
    if (tig == 0) {
        #pragma unroll
        for (int mt = 0; mt < 2; mt++)
            #pragma unroll
            for (int rp = 0; rp < 2; rp++) {
                int ix = ((warp * 16 + g) * 4 + mt * 2 + rp) * 2;
                red[ix] = sums[mt][rp]; red[ix + 1] = sqs[mt][rp];
            }
    }
    __syncthreads();
    float mean[2][2], inv[2][2];
    #pragma unroll
    for (int mt = 0; mt < 2; mt++)
        #pragma unroll
        for (int rp = 0; rp < 2; rp++) {
            int i0 = (((wm) * 16 + g) * 4 + mt * 2 + rp) * 2;
            int i1 = (((wm + 4) * 16 + g) * 4 + mt * 2 + rp) * 2;
            float s = red[i0] + red[i1];
            float q = red[i0 + 1] + red[i1 + 1];
            float mm = s * (1.f / 128.f);
            float var = q * (1.f / 128.f) - mm * mm;
            mean[mt][rp] = mm;
            inv[mt][rp] = rsqrtf(var + 1e-5f);
        }
    __syncthreads();   // all reads of red done before SH reuse below
    #pragma unroll
    for (int mt = 0; mt < 2; mt++) {
        int r0 = bm + wm * 32 + mt * 16 + g;
        int lr0 = wm * 32 + mt * 16 + g;
        int lr1 = lr0 + 8;
        int sw0 = (lr0 >> 1) & 3, sw1 = (lr1 >> 1) & 3;
        #pragma unroll
        for (int nt = 0; nt < 8; nt++) {
            int c0 = wn * 64 + nt * 8 + 2 * tig;
            float g0 = gamma[c0], g1 = gamma[c0 + 1];
            float be0 = beta[c0], be1 = beta[c0 + 1];
            float v00 = (acc2[mt][nt][0] - mean[mt][0]) * inv[mt][0] * g0 + be0;
            float v01 = (acc2[mt][nt][1] - mean[mt][0]) * inv[mt][0] * g1 + be1;
            float v10 = (acc2[mt][nt][2] - mean[mt][1]) * inv[mt][1] * g0 + be0;
            float v11 = (acc2[mt][nt][3] - mean[mt][1]) * inv[mt][1] * g1 + be1;
            *(float2*)(X + (size_t)r0 * 128 + c0)       = make_float2(v00, v01);
            *(float2*)(X + (size_t)(r0 + 8) * 128 + c0) = make_float2(v10, v11);
            __half2 hv0 = __floats2half2_rn(v00, v01);
            __half2 hv1 = __floats2half2_rn(v10, v11);
            *(__half2*)(XH + (size_t)r0 * 128 + c0)       = hv0;
            *(__half2*)(XH + (size_t)(r0 + 8) * 128 + c0) = hv1;
            if (Wqkv) {
                int kc = c0 >> 5;
                int chunkLog = (c0 >> 3) & 3;
                unsigned off = (unsigned)(kc * 8192 + ((chunkLog ^ sw0)) * 16 + 4 * tig);
                asm volatile("st.shared.b32 [%0], %1;" :: "r"(baseSH + lr0 * 64 + off), "r"(*(unsigned*)&hv0));
                unsigned off1 = (unsigned)(kc * 8192 + ((chunkLog ^ sw1)) * 16 + 4 * tig);
                asm volatile("st.shared.b32 [%0], %1;" :: "r"(baseSH + lr1 * 64 + off1), "r"(*(unsigned*)&hv1));
            }
        }
    }

    // ---- next-layer QKV from the XH tile in SH ----
    if (Wqkv) {
        for (int p = 0; p < 3; p++) {
            int buf = p & 1;
            asm volatile("cp.async.wait_group 0;");
            __syncthreads();
            if (p + 1 < 3)
                load_tile128(baseW1 + (buf ^ 1) * 32768u, Wqkv + (size_t)(p + 1) * 128 * 128, 128, tid);
            asm volatile("cp.async.commit_group;");

            float qacc[2][8][4] = {};
            gemm128(qacc, baseSH, baseW1 + buf * 32768u, rA0, rB0, swA, swB, kselA, kselB);

            #pragma unroll
            for (int mt = 0; mt < 2; mt++) {
                int r0 = bm + wm * 32 + mt * 16 + g;
                int r1 = r0 + 8;
                #pragma unroll
                for (int nt = 0; nt < 8; nt++) {
                    int rem = wn * 64 + nt * 8 + 2 * tig;
                    int h = rem >> 4, d = rem & 15;
                    int c0 = p * 128 + rem;
                    float bv0 = bqkv[c0], bv1 = bqkv[c0 + 1];
                    size_t b0 = ((size_t)((p * 8 + h) * 128 + (r0 & 127)) * 256 + (r0 >> 7)) * 16 + d;
                    size_t b1 = ((size_t)((p * 8 + h) * 128 + (r1 & 127)) * 256 + (r1 >> 7)) * 16 + d;
                    *(__half2*)(QKV + b0) = __floats2half2_rn(qacc[mt][nt][0] + bv0, qacc[mt][nt][1] + bv1);
                    *(__half2*)(QKV + b1) = __floats2half2_rn(qacc[mt][nt][2] + bv0, qacc[mt][nt][3] + bv1);
                }
            }
        }
    }
}

// ---------------- split-K reduce + reparameterization + KLD -----------------
__global__ void k_zred(const float* __restrict__ eps, const int* __restrict__ iftrain) {
    int idx = blockIdx.x * 256 + threadIdx.x;
    int i = idx >> 7, j = idx & 127;
    float mu = 0.f, ls = 0.f;
    #pragma unroll
    for (int z = 0; z < 8; z++) {
        mu += g_PART[((size_t)z * NNODE + i) * 256 + j];
        ls += g_PART[((size_t)z * NNODE + i) * 256 + 128 + j];
    }
    ls = fminf(ls, 10.f);
    float zz = (*iftrain > 0) ? (mu + eps[idx] * expf(ls)) : mu;
    g_ZH[idx] = __float2half(zz);
    float term = 1.f + 2.f * ls - mu * mu - expf(2.f * ls);
    float bs = block_sum<8>(term);
    if (threadIdx.x == 0) atomicAdd(&g_kld, (double)bs);
}

// ---------------- build transformer input x ----------------
__global__ void k_xbuild(const float* __restrict__ w3, const float* __restrict__ b3) {
    int idx = blockIdx.x * 256 + threadIdx.x;
    int j = idx & 127;
    int tok = idx >> 7;
    int a = tok >> 7, h = tok & 127;
    float acc = b3[j];
    #pragma unroll
    for (int t = 0; t < OBS; t++)
        acc += g_OUTB[(size_t)((t << 8) + a) * H + h] * w3[j * OBS + t];
    g_X[idx] = acc;
    g_XH[idx] = __float2half(acc);
}

// ---------------- tensor-core flash attention -------------------------------
__global__ __launch_bounds__(256) void k_attn_tc() {
    __shared__ __half Qs[256][16];
    __shared__ __half Ks[256][16];
    __shared__ __half Vt[16][264];
    int bh = blockIdx.x;
    int b = bh >> 3, h = bh & 7;
    int tid = threadIdx.x, warp = tid >> 5, lane = tid & 31;
    int g = lane >> 2, tig = lane & 3;
    const __half* Qb = g_QKVH + ((size_t)((0 * 8 + h) * 128 + b)) * 4096;
    const __half* Kb = g_QKVH + ((size_t)((1 * 8 + h) * 128 + b)) * 4096;
    const __half* Vb = g_QKVH + ((size_t)((2 * 8 + h) * 128 + b)) * 4096;
    for (int i = tid; i < 512; i += 256) {
        ((uint4*)Qs)[i] = ((const uint4*)Qb)[i];
        ((uint4*)Ks)[i] = ((const uint4*)Kb)[i];
    }
    {
        const __half2* vp = (const __half2*)(Vb + (size_t)tid * 16);
        #pragma unroll
        for (int j = 0; j < 8; j++) {
            __half2 v = vp[j];
            Vt[2 * j][tid] = __low2half(v);
            Vt[2 * j + 1][tid] = __high2half(v);
        }
    }
    __syncthreads();

    unsigned qf[2][4];
    #pragma unroll
    for (int mt = 0; mt < 2; mt++) {
        int r = warp * 32 + mt * 16 + g;
        qf[mt][0] = *(const unsigned*)&Qs[r][2 * tig];
        qf[mt][1] = *(const unsigned*)&Qs[r + 8][2 * tig];
        qf[mt][2] = *(const unsigned*)&Qs[r][2 * tig + 8];
        qf[mt][3] = *(const unsigned*)&Qs[r + 8][2 * tig + 8];
    }
    float mr[2][2], lr[2][2], oa[2][2][4];
    #pragma unroll
    for (int mt = 0; mt < 2; mt++)
        #pragma unroll
        for (int rp = 0; rp < 2; rp++) { mr[mt][rp] = -1e30f; lr[mt][rp] = 0.f; }
    #pragma unroll
    for (int mt = 0; mt < 2; mt++)
        #pragma unroll
        for (int nv = 0; nv < 2; nv++)
            #pragma unroll
            for (int c = 0; c < 4; c++) oa[mt][nv][c] = 0.f;

    #pragma unroll
    for (int kt = 0; kt < 4; kt++) {
        float s[2][8][4] = {};
        #pragma unroll
        for (int nt = 0; nt < 8; nt++) {
            int sr = kt * 64 + nt * 8 + g;
            unsigned b0 = *(const unsigned*)&Ks[sr][2 * tig];
            unsigned b1 = *(const unsigned*)&Ks[sr][2 * tig + 8];
            mma_f16(s[0][nt], qf[0], b0, b1);
            mma_f16(s[1][nt], qf[1], b0, b1);
        }
        #pragma unroll
        for (int mt = 0; mt < 2; mt++) {
            float mx[2] = {-1e30f, -1e30f};
            #pragma unroll
            for (int nt = 0; nt < 8; nt++) {
                mx[0] = fmaxf(mx[0], fmaxf(s[mt][nt][0], s[mt][nt][1]));
                mx[1] = fmaxf(mx[1], fmaxf(s[mt][nt][2], s[mt][nt][3]));
            }
            float mnew[2], corr[2], sum[2] = {0.f, 0.f};
            #pragma unroll
            for (int rp = 0; rp < 2; rp++) {
                mx[rp] = fmaxf(mx[rp], __shfl_xor_sync(0xffffffffu, mx[rp], 1));
                mx[rp] = fmaxf(mx[rp], __shfl_xor_sync(0xffffffffu, mx[rp], 2));
                mnew[rp] = fmaxf(mr[mt][rp], mx[rp]);
                corr[rp] = __expf((mr[mt][rp] - mnew[rp]) * 0.25f);
                mr[mt][rp] = mnew[rp];
            }
            #pragma unroll
            for (int nt = 0; nt < 8; nt++) {
                s[mt][nt][0] = __expf((s[mt][nt][0] - mnew[0]) * 0.25f);
                s[mt][nt][1] = __expf((s[mt][nt][1] - mnew[0]) * 0.25f);
                s[mt][nt][2] = __expf((s[mt][nt][2] - mnew[1]) * 0.25f);
                s[mt][nt][3] = __expf((s[mt][nt][3] - mnew[1]) * 0.25f);
                sum[0] += s[mt][nt][0] + s[mt][nt][1];
                sum[1] += s[mt][nt][2] + s[mt][nt][3];
            }
            #pragma unroll
            for (int rp = 0; rp < 2; rp++) {
                sum[rp] += __shfl_xor_sync(0xffffffffu, sum[rp], 1);
                sum[rp] += __shfl_xor_sync(0xffffffffu, sum[rp], 2);
                lr[mt][rp] = lr[mt][rp] * corr[rp] + sum[rp];
            }
            #pragma unroll
            for (int nv = 0; nv < 2; nv++) {
                oa[mt][nv][0] *= corr[0]; oa[mt][nv][1] *= corr[0];
                oa[mt][nv][2] *= corr[1]; oa[mt][nv][3] *= corr[1];
            }
        }
        #pragma unroll
        for (int ks = 0; ks < 4; ks++) {
            unsigned pa[2][4];
            #pragma unroll
            for (int mt = 0; mt < 2; mt++) {
                pa[mt][0] = h2pack(s[mt][2 * ks][0], s[mt][2 * ks][1]);
                pa[mt][1] = h2pack(s[mt][2 * ks][2], s[mt][2 * ks][3]);
                pa[mt][2] = h2pack(s[mt][2 * ks + 1][0], s[mt][2 * ks + 1][1]);
                pa[mt][3] = h2pack(s[mt][2 * ks + 1][2], s[mt][2 * ks + 1][3]);
            }
            int kr = kt * 64 + ks * 16;
            #pragma unroll
            for (int nv = 0; nv < 2; nv++) {
                unsigned b0 = *(const unsigned*)&Vt[nv * 8 + g][kr + 2 * tig];
                unsigned b1 = *(const unsigned*)&Vt[nv * 8 + g][kr + 2 * tig + 8];
                mma_f16(oa[0][nv], pa[0], b0, b1);
                mma_f16(oa[1][nv], pa[1], b0, b1);
            }
        }
    }
    #pragma unroll
    for (int mt = 0; mt < 2; mt++) {
        int r0 = warp * 32 + mt * 16 + g;
        float il0 = 1.f / lr[mt][0], il1 = 1.f / lr[mt][1];
        #pragma unroll
        for (int nv = 0; nv < 2; nv++) {
            int d = nv * 8 + 2 * tig;
            *(__half2*)(g_OH + ((size_t)r0 * BB + b) * H + h * 16 + d) =
                __floats2half2_rn(oa[mt][nv][0] * il0, oa[mt][nv][1] * il0);
            *(__half2*)(g_OH + ((size_t)(r0 + 8) * BB + b) * H + h * 16 + d) =
                __floats2half2_rn(oa[mt][nv][2] * il1, oa[mt][nv][3] * il1);
        }
    }
}

// ---------------- final projection + traj output + traj loss ----------------
__global__ void k_traj(const float* __restrict__ w4, const float* __restrict__ b4,
                       const float* __restrict__ w5, const float* __restrict__ b5,
                       const float* __restrict__ traj_in, float* __restrict__ out) {
    int tt = blockIdx.x >> 8;
    int a  = blockIdx.x & 255;
    int b  = threadIdx.x;
    int o = tt + (OBS - PRED);
    const float* xr = g_X + ((size_t)a * 128 + b) * 128;
    float acc = b4[o];
    #pragma unroll 8
    for (int j = 0; j < 128; j++) acc += xr[j] * w4[o * 128 + j];
    float s0 = block_sum<4>(acc * w5[b]);
    float s1 = block_sum<4>(acc * w5[128 + b]);
    if (b == 0) {
        float t0 = s0 + b5[0], t1 = s1 + b5[1];
        float y0 = traj_in[(OBS + tt) * (NAG * 2) + a * 2 + 0];
        float y1 = traj_in[(OBS + tt) * (NAG * 2) + a * 2 + 1];
        out[(tt * 256 + a) * 2 + 0] = t0;
        out[(tt * 256 + a) * 2 + 1] = t1;
        float d0 = t0 - y0, d1 = t1 - y1;
        atomicAdd(&g_traj, (double)sqrtf(d0 * d0 + d1 * d1));
    }
}

__global__ void k_final(float* __restrict__ out) {
    double kld = -0.5 * (g_kld / 2048.0);
    double st = g_struct / (2048.0 * 2048.0);
    double tl = g_traj / 256.0;
    out[PRED * NAG * FOUT] = (float)(tl + kld + st);
}

// ---------------- launch ----------------
extern "C" void kernel_launch(void* const* d_in, const int* in_sizes, int n_in,
                              void* d_out, int out_size) {
    const float* traj_in = (const float*)d_in[0];
    const float* adj_in  = (const float*)d_in[1];
    const float* eps     = (const float*)d_in[2];
    const float* pro1_w  = (const float*)d_in[3];
    const float* pro1_b  = (const float*)d_in[4];
    const float* pro2_w  = (const float*)d_in[5];
    const float* pro2_b  = (const float*)d_in[6];
    const float* mu_w    = (const float*)d_in[7];
    const float* mu_b    = (const float*)d_in[8];
    const float* ls_w    = (const float*)d_in[9];
    const float* ls_b    = (const float*)d_in[10];
    const float* gdl_w   = (const float*)d_in[11];
    const float* gdl_b   = (const float*)d_in[12];
    const float* pro3_w  = (const float*)d_in[13];
    const float* pro3_b  = (const float*)d_in[14];
    const float* pro4_w  = (const float*)d_in[15];
    const float* pro4_b  = (const float*)d_in[16];
    const float* pro5_w  = (const float*)d_in[17];
    const float* pro5_b  = (const float*)d_in[18];
    const float* qkv_w   = (const float*)d_in[19];
    const float* qkv_b   = (const float*)d_in[20];
    const float* out_w   = (const float*)d_in[21];
    const float* out_b   = (const float*)d_in[22];
    const float* ff1_w   = (const float*)d_in[23];
    const float* ff1_b   = (const float*)d_in[24];
    const float* ff2_w   = (const float*)d_in[25];
    const float* ff2_b   = (const float*)d_in[26];
    const float* ln1_g   = (const float*)d_in[27];
    const float* ln1_b   = (const float*)d_in[28];
    const float* ln2_g   = (const float*)d_in[29];
    const float* ln2_b   = (const float*)d_in[30];
    const int*   iftrain = (const int*)d_in[31];
    float* out = (float*)d_out;

    float *pOUTB, *pBMLS, *pX, *pPART;
    __half *pMLSH, *pAGGH, *pENCH, *pZH, *pXH, *pOH, *pQKVH;
    __half *pWQKVH, *pWOUTH, *pWFF1H, *pWFF2H, *pWGDLH, *pWMLSH;
    cudaGetSymbolAddress((void**)&pOUTB,  g_OUTB);
    cudaGetSymbolAddress((void**)&pBMLS,  g_BMLS);
    cudaGetSymbolAddress((void**)&pX,     g_X);
    cudaGetSymbolAddress((void**)&pPART,  g_PART);
    cudaGetSymbolAddress((void**)&pMLSH,  g_MLSH);
    cudaGetSymbolAddress((void**)&pAGGH,  g_AGGH);
    cudaGetSymbolAddress((void**)&pENCH,  g_ENCH);
    cudaGetSymbolAddress((void**)&pZH,    g_ZH);
    cudaGetSymbolAddress((void**)&pXH,    g_XH);
    cudaGetSymbolAddress((void**)&pOH,    g_OH);
    cudaGetSymbolAddress((void**)&pQKVH,  g_QKVH);
    cudaGetSymbolAddress((void**)&pWQKVH, g_WQKVH);
    cudaGetSymbolAddress((void**)&pWOUTH, g_WOUTH);
    cudaGetSymbolAddress((void**)&pWFF1H, g_WFF1H);
    cudaGetSymbolAddress((void**)&pWFF2H, g_WFF2H);
    cudaGetSymbolAddress((void**)&pWGDLH, g_WGDLH);
    cudaGetSymbolAddress((void**)&pWMLSH, g_WMLSH);

    static int smem_set = 0;
    if (!smem_set) {
        cudaFuncSetAttribute(k_ffn, cudaFuncAttributeMaxDynamicSharedMemorySize, 196608);
        smem_set = 1;
    }

    // ---- fused weight conversion + packing ----
    k_cvt<<<3505, 256>>>(qkv_w, out_w, ff1_w, ff2_w, gdl_w, mu_w, ls_w, mu_b, ls_b);

    // ---- graph-VAE front end ----
    k_init<<<8, 256>>>();
    k_minmax<<<512, 256>>>(adj_in);
    k_build<<<dim3(2, NNODE), 256>>>(adj_in);
    k_colsum<<<dim3(16, 64), 128>>>();
    k_dis<<<8, 256>>>();
    k_agg<<<dim3(64, 64), dim3(32, 32)>>>();
    k_enc<<<NNODE, 128>>>(traj_in, pro1_w, pro1_b, pro2_w, pro2_b);

    k_hgemm<5><<<dim3(2, 16), 256>>>(pENCH, pWMLSH, pBMLS, nullptr, pMLSH,
                                     NNODE, 256, H, nullptr, nullptr);
    k_hgemm<7><<<dim3(2, 16, 8), 256>>>(pAGGH, pMLSH, nullptr, pPART, nullptr,
                                        NNODE, 256, NNODE, nullptr, nullptr);
    k_zred<<<1024, 256>>>(eps, iftrain);
    k_hgemm<6><<<dim3(16, 16), 256>>>(pZH, pZH, nullptr, nullptr, nullptr,
                                      NNODE, NNODE, H, nullptr, nullptr);
    k_hgemm<0><<<dim3(1, 16), 256>>>(pZH, pWGDLH, gdl_b, pOUTB, nullptr,
                                     NNODE, H, H, nullptr, nullptr);
    k_xbuild<<<16384, 256>>>(pro3_w, pro3_b);

    // ---- transformer ----
    // layer 0 QKV standalone; k_ffn(l) produces QKV for layer l+1
    k_hgemm<1><<<dim3(3, 256), 256>>>(pXH, pWQKVH, qkv_b,
                                      nullptr, pQKVH, NTOK, 3 * H, H, nullptr, nullptr);
    for (int l = 0; l < NL; l++) {
        k_attn_tc<<<BB * NH, 256>>>();
        k_hgemm<2><<<dim3(1, 256), 256>>>(pOH, pWOUTH + (size_t)l * H * H, out_b + (size_t)l * H,
                                          pX, pXH, NTOK, H, H, ln1_g + l * H, ln1_b + l * H);
        const __half* wq = (l + 1 < NL) ? pWQKVH + (size_t)(l + 1) * 3 * H * H : nullptr;
        const float*  bq = (l + 1 < NL) ? qkv_b + (size_t)(l + 1) * 3 * H : nullptr;
        k_ffn<<<256, 256, 196608>>>(ff1_b + (size_t)l * FFD, ff2_b + (size_t)l * H,
                                    pWFF1H + (size_t)l * FFD * H, pWFF2H + (size_t)l * H * FFD,
                                    pX, pXH, ln2_g + l * H, ln2_b + l * H,
                                    wq, bq, pQKVH);
    }

    // ---- output + loss ----
    k_traj<<<PRED * NAG, 128>>>(pro4_w, pro4_b, pro5_w, pro5_b, traj_in, out);
    k_final<<<1, 1>>>(out);
}

// round 15
// speedup vs baseline: 1.1571x; 1.0030x over previous
#include <cuda_runtime.h>
#include <cuda_fp16.h>
#include <math.h>

#define OBS 8
#define PRED 4
#define NAG 256
#define FIN 2
#define FOUT 2
#define H 128
#define NH 8
#define DH 16
#define FFD 2048
#define NL 6
#define NNODE (OBS*NAG)        /* 2048 */
#define SEQ NAG                /* 256  */
#define BB H                   /* 128  */
#define NTOK (SEQ*BB)          /* 32768 */

// ---------------- scratch (device globals; no allocation) ----------------
static __device__ float  g_ADJ[NNODE*NNODE];
static __device__ __half g_AGGH[NNODE*NNODE];
static __device__ __half g_ENCH[NNODE*H];
static __device__ __half g_MLSH[2*H*NNODE];
static __device__ float  g_PART[8*NNODE*2*H];
static __device__ __half g_ZH[NNODE*H];
static __device__ float  g_OUTB[NNODE*H];
static __device__ float  g_X[NTOK*H];
static __device__ __half g_XH[NTOK*H];
static __device__ __half g_OH[NTOK*H];
static __device__ __half g_QKVH[NTOK*3*H];
static __device__ __half g_WQKVH[NL*3*H*H];
static __device__ __half g_WOUTH[NL*H*H];
static __device__ __half g_WFF1H[(size_t)NL*FFD*H];
static __device__ __half g_WFF2H[(size_t)NL*H*FFD];
static __device__ __half g_WGDLH[H*H];
static __device__ __half g_WMLSH[2*H*H];
static __device__ float  g_BMLS[2*H];
static __device__ float  g_COL[NNODE];
static __device__ float  g_SELF[NNODE];
static __device__ float  g_DIS[NNODE];
static __device__ float  g_mn_acc, g_mx_acc;
static __device__ double g_kld, g_struct, g_traj;

// ---------------- helpers ----------------
__device__ __forceinline__ void atomicMinF(float* a, float v) {
    int* ai = (int*)a; int old = *ai;
    while (__int_as_float(old) > v) {
        int assumed = old;
        old = atomicCAS(ai, assumed, __float_as_int(v));
        if (old == assumed) break;
    }
}
__device__ __forceinline__ void atomicMaxF(float* a, float v) {
    int* ai = (int*)a; int old = *ai;
    while (__int_as_float(old) < v) {
        int assumed = old;
        old = atomicCAS(ai, assumed, __float_as_int(v));
        if (old == assumed) break;
    }
}

template<int NWARPS>
__device__ __forceinline__ float block_sum(float v) {
    __shared__ float w[NWARPS];
    int tid = threadIdx.x + threadIdx.y * blockDim.x;
    int lane = tid & 31, wid = tid >> 5;
    #pragma unroll
    for (int o = 16; o > 0; o >>= 1) v += __shfl_down_sync(0xffffffffu, v, o);
    if (lane == 0) w[wid] = v;
    __syncthreads();
    float r = 0.f;
    #pragma unroll
    for (int i = 0; i < NWARPS; i++) r += w[i];
    __syncthreads();
    return r;
}

__device__ __forceinline__ void mma_f16(float* c, const unsigned* a, unsigned b0, unsigned b1) {
    asm volatile(
        "mma.sync.aligned.m16n8k16.row.col.f32.f16.f16.f32 "
        "{%0,%1,%2,%3}, {%4,%5,%6,%7}, {%8,%9}, {%0,%1,%2,%3};"
        : "+f"(c[0]), "+f"(c[1]), "+f"(c[2]), "+f"(c[3])
        : "r"(a[0]), "r"(a[1]), "r"(a[2]), "r"(a[3]), "r"(b0), "r"(b1));
}

__device__ __forceinline__ unsigned h2pack(float x, float y) {
    __half2 h = __floats2half2_rn(x, y);
    return *(unsigned*)&h;
}

__device__ __forceinline__ unsigned smem_u32(const void* p) {
    return (unsigned)__cvta_generic_to_shared(p);
}
__device__ __forceinline__ void cpa16(unsigned dst, const void* src) {
    asm volatile("cp.async.cg.shared.global [%0], [%1], 16;" :: "r"(dst), "l"(src));
}
__device__ __forceinline__ void lmx4(unsigned& r0, unsigned& r1, unsigned& r2, unsigned& r3, unsigned addr) {
    asm volatile("ldmatrix.sync.aligned.m8n8.x4.shared.b16 {%0,%1,%2,%3}, [%4];"
                 : "=r"(r0), "=r"(r1), "=r"(r2), "=r"(r3) : "r"(addr));
}

// Load a 128x128 half tile into 4 swizzled 8KB sub-buffers.
__device__ __forceinline__ void load_tile128(unsigned dstBase, const __half* src, int srcStride, int tid) {
    int crow = tid >> 1, cpi = (tid & 1) * 2;
    int cswz = (crow >> 1) & 3;
    #pragma unroll
    for (int kc = 0; kc < 4; kc++) {
        const __half* s = src + (size_t)crow * srcStride + kc * 32 + cpi * 8;
        unsigned d = dstBase + kc * 8192 + crow * 64;
        cpa16(d + ((cpi ^ cswz)) * 16, s);
        cpa16(d + (((cpi + 1) ^ cswz)) * 16, s + 8);
    }
}

__device__ __forceinline__ void gemm128(float (&acc)[2][8][4], unsigned abase, unsigned bbase,
                                        int rA0, int rB0, int swA, int swB, int kselA, int kselB) {
    #pragma unroll
    for (int kc = 0; kc < 4; kc++) {
        #pragma unroll
        for (int ks = 0; ks < 2; ks++) {
            unsigned af[2][4];
            #pragma unroll
            for (int mt = 0; mt < 2; mt++) {
                unsigned addr = abase + kc * 8192 + (rA0 + mt * 16) * 64 + (((2 * ks + kselA) ^ swA)) * 16;
                lmx4(af[mt][0], af[mt][1], af[mt][2], af[mt][3], addr);
            }
            unsigned bf[8][2];
            #pragma unroll
            for (int jj = 0; jj < 4; jj++) {
                unsigned addr = bbase + kc * 8192 + (rB0 + jj * 16) * 64 + (((2 * ks + kselB) ^ swB)) * 16;
                lmx4(bf[2 * jj][0], bf[2 * jj][1], bf[2 * jj + 1][0], bf[2 * jj + 1][1], addr);
            }
            #pragma unroll
            for (int nt = 0; nt < 8; nt++) {
                mma_f16(acc[0][nt], af[0], bf[nt][0], bf[nt][1]);
                mma_f16(acc[1][nt], af[1], bf[nt][0], bf[nt][1]);
            }
        }
    }
}

// ---------------- init ----------------
__global__ void k_init() {
    int i = blockIdx.x * 256 + threadIdx.x;
    if (i < NNODE) g_COL[i] = 0.f;
    if (i == 0) {
        g_mn_acc = __int_as_float(0x7f800000);
        g_mx_acc = __int_as_float(0xff800000);
        g_kld = 0.0; g_struct = 0.0; g_traj = 0.0;
    }
}

// ---------------- fused weight conversion ----------------
__global__ void k_cvt(const float* __restrict__ qkv, const float* __restrict__ outw,
                      const float* __restrict__ ff1, const float* __restrict__ ff2,
                      const float* __restrict__ gdl, const float* __restrict__ muw,
                      const float* __restrict__ lsw, const float* __restrict__ mub,
                      const float* __restrict__ lsb) {
    int k = blockIdx.x * 256 + threadIdx.x;
    const float* src; __half* dst; int off;
    if (k < 73728)       { src = qkv;  dst = g_WQKVH;        off = k; }
    else if (k < 98304)  { src = outw; dst = g_WOUTH;        off = k - 73728; }
    else if (k < 491520) { src = ff1;  dst = g_WFF1H;        off = k - 98304; }
    else if (k < 884736) { src = ff2;  dst = g_WFF2H;        off = k - 491520; }
    else if (k < 888832) { src = gdl;  dst = g_WGDLH;        off = k - 884736; }
    else if (k < 892928) { src = muw;  dst = g_WMLSH;        off = k - 888832; }
    else if (k < 897024) { src = lsw;  dst = g_WMLSH + H*H;  off = k - 892928; }
    else if (k < 897088) {
        int o = k - 897024;
        float4 v = (o < 32) ? ((const float4*)mub)[o] : ((const float4*)lsb)[o - 32];
        ((float4*)g_BMLS)[o] = v;
        return;
    } else return;
    float4 v = ((const float4*)src)[off];
    __half2* d = (__half2*)dst + off * 2;
    d[0] = __floats2half2_rn(v.x, v.y);
    d[1] = __floats2half2_rn(v.z, v.w);
}

// ---------------- adjacency prep ----------------
__global__ void k_minmax(const float* __restrict__ adj) {
    const int n = OBS * NAG * NAG;
    float mn = __int_as_float(0x7f800000), mx = -mn;
    for (int i = blockIdx.x * blockDim.x + threadIdx.x; i < n; i += gridDim.x * blockDim.x) {
        float v = adj[i];
        mn = fminf(mn, v); mx = fmaxf(mx, v);
    }
    #pragma unroll
    for (int o = 16; o > 0; o >>= 1) {
        mn = fminf(mn, __shfl_down_sync(0xffffffffu, mn, o));
        mx = fmaxf(mx, __shfl_down_sync(0xffffffffu, mx, o));
    }
    __shared__ float smn[8], smx[8];
    int lane = threadIdx.x & 31, wid = threadIdx.x >> 5;
    if (lane == 0) { smn[wid] = mn; smx[wid] = mx; }
    __syncthreads();
    if (threadIdx.x == 0) {
        for (int w = 1; w < 8; w++) { mn = fminf(mn, smn[w]); mx = fmaxf(mx, smx[w]); }
        atomicMinF(&g_mn_acc, mn);
        atomicMaxF(&g_mx_acc, mx);
    }
}

__global__ void k_build(const float* __restrict__ adj) {
    float mn = fminf(g_mn_acc, 0.f);
    float mx = fmaxf(g_mx_acc, 0.f);
    float inv = 1.f / (mx - mn);
    int i = blockIdx.y;
    int j = (blockIdx.x * 256 + threadIdx.x) * 4;
    int ti = i >> 8, tj = j >> 8;
    float4 a = make_float4(0.f, 0.f, 0.f, 0.f);
    if (ti == tj)
        a = *(const float4*)(adj + (ti << 16) + ((i & 255) << 8) + (j & 255));
    float4 v = make_float4((a.x - mn) * inv, (a.y - mn) * inv, (a.z - mn) * inv, (a.w - mn) * inv);
    *(float4*)(g_ADJ + (size_t)i * NNODE + j) = v;
    if (i >= j && i < j + 4) {
        float d = (i == j) ? v.x : (i == j + 1) ? v.y : (i == j + 2) ? v.z : v.w;
        g_SELF[i] = (d == 0.f) ? 1.f : 0.f;
    }
}

__global__ void k_colsum() {
    int j = blockIdx.x * 128 + threadIdx.x;
    int i0 = blockIdx.y * 32;
    float s = 0.f;
    for (int r = 0; r < 32; r++) s += g_ADJ[(size_t)(i0 + r) * NNODE + j];
    atomicAdd(&g_COL[j], s);
}

__global__ void k_dis() {
    int j = blockIdx.x * 256 + threadIdx.x;
    if (j < NNODE) {
        float deg = g_COL[j] + g_SELF[j];
        g_DIS[j] = (deg > 0.f) ? (1.f / sqrtf(deg)) : 0.f;
    }
}

__global__ void k_agg() {
    __shared__ float s[32][33];
    int i0 = blockIdx.y * 32, j0 = blockIdx.x * 32;
    int tx = threadIdx.x, ty = threadIdx.y;
    s[ty][tx] = g_ADJ[(size_t)(j0 + ty) * NNODE + (i0 + tx)];
    __syncthreads();
    int i = i0 + ty, j = j0 + tx;
    float v = s[tx][ty];
    if (i == j) v += g_SELF[i];
    g_AGGH[(size_t)i * NNODE + j] = __float2half(g_DIS[j] * v * g_DIS[i]);
}

// ---------------- encoder ----------------
__global__ void k_enc(const float* __restrict__ traj,
                      const float* __restrict__ w1, const float* __restrict__ b1,
                      const float* __restrict__ w2, const float* __restrict__ b2) {
    int n = blockIdx.x, j = threadIdx.x;
    __shared__ float h1[128];
    float x0 = traj[n * 2], x1 = traj[n * 2 + 1];
    h1[j] = fmaxf(w1[j * 2] * x0 + w1[j * 2 + 1] * x1 + b1[j], 0.f);
    __syncthreads();
    float a = b2[j];
    #pragma unroll 8
    for (int k = 0; k < 128; k++) a += w2[j * 128 + k] * h1[k];
    g_ENCH[n * 128 + j] = __float2half(a);
}

// ---------------- fp16 TC GEMM, cp.async 3-stage + ldmatrix ------------------
template<int EPI>
__global__ __launch_bounds__(256, 2) void k_hgemm(
    const __half* __restrict__ A, const __half* __restrict__ B,
    const float* __restrict__ bias, float* __restrict__ C, __half* __restrict__ Ch,
    int M, int N, int K,
    const float* __restrict__ gamma, const float* __restrict__ beta)
{
    __shared__ __align__(16) __half SA[3][4096];
    __shared__ __align__(16) __half SB[3][4096];
    int bm = blockIdx.y * 128, bn = blockIdx.x * 128;
    int tid = threadIdx.x;
    int warp = tid >> 5, lane = tid & 31;
    int wm = warp & 3, wn = warp >> 2;
    int g = lane >> 2, tig = lane & 3;

    int ksz = K / gridDim.z;
    int k_begin = blockIdx.z * ksz;
    const int nch = ksz >> 5;

    unsigned baseSA = smem_u32(&SA[0][0]);
    unsigned baseSB = smem_u32(&SB[0][0]);

    int crow = tid >> 1, cp = (tid & 1) * 2;
    int cswz = (crow >> 1) & 3;
    unsigned dA0 = baseSA + crow * 64 + ((cp ^ cswz)) * 16;
    unsigned dA1 = baseSA + crow * 64 + (((cp + 1) ^ cswz)) * 16;
    unsigned dB0 = baseSB + crow * 64 + ((cp ^ cswz)) * 16;
    unsigned dB1 = baseSB + crow * 64 + (((cp + 1) ^ cswz)) * 16;
    const __half* srcA = A + (size_t)(bm + crow) * K + k_begin + cp * 8;
    const __half* srcB = B + (size_t)(bn + crow) * K + k_begin + cp * 8;

    int m = lane >> 3, mi = lane & 7;
    int rA0 = wm * 32 + ((m & 1) << 3) + mi;
    int rB0 = wn * 64 + ((m >> 1) << 3) + mi;
    int swA = (rA0 >> 1) & 3;
    int swB = (rB0 >> 1) & 3;
    int kselA = m >> 1, kselB = m & 1;

    float acc[2][8][4] = {};

    #pragma unroll
    for (int s = 0; s < 2; s++) {
        if (s < nch) {
            unsigned so = s * 8192u;
            cpa16(dA0 + so, srcA + s * 32);
            cpa16(dA1 + so, srcA + s * 32 + 8);
            cpa16(dB0 + so, srcB + s * 32);
            cpa16(dB1 + so, srcB + s * 32 + 8);
        }
        asm volatile("cp.async.commit_group;");
    }

    for (int c = 0; c < nch; c++) {
        asm volatile("cp.async.wait_group 1;");
        __syncthreads();
        int pf = c + 2;
        if (pf < nch) {
            unsigned so = (pf % 3) * 8192u;
            cpa16(dA0 + so, srcA + pf * 32);
            cpa16(dA1 + so, srcA + pf * 32 + 8);
            cpa16(dB0 + so, srcB + pf * 32);
            cpa16(dB1 + so, srcB + pf * 32 + 8);
        }
        asm volatile("cp.async.commit_group;");
        unsigned so = (c % 3) * 8192u;
        #pragma unroll
        for (int ks = 0; ks < 2; ks++) {
            unsigned af[2][4];
            #pragma unroll
            for (int mt = 0; mt < 2; mt++) {
                unsigned addr = baseSA + so + (rA0 + mt * 16) * 64 + (((2 * ks + kselA) ^ swA)) * 16;
                lmx4(af[mt][0], af[mt][1], af[mt][2], af[mt][3], addr);
            }
            unsigned bf[8][2];
            #pragma unroll
            for (int jj = 0; jj < 4; jj++) {
                unsigned addr = baseSB + so + (rB0 + jj * 16) * 64 + (((2 * ks + kselB) ^ swB)) * 16;
                lmx4(bf[2 * jj][0], bf[2 * jj][1], bf[2 * jj + 1][0], bf[2 * jj + 1][1], addr);
            }
            #pragma unroll
            for (int nt = 0; nt < 8; nt++) {
                mma_f16(acc[0][nt], af[0], bf[nt][0], bf[nt][1]);
                mma_f16(acc[1][nt], af[1], bf[nt][0], bf[nt][1]);
            }
        }
    }

    if (EPI == 0) {
        #pragma unroll
        for (int mt = 0; mt < 2; mt++) {
            int r0 = bm + wm * 32 + mt * 16 + g;
            #pragma unroll
            for (int nt = 0; nt < 8; nt++) {
                int c0 = bn + wn * 64 + nt * 8 + 2 * tig;
                float bv0 = bias[c0], bv1 = bias[c0 + 1];
                *(float2*)(C + (size_t)r0 * N + c0) =
                    make_float2(acc[mt][nt][0] + bv0, acc[mt][nt][1] + bv1);
                *(float2*)(C + (size_t)(r0 + 8) * N + c0) =
                    make_float2(acc[mt][nt][2] + bv0, acc[mt][nt][3] + bv1);
            }
        }
    } else if (EPI == 1) {
        int p = blockIdx.x;
        #pragma unroll
        for (int mt = 0; mt < 2; mt++) {
            int r0 = bm + wm * 32 + mt * 16 + g;
            int r1 = r0 + 8;
            #pragma unroll
            for (int nt = 0; nt < 8; nt++) {
                int rem = wn * 64 + nt * 8 + 2 * tig;
                int h = rem >> 4, d = rem & 15;
                int c0 = bn + rem;
                float bv0 = bias[c0], bv1 = bias[c0 + 1];
                size_t b0 = ((size_t)((p * 8 + h) * 128 + (r0 & 127)) * 256 + (r0 >> 7)) * 16 + d;
                size_t b1 = ((size_t)((p * 8 + h) * 128 + (r1 & 127)) * 256 + (r1 >> 7)) * 16 + d;
                *(__half2*)(Ch + b0) = __floats2half2_rn(acc[mt][nt][0] + bv0, acc[mt][nt][1] + bv1);
                *(__half2*)(Ch + b1) = __floats2half2_rn(acc[mt][nt][2] + bv0, acc[mt][nt][3] + bv1);
            }
        }
    } else if (EPI == 2) {
        float sums[2][2], sqs[2][2];
        #pragma unroll
        for (int mt = 0; mt < 2; mt++) { sums[mt][0] = sums[mt][1] = sqs[mt][0] = sqs[mt][1] = 0.f; }
        #pragma unroll
        for (int mt = 0; mt < 2; mt++) {
            int r0 = bm + wm * 32 + mt * 16 + g;
            #pragma unroll
            for (int nt = 0; nt < 8; nt++) {
                int c0 = wn * 64 + nt * 8 + 2 * tig;
                float bv0 = bias[c0], bv1 = bias[c0 + 1];
                float v00 = acc[mt][nt][0] + bv0 + C[(size_t)r0 * 128 + c0];
                float v01 = acc[mt][nt][1] + bv1 + C[(size_t)r0 * 128 + c0 + 1];
                float v10 = acc[mt][nt][2] + bv0 + C[(size_t)(r0 + 8) * 128 + c0];
                float v11 = acc[mt][nt][3] + bv1 + C[(size_t)(r0 + 8) * 128 + c0 + 1];
                acc[mt][nt][0] = v00; acc[mt][nt][1] = v01;
                acc[mt][nt][2] = v10; acc[mt][nt][3] = v11;
                sums[mt][0] += v00 + v01; sqs[mt][0] += v00 * v00 + v01 * v01;
                sums[mt][1] += v10 + v11; sqs[mt][1] += v10 * v10 + v11 * v11;
            }
        }
        #pragma unroll
        for (int mt = 0; mt < 2; mt++)
            #pragma unroll
            for (int rp = 0; rp < 2; rp++) {
                float s = sums[mt][rp], q = sqs[mt][rp];
                s += __shfl_xor_sync(0xffffffffu, s, 1); q += __shfl_xor_sync(0xffffffffu, q, 1);
                s += __shfl_xor_sync(0xffffffffu, s, 2); q += __shfl_xor_sync(0xffffffffu, q, 2);
                sums[mt][rp] = s; sqs[mt][rp] = q;
            }
        __syncthreads();
        float* red = (float*)SA;
        if (tig == 0) {
            #pragma unroll
            for (int mt = 0; mt < 2; mt++)
                #pragma unroll
                for (int rp = 0; rp < 2; rp++) {
                    int ix = ((warp * 16 + g) * 4 + mt * 2 + rp) * 2;
                    red[ix] = sums[mt][rp]; red[ix + 1] = sqs[mt][rp];
                }
        }
        __syncthreads();
        float mean[2][2], inv[2][2];
        #pragma unroll
        for (int mt = 0; mt < 2; mt++)
            #pragma unroll
            for (int rp = 0; rp < 2; rp++) {
                int i0 = (((wm) * 16 + g) * 4 + mt * 2 + rp) * 2;
                int i1 = (((wm + 4) * 16 + g) * 4 + mt * 2 + rp) * 2;
                float s = red[i0] + red[i1];
                float q = red[i0 + 1] + red[i1 + 1];
                float mm = s * (1.f / 128.f);
                float var = q * (1.f / 128.f) - mm * mm;
                mean[mt][rp] = mm;
                inv[mt][rp] = rsqrtf(var + 1e-5f);
            }
        #pragma unroll
        for (int mt = 0; mt < 2; mt++) {
            int r0 = bm + wm * 32 + mt * 16 + g;
            #pragma unroll
            for (int nt = 0; nt < 8; nt++) {
                int c0 = wn * 64 + nt * 8 + 2 * tig;
                float g0 = gamma[c0], g1 = gamma[c0 + 1];
                float be0 = beta[c0], be1 = beta[c0 + 1];
                float v00 = (acc[mt][nt][0] - mean[mt][0]) * inv[mt][0] * g0 + be0;
                float v01 = (acc[mt][nt][1] - mean[mt][0]) * inv[mt][0] * g1 + be1;
                float v10 = (acc[mt][nt][2] - mean[mt][1]) * inv[mt][1] * g0 + be0;
                float v11 = (acc[mt][nt][3] - mean[mt][1]) * inv[mt][1] * g1 + be1;
                *(float2*)(C + (size_t)r0 * 128 + c0)       = make_float2(v00, v01);
                *(float2*)(C + (size_t)(r0 + 8) * 128 + c0) = make_float2(v10, v11);
                *(__half2*)(Ch + (size_t)r0 * 128 + c0)       = __floats2half2_rn(v00, v01);
                *(__half2*)(Ch + (size_t)(r0 + 8) * 128 + c0) = __floats2half2_rn(v10, v11);
            }
        }
    } else if (EPI == 5) {
        #pragma unroll
        for (int mt = 0; mt < 2; mt++) {
            int r0 = bm + wm * 32 + mt * 16 + g;
            #pragma unroll
            for (int nt = 0; nt < 8; nt++) {
                int c0 = bn + wn * 64 + nt * 8 + 2 * tig;
                float bv0 = bias[c0], bv1 = bias[c0 + 1];
                Ch[(size_t)c0 * M + r0]           = __float2half(acc[mt][nt][0] + bv0);
                Ch[(size_t)(c0 + 1) * M + r0]     = __float2half(acc[mt][nt][1] + bv1);
                Ch[(size_t)c0 * M + r0 + 8]       = __float2half(acc[mt][nt][2] + bv0);
                Ch[(size_t)(c0 + 1) * M + r0 + 8] = __float2half(acc[mt][nt][3] + bv1);
            }
        }
    } else if (EPI == 6) {
        float contrib = 0.f;
        #pragma unroll
        for (int mt = 0; mt < 2; mt++) {
            int r0 = bm + wm * 32 + mt * 16 + g;
            #pragma unroll
            for (int nt = 0; nt < 8; nt++) {
                int c0 = bn + wn * 64 + nt * 8 + 2 * tig;
                float2 ad0 = *(const float2*)(g_ADJ + (size_t)r0 * NNODE + c0);
                float2 ad1 = *(const float2*)(g_ADJ + (size_t)(r0 + 8) * NNODE + c0);
                float a00 = acc[mt][nt][0], a01 = acc[mt][nt][1];
                float a10 = acc[mt][nt][2], a11 = acc[mt][nt][3];
                contrib += fmaxf(a00, 0.f) - a00 * ad0.x + log1pf(expf(-fabsf(a00)));
                contrib += fmaxf(a01, 0.f) - a01 * ad0.y + log1pf(expf(-fabsf(a01)));
                contrib += fmaxf(a10, 0.f) - a10 * ad1.x + log1pf(expf(-fabsf(a10)));
                contrib += fmaxf(a11, 0.f) - a11 * ad1.y + log1pf(expf(-fabsf(a11)));
            }
        }
        #pragma unroll
        for (int o = 16; o > 0; o >>= 1) contrib += __shfl_down_sync(0xffffffffu, contrib, o);
        __syncthreads();
        float* red = (float*)SA;
        if (lane == 0) red[warp] = contrib;
        __syncthreads();
        if (tid == 0) {
            float s = 0.f;
            for (int w = 0; w < 8; w++) s += red[w];
            atomicAdd(&g_struct, (double)s);
        }
    } else { // EPI == 7
        float* P = C + (size_t)blockIdx.z * M * N;
        #pragma unroll
        for (int mt = 0; mt < 2; mt++) {
            int r0 = bm + wm * 32 + mt * 16 + g;
            #pragma unroll
            for (int nt = 0; nt < 8; nt++) {
                int c0 = bn + wn * 64 + nt * 8 + 2 * tig;
                *(float2*)(P + (size_t)r0 * N + c0)       = make_float2(acc[mt][nt][0], acc[mt][nt][1]);
                *(float2*)(P + (size_t)(r0 + 8) * N + c0) = make_float2(acc[mt][nt][2], acc[mt][nt][3]);
            }
        }
    }
}

// ---------------- fused FF + next-layer QKV ---------------------------------
__global__ __launch_bounds__(256, 1) void k_ffn(
    const float* __restrict__ bias1, const float* __restrict__ bias2,
    const __half* __restrict__ W1, const __half* __restrict__ W2,
    float* __restrict__ X, __half* __restrict__ XH,
    const float* __restrict__ gamma, const float* __restrict__ beta,
    const __half* __restrict__ Wqkv, const float* __restrict__ bqkv,
    __half* __restrict__ QKV)
{
    extern __shared__ __align__(16) __half sm[];
    unsigned baseSX = smem_u32(sm);
    unsigned baseSH = baseSX + 32768;
    unsigned baseW1 = baseSH + 32768;
    unsigned baseW2 = baseW1 + 65536;
    int bm = blockIdx.x * 128;
    int tid = threadIdx.x;
    int warp = tid >> 5, lane = tid & 31;
    int wm = warp & 3, wn = warp >> 2;
    int g = lane >> 2, tig = lane & 3;
    int m = lane >> 3, mi = lane & 7;
    int rA0 = wm * 32 + ((m & 1) << 3) + mi;
    int rB0 = wn * 64 + ((m >> 1) << 3) + mi;
    int swA = (rA0 >> 1) & 3;
    int swB = (rB0 >> 1) & 3;
    int kselA = m >> 1, kselB = m & 1;

    load_tile128(baseSX, XH + (size_t)bm * 128, 128, tid);
    load_tile128(baseW1, W1, 128, tid);
    load_tile128(baseW2, W2, FFD, tid);
    asm volatile("cp.async.commit_group;");

    float acc2[2][8][4] = {};

    for (int ch = 0; ch < 16; ch++) {
        int buf = ch & 1;
        asm volatile("cp.async.wait_group 0;");
        __syncthreads();
        if (ch + 1 < 16) {
            load_tile128(baseW1 + (buf ^ 1) * 32768u, W1 + (size_t)(ch + 1) * 128 * 128, 128, tid);
            load_tile128(baseW2 + (buf ^ 1) * 32768u, W2 + (ch + 1) * 128, FFD, tid);
        }
        asm volatile("cp.async.commit_group;");

        float acc1[2][8][4] = {};
        gemm128(acc1, baseSX, baseW1 + buf * 32768u, rA0, rB0, swA, swB, kselA, kselB);

        #pragma unroll
        for (int mt = 0; mt < 2; mt++) {
            int r0 = wm * 32 + mt * 16 + g;
            int r1 = r0 + 8;
            int sw0 = (r0 >> 1) & 3, sw1 = (r1 >> 1) & 3;
            #pragma unroll
            for (int nt = 0; nt < 8; nt++) {
                int c0 = wn * 64 + nt * 8 + 2 * tig;
                float bv0 = bias1[ch * 128 + c0], bv1 = bias1[ch * 128 + c0 + 1];
                unsigned h0 = h2pack(fmaxf(acc1[mt][nt][0] + bv0, 0.f), fmaxf(acc1[mt][nt][1] + bv1, 0.f));
                unsigned h1 = h2pack(fmaxf(acc1[mt][nt][2] + bv0, 0.f), fmaxf(acc1[mt][nt][3] + bv1, 0.f));
                int kc = c0 >> 5;
                int chunkLog = (c0 >> 3) & 3;
                unsigned off = (unsigned)(kc * 8192 + ((chunkLog ^ sw0)) * 16 + 2 * (2 * tig));
                asm volatile("st.shared.b32 [%0], %1;" :: "r"(baseSH + r0 * 64 + off), "r"(h0));
                unsigned off1 = (unsigned)(kc * 8192 + ((chunkLog ^ sw1)) * 16 + 2 * (2 * tig));
                asm volatile("st.shared.b32 [%0], %1;" :: "r"(baseSH + r1 * 64 + off1), "r"(h1));
            }
        }
        __syncthreads();
        gemm128(acc2, baseSH, baseW2 + buf * 32768u, rA0, rB0, swA, swB, kselA, kselB);
    }

    if (Wqkv) load_tile128(baseW1, Wqkv, 128, tid);
    asm volatile("cp.async.commit_group;");

    float sums[2][2], sqs[2][2];
    #pragma unroll
    for (int mt = 0; mt < 2; mt++) { sums[mt][0] = sums[mt][1] = sqs[mt][0] = sqs[mt][1] = 0.f; }
    #pragma unroll
    for (int mt = 0; mt < 2; mt++) {
        int r0 = bm + wm * 32 + mt * 16 + g;
        #pragma unroll
        for (int nt = 0; nt < 8; nt++) {
            int c0 = wn * 64 + nt * 8 + 2 * tig;
            float bv0 = bias2[c0], bv1 = bias2[c0 + 1];
            float v00 = acc2[mt][nt][0] + bv0 + X[(size_t)r0 * 128 + c0];
            float v01 = acc2[mt][nt][1] + bv1 + X[(size_t)r0 * 128 + c0 + 1];
            float v10 = acc2[mt][nt][2] + bv0 + X[(size_t)(r0 + 8) * 128 + c0];
            float v11 = acc2[mt][nt][3] + bv1 + X[(size_t)(r0 + 8) * 128 + c0 + 1];
            acc2[mt][nt][0] = v00; acc2[mt][nt][1] = v01;
            acc2[mt][nt][2] = v10; acc2[mt][nt][3] = v11;
            sums[mt][0] += v00 + v01; sqs[mt][0] += v00 * v00 + v01 * v01;
            sums[mt][1] += v10 + v11; sqs[mt][1] += v10 * v10 + v11 * v11;
        }
    }
    #pragma unroll
    for (int mt = 0; mt < 2; mt++)
        #pragma unroll
        for (int rp = 0; rp < 2; rp++) {
            float s = sums[mt][rp], q = sqs[mt][rp];
            s += __shfl_xor_sync(0xffffffffu, s, 1); q += __shfl_xor_sync(0xffffffffu, q, 1);
            s += __shfl_xor_sync(0xffffffffu, s, 2); q += __shfl_xor_sync(0xffffffffu, q, 2);
            sums[mt][rp] = s; sqs[mt][rp] = q;
        }
    __syncthreads();
    float* red = (float*)sm;
    if (tig == 0) {
        #pragma unroll
        for (int mt = 0; mt < 2; mt++)
            #pragma unroll
            for (int rp = 0; rp < 2; rp++) {
                int ix = ((warp * 16 + g) * 4 + mt * 2 + rp) * 2;
                red[ix] = sums[mt][rp]; red[ix + 1] = sqs[mt][rp];
            }
    }
    __syncthreads();
    float mean[2][2], inv[2][2];
    #pragma unroll
    for (int mt = 0; mt < 2; mt++)
        #pragma unroll
        for (int rp = 0; rp < 2; rp++) {
            int i0 = (((wm) * 16 + g) * 4 + mt * 2 + rp) * 2;
            int i1 = (((wm + 4) * 16 + g) * 4 + mt * 2 + rp) * 2;
            float s = red[i0] + red[i1];
            float q = red[i0 + 1] + red[i1 + 1];
            float mm = s * (1.f / 128.f);
            float var = q * (1.f / 128.f) - mm * mm;
            mean[mt][rp] = mm;
            inv[mt][rp] = rsqrtf(var + 1e-5f);
        }
    __syncthreads();
    #pragma unroll
    for (int mt = 0; mt < 2; mt++) {
        int r0 = bm + wm * 32 + mt * 16 + g;
        int lr0 = wm * 32 + mt * 16 + g;
        int lr1 = lr0 + 8;
        int sw0 = (lr0 >> 1) & 3, sw1 = (lr1 >> 1) & 3;
        #pragma unroll
        for (int nt = 0; nt < 8; nt++) {
            int c0 = wn * 64 + nt * 8 + 2 * tig;
            float g0 = gamma[c0], g1 = gamma[c0 + 1];
            float be0 = beta[c0], be1 = beta[c0 + 1];
            float v00 = (acc2[mt][nt][0] - mean[mt][0]) * inv[mt][0] * g0 + be0;
            float v01 = (acc2[mt][nt][1] - mean[mt][0]) * inv[mt][0] * g1 + be1;
            float v10 = (acc2[mt][nt][2] - mean[mt][1]) * inv[mt][1] * g0 + be0;
            float v11 = (acc2[mt][nt][3] - mean[mt][1]) * inv[mt][1] * g1 + be1;
            *(float2*)(X + (size_t)r0 * 128 + c0)       = make_float2(v00, v01);
            *(float2*)(X + (size_t)(r0 + 8) * 128 + c0) = make_float2(v10, v11);
            __half2 hv0 = __floats2half2_rn(v00, v01);
            __half2 hv1 = __floats2half2_rn(v10, v11);
            *(__half2*)(XH + (size_t)r0 * 128 + c0)       = hv0;
            *(__half2*)(XH + (size_t)(r0 + 8) * 128 + c0) = hv1;
            if (Wqkv) {
                int kc = c0 >> 5;
                int chunkLog = (c0 >> 3) & 3;
                unsigned off = (unsigned)(kc * 8192 + ((chunkLog ^ sw0)) * 16 + 4 * tig);
                asm volatile("st.shared.b32 [%0], %1;" :: "r"(baseSH + lr0 * 64 + off), "r"(*(unsigned*)&hv0));
                unsigned off1 = (unsigned)(kc * 8192 + ((chunkLog ^ sw1)) * 16 + 4 * tig);
                asm volatile("st.shared.b32 [%0], %1;" :: "r"(baseSH + lr1 * 64 + off1), "r"(*(unsigned*)&hv1));
            }
        }
    }

    if (Wqkv) {
        for (int p = 0; p < 3; p++) {
            int buf = p & 1;
            asm volatile("cp.async.wait_group 0;");
            __syncthreads();
            if (p + 1 < 3)
                load_tile128(baseW1 + (buf ^ 1) * 32768u, Wqkv + (size_t)(p + 1) * 128 * 128, 128, tid);
            asm volatile("cp.async.commit_group;");

            float qacc[2][8][4] = {};
            gemm128(qacc, baseSH, baseW1 + buf * 32768u, rA0, rB0, swA, swB, kselA, kselB);

            #pragma unroll
            for (int mt = 0; mt < 2; mt++) {
                int r0 = bm + wm * 32 + mt * 16 + g;
                int r1 = r0 + 8;
                #pragma unroll
                for (int nt = 0; nt < 8; nt++) {
                    int rem = wn * 64 + nt * 8 + 2 * tig;
                    int h = rem >> 4, d = rem & 15;
                    int c0 = p * 128 + rem;
                    float bv0 = bqkv[c0], bv1 = bqkv[c0 + 1];
                    size_t b0 = ((size_t)((p * 8 + h) * 128 + (r0 & 127)) * 256 + (r0 >> 7)) * 16 + d;
                    size_t b1 = ((size_t)((p * 8 + h) * 128 + (r1 & 127)) * 256 + (r1 >> 7)) * 16 + d;
                    *(__half2*)(QKV + b0) = __floats2half2_rn(qacc[mt][nt][0] + bv0, qacc[mt][nt][1] + bv1);
                    *(__half2*)(QKV + b1) = __floats2half2_rn(qacc[mt][nt][2] + bv0, qacc[mt][nt][3] + bv1);
                }
            }
        }
    }
}

// ---------------- split-K reduce + reparameterization + KLD -----------------
__global__ void k_zred(const float* __restrict__ eps, const int* __restrict__ iftrain) {
    int idx = blockIdx.x * 256 + threadIdx.x;
    int i = idx >> 7, j = idx & 127;
    float mu = 0.f, ls = 0.f;
    #pragma unroll
    for (int z = 0; z < 8; z++) {
        mu += g_PART[((size_t)z * NNODE + i) * 256 + j];
        ls += g_PART[((size_t)z * NNODE + i) * 256 + 128 + j];
    }
    ls = fminf(ls, 10.f);
    float zz = (*iftrain > 0) ? (mu + eps[idx] * expf(ls)) : mu;
    g_ZH[idx] = __float2half(zz);
    float term = 1.f + 2.f * ls - mu * mu - expf(2.f * ls);
    float bs = block_sum<8>(term);
    if (threadIdx.x == 0) atomicAdd(&g_kld, (double)bs);
}

// ---------------- build transformer input x ----------------
__global__ void k_xbuild(const float* __restrict__ w3, const float* __restrict__ b3) {
    int idx = blockIdx.x * 256 + threadIdx.x;
    int j = idx & 127;
    int tok = idx >> 7;
    int a = tok >> 7, h = tok & 127;
    float acc = b3[j];
    #pragma unroll
    for (int t = 0; t < OBS; t++)
        acc += g_OUTB[(size_t)((t << 8) + a) * H + h] * w3[j * OBS + t];
    g_X[idx] = acc;
    g_XH[idx] = __float2half(acc);
}

// ---------------- tensor-core flash attention (online max, R13) -------------
__global__ __launch_bounds__(256) void k_attn_tc() {
    __shared__ __half Qs[256][16];
    __shared__ __half Ks[256][16];
    __shared__ __half Vt[16][264];
    int bh = blockIdx.x;
    int b = bh >> 3, h = bh & 7;
    int tid = threadIdx.x, warp = tid >> 5, lane = tid & 31;
    int g = lane >> 2, tig = lane & 3;
    const __half* Qb = g_QKVH + ((size_t)((0 * 8 + h) * 128 + b)) * 4096;
    const __half* Kb = g_QKVH + ((size_t)((1 * 8 + h) * 128 + b)) * 4096;
    const __half* Vb = g_QKVH + ((size_t)((2 * 8 + h) * 128 + b)) * 4096;
    for (int i = tid; i < 512; i += 256) {
        ((uint4*)Qs)[i] = ((const uint4*)Qb)[i];
        ((uint4*)Ks)[i] = ((const uint4*)Kb)[i];
    }
    {
        const __half2* vp = (const __half2*)(Vb + (size_t)tid * 16);
        #pragma unroll
        for (int j = 0; j < 8; j++) {
            __half2 v = vp[j];
            Vt[2 * j][tid] = __low2half(v);
            Vt[2 * j + 1][tid] = __high2half(v);
        }
    }
    __syncthreads();

    unsigned qf[2][4];
    #pragma unroll
    for (int mt = 0; mt < 2; mt++) {
        int r = warp * 32 + mt * 16 + g;
        qf[mt][0] = *(const unsigned*)&Qs[r][2 * tig];
        qf[mt][1] = *(const unsigned*)&Qs[r + 8][2 * tig];
        qf[mt][2] = *(const unsigned*)&Qs[r][2 * tig + 8];
        qf[mt][3] = *(const unsigned*)&Qs[r + 8][2 * tig + 8];
    }
    float mr[2][2], lr[2][2], oa[2][2][4];
    #pragma unroll
    for (int mt = 0; mt < 2; mt++)
        #pragma unroll
        for (int rp = 0; rp < 2; rp++) { mr[mt][rp] = -1e30f; lr[mt][rp] = 0.f; }
    #pragma unroll
    for (int mt = 0; mt < 2; mt++)
        #pragma unroll
        for (int nv = 0; nv < 2; nv++)
            #pragma unroll
            for (int c = 0; c < 4; c++) oa[mt][nv][c] = 0.f;

    #pragma unroll
    for (int kt = 0; kt < 4; kt++) {
        float s[2][8][4] = {};
        #pragma unroll
        for (int nt = 0; nt < 8; nt++) {
            int sr = kt * 64 + nt * 8 + g;
            unsigned b0 = *(const unsigned*)&Ks[sr][2 * tig];
            unsigned b1 = *(const unsigned*)&Ks[sr][2 * tig + 8];
            mma_f16(s[0][nt], qf[0], b0, b1);
            mma_f16(s[1][nt], qf[1], b0, b1);
        }
        #pragma unroll
        for (int mt = 0; mt < 2; mt++) {
            float mx[2] = {-1e30f, -1e30f};
            #pragma unroll
            for (int nt = 0; nt < 8; nt++) {
                mx[0] = fmaxf(mx[0], fmaxf(s[mt][nt][0], s[mt][nt][1]));
                mx[1] = fmaxf(mx[1], fmaxf(s[mt][nt][2], s[mt][nt][3]));
            }
            float mnew[2], corr[2], sum[2] = {0.f, 0.f};
            #pragma unroll
            for (int rp = 0; rp < 2; rp++) {
                mx[rp] = fmaxf(mx[rp], __shfl_xor_sync(0xffffffffu, mx[rp], 1));
                mx[rp] = fmaxf(mx[rp], __shfl_xor_sync(0xffffffffu, mx[rp], 2));
                mnew[rp] = fmaxf(mr[mt][rp], mx[rp]);
                corr[rp] = __expf((mr[mt][rp] - mnew[rp]) * 0.25f);
                mr[mt][rp] = mnew[rp];
            }
            #pragma unroll
            for (int nt = 0; nt < 8; nt++) {
                s[mt][nt][0] = __expf((s[mt][nt][0] - mnew[0]) * 0.25f);
                s[mt][nt][1] = __expf((s[mt][nt][1] - mnew[0]) * 0.25f);
                s[mt][nt][2] = __expf((s[mt][nt][2] - mnew[1]) * 0.25f);
                s[mt][nt][3] = __expf((s[mt][nt][3] - mnew[1]) * 0.25f);
                sum[0] += s[mt][nt][0] + s[mt][nt][1];
                sum[1] += s[mt][nt][2] + s[mt][nt][3];
            }
            #pragma unroll
            for (int rp = 0; rp < 2; rp++) {
                sum[rp] += __shfl_xor_sync(0xffffffffu, sum[rp], 1);
                sum[rp] += __shfl_xor_sync(0xffffffffu, sum[rp], 2);
                lr[mt][rp] = lr[mt][rp] * corr[rp] + sum[rp];
            }
            #pragma unroll
            for (int nv = 0; nv < 2; nv++) {
                oa[mt][nv][0] *= corr[0]; oa[mt][nv][1] *= corr[0];
                oa[mt][nv][2] *= corr[1]; oa[mt][nv][3] *= corr[1];
            }
        }
        #pragma unroll
        for (int ks = 0; ks < 4; ks++) {
            unsigned pa[2][4];
            #pragma unroll
            for (int mt = 0; mt < 2; mt++) {
                pa[mt][0] = h2pack(s[mt][2 * ks][0], s[mt][2 * ks][1]);
                pa[mt][1] = h2pack(s[mt][2 * ks][2], s[mt][2 * ks][3]);
                pa[mt][2] = h2pack(s[mt][2 * ks + 1][0], s[mt][2 * ks + 1][1]);
                pa[mt][3] = h2pack(s[mt][2 * ks + 1][2], s[mt][2 * ks + 1][3]);
            }
            int kr = kt * 64 + ks * 16;
            #pragma unroll
            for (int nv = 0; nv < 2; nv++) {
                unsigned b0 = *(const unsigned*)&Vt[nv * 8 + g][kr + 2 * tig];
                unsigned b1 = *(const unsigned*)&Vt[nv * 8 + g][kr + 2 * tig + 8];
                mma_f16(oa[0][nv], pa[0], b0, b1);
                mma_f16(oa[1][nv], pa[1], b0, b1);
            }
        }
    }
    #pragma unroll
    for (int mt = 0; mt < 2; mt++) {
        int r0 = warp * 32 + mt * 16 + g;
        float il0 = 1.f / lr[mt][0], il1 = 1.f / lr[mt][1];
        #pragma unroll
        for (int nv = 0; nv < 2; nv++) {
            int d = nv * 8 + 2 * tig;
            *(__half2*)(g_OH + ((size_t)r0 * BB + b) * H + h * 16 + d) =
                __floats2half2_rn(oa[mt][nv][0] * il0, oa[mt][nv][1] * il0);
            *(__half2*)(g_OH + ((size_t)(r0 + 8) * BB + b) * H + h * 16 + d) =
                __floats2half2_rn(oa[mt][nv][2] * il1, oa[mt][nv][3] * il1);
        }
    }
}

// ---------------- final projection + traj output + traj loss ----------------
__global__ void k_traj(const float* __restrict__ w4, const float* __restrict__ b4,
                       const float* __restrict__ w5, const float* __restrict__ b5,
                       const float* __restrict__ traj_in, float* __restrict__ out) {
    int tt = blockIdx.x >> 8;
    int a  = blockIdx.x & 255;
    int b  = threadIdx.x;
    int o = tt + (OBS - PRED);
    const float* xr = g_X + ((size_t)a * 128 + b) * 128;
    float acc = b4[o];
    #pragma unroll 8
    for (int j = 0; j < 128; j++) acc += xr[j] * w4[o * 128 + j];
    float s0 = block_sum<4>(acc * w5[b]);
    float s1 = block_sum<4>(acc * w5[128 + b]);
    if (b == 0) {
        float t0 = s0 + b5[0], t1 = s1 + b5[1];
        float y0 = traj_in[(OBS + tt) * (NAG * 2) + a * 2 + 0];
        float y1 = traj_in[(OBS + tt) * (NAG * 2) + a * 2 + 1];
        out[(tt * 256 + a) * 2 + 0] = t0;
        out[(tt * 256 + a) * 2 + 1] = t1;
        float d0 = t0 - y0, d1 = t1 - y1;
        atomicAdd(&g_traj, (double)sqrtf(d0 * d0 + d1 * d1));
    }
}

__global__ void k_final(float* __restrict__ out) {
    double kld = -0.5 * (g_kld / 2048.0);
    double st = g_struct / (2048.0 * 2048.0);
    double tl = g_traj / 256.0;
    out[PRED * NAG * FOUT] = (float)(tl + kld + st);
}

// ---------------- launch ----------------
extern "C" void kernel_launch(void* const* d_in, const int* in_sizes, int n_in,
                              void* d_out, int out_size) {
    const float* traj_in = (const float*)d_in[0];
    const float* adj_in  = (const float*)d_in[1];
    const float* eps     = (const float*)d_in[2];
    const float* pro1_w  = (const float*)d_in[3];
    const float* pro1_b  = (const float*)d_in[4];
    const float* pro2_w  = (const float*)d_in[5];
    const float* pro2_b  = (const float*)d_in[6];
    const float* mu_w    = (const float*)d_in[7];
    const float* mu_b    = (const float*)d_in[8];
    const float* ls_w    = (const float*)d_in[9];
    const float* ls_b    = (const float*)d_in[10];
    const float* gdl_w   = (const float*)d_in[11];
    const float* gdl_b   = (const float*)d_in[12];
    const float* pro3_w  = (const float*)d_in[13];
    const float* pro3_b  = (const float*)d_in[14];
    const float* pro4_w  = (const float*)d_in[15];
    const float* pro4_b  = (const float*)d_in[16];
    const float* pro5_w  = (const float*)d_in[17];
    const float* pro5_b  = (const float*)d_in[18];
    const float* qkv_w   = (const float*)d_in[19];
    const float* qkv_b   = (const float*)d_in[20];
    const float* out_w   = (const float*)d_in[21];
    const float* out_b   = (const float*)d_in[22];
    const float* ff1_w   = (const float*)d_in[23];
    const float* ff1_b   = (const float*)d_in[24];
    const float* ff2_w   = (const float*)d_in[25];
    const float* ff2_b   = (const float*)d_in[26];
    const float* ln1_g   = (const float*)d_in[27];
    const float* ln1_b   = (const float*)d_in[28];
    const float* ln2_g   = (const float*)d_in[29];
    const float* ln2_b   = (const float*)d_in[30];
    const int*   iftrain = (const int*)d_in[31];
    float* out = (float*)d_out;

    float *pOUTB, *pBMLS, *pX, *pPART;
    __half *pMLSH, *pAGGH, *pENCH, *pZH, *pXH, *pOH, *pQKVH;
    __half *pWQKVH, *pWOUTH, *pWFF1H, *pWFF2H, *pWGDLH, *pWMLSH;
    cudaGetSymbolAddress((void**)&pOUTB,  g_OUTB);
    cudaGetSymbolAddress((void**)&pBMLS,  g_BMLS);
    cudaGetSymbolAddress((void**)&pX,     g_X);
    cudaGetSymbolAddress((void**)&pPART,  g_PART);
    cudaGetSymbolAddress((void**)&pMLSH,  g_MLSH);
    cudaGetSymbolAddress((void**)&pAGGH,  g_AGGH);
    cudaGetSymbolAddress((void**)&pENCH,  g_ENCH);
    cudaGetSymbolAddress((void**)&pZH,    g_ZH);
    cudaGetSymbolAddress((void**)&pXH,    g_XH);
    cudaGetSymbolAddress((void**)&pOH,    g_OH);
    cudaGetSymbolAddress((void**)&pQKVH,  g_QKVH);
    cudaGetSymbolAddress((void**)&pWQKVH, g_WQKVH);
    cudaGetSymbolAddress((void**)&pWOUTH, g_WOUTH);
    cudaGetSymbolAddress((void**)&pWFF1H, g_WFF1H);
    cudaGetSymbolAddress((void**)&pWFF2H, g_WFF2H);
    cudaGetSymbolAddress((void**)&pWGDLH, g_WGDLH);
    cudaGetSymbolAddress((void**)&pWMLSH, g_WMLSH);

    static int smem_set = 0;
    if (!smem_set) {
        cudaFuncSetAttribute(k_ffn, cudaFuncAttributeMaxDynamicSharedMemorySize, 196608);
        smem_set = 1;
    }

    // ---- fused weight conversion + packing ----
    k_cvt<<<3505, 256>>>(qkv_w, out_w, ff1_w, ff2_w, gdl_w, mu_w, ls_w, mu_b, ls_b);

    // ---- graph-VAE front end ----
    k_init<<<8, 256>>>();
    k_minmax<<<512, 256>>>(adj_in);
    k_build<<<dim3(2, NNODE), 256>>>(adj_in);
    k_colsum<<<dim3(16, 64), 128>>>();
    k_dis<<<8, 256>>>();
    k_agg<<<dim3(64, 64), dim3(32, 32)>>>();
    k_enc<<<NNODE, 128>>>(traj_in, pro1_w, pro1_b, pro2_w, pro2_b);

    k_hgemm<5><<<dim3(2, 16), 256>>>(pENCH, pWMLSH, pBMLS, nullptr, pMLSH,
                                     NNODE, 256, H, nullptr, nullptr);
    k_hgemm<7><<<dim3(2, 16, 8), 256>>>(pAGGH, pMLSH, nullptr, pPART, nullptr,
                                        NNODE, 256, NNODE, nullptr, nullptr);
    k_zred<<<1024, 256>>>(eps, iftrain);
    k_hgemm<6><<<dim3(16, 16), 256>>>(pZH, pZH, nullptr, nullptr, nullptr,
                                      NNODE, NNODE, H, nullptr, nullptr);
    k_hgemm<0><<<dim3(1, 16), 256>>>(pZH, pWGDLH, gdl_b, pOUTB, nullptr,
                                     NNODE, H, H, nullptr, nullptr);
    k_xbuild<<<16384, 256>>>(pro3_w, pro3_b);

    // ---- transformer ----
    k_hgemm<1><<<dim3(3, 256), 256>>>(pXH, pWQKVH, qkv_b,
                                      nullptr, pQKVH, NTOK, 3 * H, H, nullptr, nullptr);
    for (int l = 0; l < NL; l++) {
        k_attn_tc<<<BB * NH, 256>>>();
        k_hgemm<2><<<dim3(1, 256), 256>>>(pOH, pWOUTH + (size_t)l * H * H, out_b + (size_t)l * H,
                                          pX, pXH, NTOK, H, H, ln1_g + l * H, ln1_b + l * H);
        const __half* wq = (l + 1 < NL) ? pWQKVH + (size_t)(l + 1) * 3 * H * H : nullptr;
        const float*  bq = (l + 1 < NL) ? qkv_b + (size_t)(l + 1) * 3 * H : nullptr;
        k_ffn<<<256, 256, 196608>>>(ff1_b + (size_t)l * FFD, ff2_b + (size_t)l * H,
                                    pWFF1H + (size_t)l * FFD * H, pWFF2H + (size_t)l * H * FFD,
                                    pX, pXH, ln2_g + l * H, ln2_b + l * H,
                                    wq, bq, pQKVH);
    }

    // ---- output + loss ----
    k_traj<<<PRED * NAG, 128>>>(pro4_w, pro4_b, pro5_w, pro5_b, traj_in, out);
    k_final<<<1, 1>>>(out);
}